// round 9
// baseline (speedup 1.0000x reference)
#include <cuda_runtime.h>
#include <cuda_bf16.h>
#include <math.h>
#include <float.h>

#define Bc 4
#define Lc 1024
#define Hc 12
#define Ec 64
#define BM 64
#define BN 64
#define NIT (Lc / BM)    // 16 i-tiles
#define NBH (Bc * Hc)    // 48
#define PBH (Lc * 128)   // 131072 bytes per (b,h) per bf16 array

// ---------------------------------------------------------------------------
// global scratch (allocation-free rule: __device__ globals)
// bf16 hi/lo images, PRE-SWIZZLED exactly like the stage2 smem tiles
// ---------------------------------------------------------------------------
__device__ __align__(16) unsigned char g_qhi[NBH * PBH];
__device__ __align__(16) unsigned char g_qlo[NBH * PBH];
__device__ __align__(16) unsigned char g_khi[NBH * PBH];
__device__ __align__(16) unsigned char g_klo[NBH * PBH];
__device__ __align__(16) unsigned char g_vhi[NBH * PBH];
__device__ __align__(16) unsigned char g_vlo[NBH * PBH];
__device__ float g_wexp[NBH * Lc];
__device__ float g_invz[NBH * Lc];
__device__ float g_kkn[NBH * Lc];          // -km * |k|^2
__device__ float g_gq[NBH * 64 * Ec];      // 16-row sums [bh][g*4+r][e]

// ---------------------------------------------------------------------------
// helpers
// ---------------------------------------------------------------------------
__device__ __forceinline__ unsigned smem_u32(const void* p) {
    unsigned a;
    asm("{ .reg .u64 t; cvta.to.shared.u64 t, %1; cvt.u32.u64 %0, t; }"
        : "=r"(a) : "l"(p));
    return a;
}
__device__ __forceinline__ void cpa16(unsigned dst, const void* src) {
    asm volatile("cp.async.cg.shared.global [%0], [%1], 16;" :: "r"(dst), "l"(src));
}
__device__ __forceinline__ void ldsm4(unsigned* r, unsigned addr) {
    asm volatile("ldmatrix.sync.aligned.m8n8.x4.shared.b16 {%0,%1,%2,%3}, [%4];"
        : "=r"(r[0]), "=r"(r[1]), "=r"(r[2]), "=r"(r[3]) : "r"(addr));
}
__device__ __forceinline__ void ldsm4t(unsigned* r, unsigned addr) {
    asm volatile("ldmatrix.sync.aligned.m8n8.x4.trans.shared.b16 {%0,%1,%2,%3}, [%4];"
        : "=r"(r[0]), "=r"(r[1]), "=r"(r[2]), "=r"(r[3]) : "r"(addr));
}
__device__ __forceinline__ void mma_bf16(float* c, const unsigned* a, const unsigned* b) {
    asm volatile(
        "mma.sync.aligned.m16n8k16.row.col.f32.bf16.bf16.f32 "
        "{%0,%1,%2,%3}, {%4,%5,%6,%7}, {%8,%9}, {%0,%1,%2,%3};"
        : "+f"(c[0]), "+f"(c[1]), "+f"(c[2]), "+f"(c[3])
        : "r"(a[0]), "r"(a[1]), "r"(a[2]), "r"(a[3]), "r"(b[0]), "r"(b[1]));
}
__device__ __forceinline__ void splitpack(float p0, float p1, unsigned& hi, unsigned& lo) {
    __nv_bfloat162 h2 = __floats2bfloat162_rn(p0, p1);
    float r0 = p0 - __low2float(h2);
    float r1 = p1 - __high2float(h2);
    __nv_bfloat162 l2 = __floats2bfloat162_rn(r0, r1);
    hi = *(unsigned*)&h2;
    lo = *(unsigned*)&l2;
}
// swizzled byte offset within a (row, c4) cell; c4 = group of 4 elements
__device__ __forceinline__ unsigned swoff(int row, int c4) {
    return (unsigned)(row * 128 + ((c4 * 8) ^ ((row & 7) << 4)));
}

// stage2 smem: Q hi/lo 2x8K, K double buffers 2x16K, V single 16K, kn 2x256B
#define SQHI 0
#define SQLO 8192
#define SKB  16384            // + buf*16384 ; hi at +0, lo at +8192
#define SVHI 49152
#define SVLO 57344
#define SKNN 65536
#define STOT (65536 + 512)

// ---------------------------------------------------------------------------
// 1) merged: blocks [0,NBH) = score+scan; blocks [NBH, NBH+4*NBH) = prep_kv
// ---------------------------------------------------------------------------
__global__ void __launch_bounds__(1024) prep_kernel(
    const float* __restrict__ q, const float* __restrict__ wv,
    const float* __restrict__ q_mask,
    const float* __restrict__ k, const float* __restrict__ v,
    const float* __restrict__ k_mask)
{
    int tid = threadIdx.x;
    if (blockIdx.x >= NBH) {
        // ---------------- prep_kv part: 256 rows per block ----------------
        int pb = blockIdx.x - NBH;
        int bh = pb >> 2, qtr = pb & 3;
        int b = bh / Hc, h = bh % Hc;
        float km = k_mask[b * Lc];
        unsigned char* khi = g_khi + (size_t)bh * PBH;
        unsigned char* klo = g_klo + (size_t)bh * PBH;
        unsigned char* vhi = g_vhi + (size_t)bh * PBH;
        unsigned char* vlo = g_vlo + (size_t)bh * PBH;
        #pragma unroll
        for (int itr = 0; itr < 4; ++itr) {
            int idx = itr * 1024 + tid;
            int row = qtr * 256 + (idx >> 4), c4 = idx & 15;
            size_t goff = ((size_t)((b * Lc + row) * Hc + h)) * Ec + c4 * 4;
            unsigned off = swoff(row, c4);
            float4 kx = *(const float4*)(k + goff);
            {
                unsigned h0, l0_, h1, l1;
                splitpack(kx.x, kx.y, h0, l0_);
                splitpack(kx.z, kx.w, h1, l1);
                *(uint2*)(khi + off) = make_uint2(h0, h1);
                *(uint2*)(klo + off) = make_uint2(l0_, l1);
            }
            {
                float4 x = *(const float4*)(v + goff);
                unsigned h0, l0_, h1, l1;
                splitpack(x.x, x.y, h0, l0_);
                splitpack(x.z, x.w, h1, l1);
                *(uint2*)(vhi + off) = make_uint2(h0, h1);
                *(uint2*)(vlo + off) = make_uint2(l0_, l1);
            }
            float ps = kx.x * kx.x + kx.y * kx.y + kx.z * kx.z + kx.w * kx.w;
            #pragma unroll
            for (int o = 1; o < 16; o <<= 1) ps += __shfl_xor_sync(0xffffffffu, ps, o);
            if ((tid & 15) == 0) g_kkn[bh * Lc + row] = -km * ps;
        }
        return;
    }

    // ---------------- score + softmax-scan part ----------------
    int bh = blockIdx.x;
    int b = bh / Hc, h = bh % Hc;

    __shared__ float s_sh[Lc];
    __shared__ float w_sh[Ec];
    __shared__ float red[32];
    __shared__ float Msh;

    int lane = tid & 31, warp = tid >> 5;

    if (tid < Ec) w_sh[tid] = wv[h * Ec + tid];
    __syncthreads();
    float qm = q_mask[b * Lc];

    for (int j = warp; j < Lc; j += 32) {
        const float* qrow = q + ((size_t)((b * Lc + j) * Hc + h)) * Ec;
        float p = qrow[lane] * w_sh[lane] + qrow[lane + 32] * w_sh[lane + 32];
        #pragma unroll
        for (int o = 16; o; o >>= 1) p += __shfl_xor_sync(0xffffffffu, p, o);
        if (lane == 0) s_sh[j] = p * qm;
    }
    __syncthreads();

    float m = s_sh[tid];
    #pragma unroll
    for (int o = 16; o; o >>= 1) m = fmaxf(m, __shfl_xor_sync(0xffffffffu, m, o));
    if (lane == 0) red[warp] = m;
    __syncthreads();
    if (warp == 0) {
        float t = red[lane];
        #pragma unroll
        for (int o = 16; o; o >>= 1) t = fmaxf(t, __shfl_xor_sync(0xffffffffu, t, o));
        if (lane == 0) Msh = t;
    }
    __syncthreads();
    float M = Msh;

    float wexp = __expf(s_sh[tid] - M);
    float sc = wexp;
    #pragma unroll
    for (int o = 1; o < 32; o <<= 1) {
        float t = __shfl_up_sync(0xffffffffu, sc, o);
        if (lane >= o) sc += t;
    }
    if (lane == 31) red[warp] = sc;
    __syncthreads();
    if (warp == 0) {
        float v0 = red[lane];
        float scn = v0;
        #pragma unroll
        for (int o = 1; o < 32; o <<= 1) {
            float t = __shfl_up_sync(0xffffffffu, scn, o);
            if (lane >= o) scn += t;
        }
        red[lane] = scn - v0;
    }
    __syncthreads();
    float Z = sc + red[warp];
    g_wexp[bh * Lc + tid] = wexp;
    g_invz[bh * Lc + tid] = 1.0f / Z;
}

// ---------------------------------------------------------------------------
// 2) 16-row sums: g_gq[bh][g*4+r][e]. grid (NBH,16), 256 threads
// ---------------------------------------------------------------------------
__global__ void __launch_bounds__(256) gsum_kernel(const float* __restrict__ q)
{
    int bh = blockIdx.x, g = blockIdx.y;
    int b = bh / Hc, h = bh % Hc;
    int e = threadIdx.x & 63, r = threadIdx.x >> 6;
    int j0 = g * 64 + r * 16;
    float s = 0.f;
    #pragma unroll
    for (int jj = 0; jj < 16; ++jj) {
        int j = j0 + jj;
        s += g_wexp[bh * Lc + j] *
             q[((size_t)((b * Lc + j) * Hc + h)) * Ec + e];
    }
    g_gq[(bh * 64 + g * 4 + r) * Ec + e] = s;
}

// ---------------------------------------------------------------------------
// 3) qhat scan -> smem stage -> vectorized bf16 hi/lo. grid (NBH,16), 256 thr
// ---------------------------------------------------------------------------
__global__ void __launch_bounds__(256) qhat_kernel(const float* __restrict__ q)
{
    __shared__ float sbuf[64][64];
    int bh = blockIdx.x, g = blockIdx.y;
    int b = bh / Hc, h = bh % Hc;
    int e = threadIdx.x & 63, r = threadIdx.x >> 6;
    int gr = g * 4 + r;
    unsigned char* qhi = g_qhi + (size_t)bh * PBH;
    unsigned char* qlo = g_qlo + (size_t)bh * PBH;

    float acc = 0.f;
    const float* gq = g_gq + bh * 64 * Ec + e;
    for (int i = 0; i < gr; ++i) acc += gq[i * Ec];

    int j0 = g * 64 + r * 16;
    #pragma unroll
    for (int jj = 0; jj < 16; ++jj) {
        int j = j0 + jj;
        acc += g_wexp[bh * Lc + j] *
               q[((size_t)((b * Lc + j) * Hc + h)) * Ec + e];
        sbuf[r * 16 + jj][e] = acc * g_invz[bh * Lc + j];
    }
    __syncthreads();

    // phase 2: vectorized split + store
    #pragma unroll
    for (int itr = 0; itr < 4; ++itr) {
        int idx = itr * 256 + threadIdx.x;
        int lr = idx >> 4, c4 = idx & 15;
        float4 x = *(const float4*)&sbuf[lr][c4 * 4];
        unsigned h0, l0_, h1, l1;
        splitpack(x.x, x.y, h0, l0_);
        splitpack(x.z, x.w, h1, l1);
        unsigned off = swoff(g * 64 + lr, c4);
        *(uint2*)(qhi + off) = make_uint2(h0, h1);
        *(uint2*)(qlo + off) = make_uint2(l0_, l1);
    }
}

// ---------------------------------------------------------------------------
// 4) Stage 2: split-bf16 mma.sync flash attention. K double-buffered,
//    V single-buffered, x4 ldmatrix B-fragments. 3 CTAs/SM.
//    grid (NBH, NIT) heavy-first, 128 threads (4 warps x 16 rows)
// ---------------------------------------------------------------------------
__global__ void __launch_bounds__(128, 3) stage2_kernel(
    const float* __restrict__ q, const float* __restrict__ k_mask,
    float* __restrict__ out)
{
    extern __shared__ char smem[];
    const unsigned sbase = smem_u32(smem);
    int tid = threadIdx.x, lane = tid & 31, w = tid >> 5;
    int bh = blockIdx.x, b = bh / Hc, h = bh % Hc;
    int it = NIT - 1 - (int)blockIdx.y;   // heavy tiles first
    int i0 = it * BM;
    float twokm = 2.f * k_mask[b * Lc];
    const size_t bhoff = (size_t)bh * PBH;

    // ---- prologue: Q + K0 + V0 + kn0, one commit group ----
    {
        const unsigned char* sq_hi = g_qhi + bhoff + (size_t)i0 * 128;
        const unsigned char* sq_lo = g_qlo + bhoff + (size_t)i0 * 128;
        #pragma unroll
        for (int c = 0; c < 4; ++c) {
            unsigned off = (unsigned)((c * 128 + tid) * 16);
            cpa16(sbase + SQHI + off, sq_hi + off);
            cpa16(sbase + SQLO + off, sq_lo + off);
            cpa16(sbase + SKB + off,        g_khi + bhoff + off);
            cpa16(sbase + SKB + 8192 + off, g_klo + bhoff + off);
            cpa16(sbase + SVHI + off, g_vhi + bhoff + off);
            cpa16(sbase + SVLO + off, g_vlo + bhoff + off);
        }
        if (tid < BN)
            *(float*)(smem + SKNN + tid * 4) = g_kkn[bh * Lc + tid];
        asm volatile("cp.async.commit_group;");
    }

    // ---- per-lane fragment geometry ----
    int a_t = lane >> 3, a_r = lane & 7;
    int a_row = w * 16 + ((a_t & 1) << 3) + a_r;
    unsigned a_rowoff = (unsigned)(a_row * 128);
    unsigned a_x = (unsigned)((a_row & 7) << 4);
    unsigned a_cb = (unsigned)(((a_t >> 1) << 3) * 2);
    int quad = lane >> 3;                 // 0..3 (x4 B-fragment geometry)
    int qlo_ = quad & 1, qhi_ = quad >> 1;
    int b_r = lane & 7;
    unsigned bx = (unsigned)(b_r << 4);
    int rA = lane >> 2;
    int igA = i0 + w * 16 + rA, igB = igA + 8;
    int cA = (lane & 3) << 1;

    float oc[8][4];
    #pragma unroll
    for (int t = 0; t < 8; ++t)
        #pragma unroll
        for (int c = 0; c < 4; ++c) oc[t][c] = 0.f;
    float mA = -INFINITY, mB = -INFINITY, lA = 0.f, lB = 0.f;

    for (int jt = 0; jt <= it; ++jt) {
        int j0 = jt * BN;
        int buf = jt & 1;
        __syncthreads();   // all reads of V(jt-1), K(jt-1) buffer, kn(jt) staged

        // ---- issue V(jt) (jt>=1) and K(jt+1)+kn(jt+1) prefetches ----
        int nIss = 0;
        if (jt >= 1) {
            const size_t tg = bhoff + (size_t)j0 * 128;
            #pragma unroll
            for (int c = 0; c < 4; ++c) {
                unsigned off = (unsigned)((c * 128 + tid) * 16);
                cpa16(sbase + SVHI + off, g_vhi + tg + off);
                cpa16(sbase + SVLO + off, g_vlo + tg + off);
            }
            asm volatile("cp.async.commit_group;");
            ++nIss;
        }
        int kIss = 0;
        if (jt < it) {
            unsigned kb = SKB + (unsigned)(buf ^ 1) * 16384;
            const size_t tg = bhoff + (size_t)(j0 + BN) * 128;
            #pragma unroll
            for (int c = 0; c < 4; ++c) {
                unsigned off = (unsigned)((c * 128 + tid) * 16);
                cpa16(sbase + kb + off,        g_khi + tg + off);
                cpa16(sbase + kb + 8192 + off, g_klo + tg + off);
            }
            if (tid < BN)
                *(float*)(smem + SKNN + (buf ^ 1) * 256 + tid * 4) =
                    g_kkn[bh * Lc + j0 + BN + tid];
            asm volatile("cp.async.commit_group;");
            ++nIss; kIss = 1;
        }
        // wait: allow only the groups issued this iteration to be pending
        if (nIss == 2)      asm volatile("cp.async.wait_group 2;");
        else if (nIss == 1) asm volatile("cp.async.wait_group 1;");
        else                asm volatile("cp.async.wait_group 0;");
        __syncthreads();

        const char* knp = smem + SKNN + buf * 256;
        unsigned KHI = SKB + (unsigned)buf * 16384, KLO = KHI + 8192;

        // ---- S = Qhat . K^T  (3-split bf16, x4 B-fragments) ----
        float sc_[8][4];
        #pragma unroll
        for (int t = 0; t < 8; ++t)
            #pragma unroll
            for (int c = 0; c < 4; ++c) sc_[t][c] = 0.f;

        #pragma unroll
        for (int ks = 0; ks < 4; ++ks) {
            unsigned ah[4], al[4];
            unsigned aoff = a_rowoff + (((unsigned)(ks * 32) + a_cb) ^ a_x);
            ldsm4(ah, sbase + SQHI + aoff);
            ldsm4(al, sbase + SQLO + aoff);
            #pragma unroll
            for (int u = 0; u < 4; ++u) {
                unsigned jroff = (unsigned)((u * 16 + qhi_ * 8 + b_r) * 128);
                unsigned boff = jroff + (((unsigned)(ks * 32 + qlo_ * 16)) ^ bx);
                unsigned kh4[4], kl4[4];
                ldsm4(kh4, sbase + KHI + boff);
                ldsm4(kl4, sbase + KLO + boff);
                mma_bf16(sc_[2 * u],     ah, kh4);
                mma_bf16(sc_[2 * u],     ah, kl4);
                mma_bf16(sc_[2 * u],     al, kh4);
                mma_bf16(sc_[2 * u + 1], ah, kh4 + 2);
                mma_bf16(sc_[2 * u + 1], ah, kl4 + 2);
                mma_bf16(sc_[2 * u + 1], al, kh4 + 2);
            }
        }

        // ---- scores + online softmax (quad lanes share row) ----
        float mxA = -INFINITY, mxB = -INFINITY;
        #pragma unroll
        for (int t = 0; t < 8; ++t) {
            int jb = j0 + t * 8 + cA;
            float k0 = *(const float*)(knp + (t * 8 + cA) * 4);
            float k1 = *(const float*)(knp + (t * 8 + cA + 1) * 4);
            float s0 = fmaf(twokm, sc_[t][0], k0); if (jb     > igA) s0 = -INFINITY;
            float s1 = fmaf(twokm, sc_[t][1], k1); if (jb + 1 > igA) s1 = -INFINITY;
            float s2 = fmaf(twokm, sc_[t][2], k0); if (jb     > igB) s2 = -INFINITY;
            float s3 = fmaf(twokm, sc_[t][3], k1); if (jb + 1 > igB) s3 = -INFINITY;
            sc_[t][0] = s0; sc_[t][1] = s1; sc_[t][2] = s2; sc_[t][3] = s3;
            mxA = fmaxf(mxA, fmaxf(s0, s1));
            mxB = fmaxf(mxB, fmaxf(s2, s3));
        }
        mxA = fmaxf(mxA, __shfl_xor_sync(0xffffffffu, mxA, 1));
        mxA = fmaxf(mxA, __shfl_xor_sync(0xffffffffu, mxA, 2));
        mxB = fmaxf(mxB, __shfl_xor_sync(0xffffffffu, mxB, 1));
        mxB = fmaxf(mxB, __shfl_xor_sync(0xffffffffu, mxB, 2));

        float mnA = fmaxf(mA, mxA), mnB = fmaxf(mB, mxB);
        float scA = __expf(mA - mnA), scB = __expf(mB - mnB);
        mA = mnA; mB = mnB;
        float rsA = 0.f, rsB = 0.f;
        #pragma unroll
        for (int t = 0; t < 8; ++t) {
            float p0 = __expf(sc_[t][0] - mnA);
            float p1 = __expf(sc_[t][1] - mnA);
            float p2 = __expf(sc_[t][2] - mnB);
            float p3 = __expf(sc_[t][3] - mnB);
            sc_[t][0] = p0; sc_[t][1] = p1; sc_[t][2] = p2; sc_[t][3] = p3;
            rsA += p0 + p1; rsB += p2 + p3;
        }
        rsA += __shfl_xor_sync(0xffffffffu, rsA, 1);
        rsA += __shfl_xor_sync(0xffffffffu, rsA, 2);
        rsB += __shfl_xor_sync(0xffffffffu, rsB, 1);
        rsB += __shfl_xor_sync(0xffffffffu, rsB, 2);
        lA = lA * scA + rsA;
        lB = lB * scB + rsB;
        // skip the O-rescale when no row's max moved (warp-convergent test)
        if (!__all_sync(0xffffffffu, (scA == 1.f) & (scB == 1.f))) {
            #pragma unroll
            for (int t = 0; t < 8; ++t) {
                oc[t][0] *= scA; oc[t][1] *= scA;
                oc[t][2] *= scB; oc[t][3] *= scB;
            }
        }

        // ---- wait V(jt) arrival, then O += P . V (x4t V-fragments) ----
        if (kIss) asm volatile("cp.async.wait_group 1;");
        else      asm volatile("cp.async.wait_group 0;");
        __syncthreads();

        #pragma unroll
        for (int ks = 0; ks < 4; ++ks) {
            unsigned pah[4], pal[4];
            splitpack(sc_[2 * ks][0],     sc_[2 * ks][1],     pah[0], pal[0]);
            splitpack(sc_[2 * ks][2],     sc_[2 * ks][3],     pah[1], pal[1]);
            splitpack(sc_[2 * ks + 1][0], sc_[2 * ks + 1][1], pah[2], pal[2]);
            splitpack(sc_[2 * ks + 1][2], sc_[2 * ks + 1][3], pah[3], pal[3]);
            unsigned vroff = (unsigned)((ks * 16 + qlo_ * 8 + b_r) * 128);
            #pragma unroll
            for (int u = 0; u < 4; ++u) {
                unsigned voff = vroff + (((unsigned)((2 * u + qhi_) * 16)) ^ bx);
                unsigned vh4[4], vl4[4];
                ldsm4t(vh4, sbase + SVHI + voff);
                ldsm4t(vl4, sbase + SVLO + voff);
                mma_bf16(oc[2 * u],     pah, vh4);
                mma_bf16(oc[2 * u],     pah, vl4);
                mma_bf16(oc[2 * u],     pal, vh4);
                mma_bf16(oc[2 * u + 1], pah, vh4 + 2);
                mma_bf16(oc[2 * u + 1], pah, vl4 + 2);
                mma_bf16(oc[2 * u + 1], pal, vh4 + 2);
            }
        }
    }

    // ---- epilogue: out = queries + O / l ----
    float liA = 1.f / lA, liB = 1.f / lB;
    #pragma unroll
    for (int t = 0; t < 8; ++t) {
        int e = t * 8 + cA;
        size_t offA = ((size_t)((b * Lc + igA) * Hc + h)) * Ec + e;
        size_t offB = ((size_t)((b * Lc + igB) * Hc + h)) * Ec + e;
        float2 qa = *(const float2*)(q + offA);
        float2 qb = *(const float2*)(q + offB);
        *(float2*)(out + offA) = make_float2(qa.x + oc[t][0] * liA,
                                             qa.y + oc[t][1] * liA);
        *(float2*)(out + offB) = make_float2(qb.x + oc[t][2] * liB,
                                             qb.y + oc[t][3] * liB);
    }
}

// ---------------------------------------------------------------------------

extern "C" void kernel_launch(void* const* d_in, const int* in_sizes, int n_in,
                              void* d_out, int out_size)
{
    const float* q  = (const float*)d_in[0];
    const float* k  = (const float*)d_in[1];
    const float* v  = (const float*)d_in[2];
    const float* qm = (const float*)d_in[3];
    const float* kmsk = (const float*)d_in[4];
    const float* w  = (const float*)d_in[5];
    float* out = (float*)d_out;

    cudaFuncSetAttribute(stage2_kernel,
                         cudaFuncAttributeMaxDynamicSharedMemorySize, STOT);

    prep_kernel<<<NBH + NBH * 4, 1024>>>(q, w, qm, k, v, kmsk);
    gsum_kernel<<<dim3(NBH, 16), 256>>>(q);
    qhat_kernel<<<dim3(NBH, 16), 256>>>(q);

    dim3 grid(NBH, NIT);   // y slow => heavy tiles (it = NIT-1-y) first
    stage2_kernel<<<grid, 128, STOT>>>(q, kmsk, out);
}

// round 10
// speedup vs baseline: 1.1468x; 1.1468x over previous
#include <cuda_runtime.h>
#include <cuda_bf16.h>
#include <cuda_fp16.h>
#include <math.h>
#include <float.h>

#define Bc 4
#define Lc 1024
#define Hc 12
#define Ec 64
#define BM 64
#define BN 64
#define NIT (Lc / BM)    // 16 i-tiles
#define NBH (Bc * Hc)    // 48
#define PBH (Lc * 128)   // 131072 bytes per (b,h) per 16-bit array

// ---------------------------------------------------------------------------
// global scratch (allocation-free rule: __device__ globals)
// Q/K: bf16 hi/lo; V: fp16 hi/lo. All PRE-SWIZZLED like the stage2 smem tiles
// ---------------------------------------------------------------------------
__device__ __align__(16) unsigned char g_qhi[NBH * PBH];
__device__ __align__(16) unsigned char g_qlo[NBH * PBH];
__device__ __align__(16) unsigned char g_khi[NBH * PBH];
__device__ __align__(16) unsigned char g_klo[NBH * PBH];
__device__ __align__(16) unsigned char g_vhi[NBH * PBH];
__device__ __align__(16) unsigned char g_vlo[NBH * PBH];
__device__ float g_wexp[NBH * Lc];
__device__ float g_invz[NBH * Lc];
__device__ float g_kkn[NBH * Lc];          // -km * |k|^2
__device__ float g_gq[NBH * 64 * Ec];      // 16-row sums [bh][g*4+r][e]

// ---------------------------------------------------------------------------
// helpers
// ---------------------------------------------------------------------------
__device__ __forceinline__ unsigned smem_u32(const void* p) {
    unsigned a;
    asm("{ .reg .u64 t; cvta.to.shared.u64 t, %1; cvt.u32.u64 %0, t; }"
        : "=r"(a) : "l"(p));
    return a;
}
__device__ __forceinline__ void cpa16(unsigned dst, const void* src) {
    asm volatile("cp.async.cg.shared.global [%0], [%1], 16;" :: "r"(dst), "l"(src));
}
__device__ __forceinline__ void ldsm4(unsigned* r, unsigned addr) {
    asm volatile("ldmatrix.sync.aligned.m8n8.x4.shared.b16 {%0,%1,%2,%3}, [%4];"
        : "=r"(r[0]), "=r"(r[1]), "=r"(r[2]), "=r"(r[3]) : "r"(addr));
}
__device__ __forceinline__ void ldsm4t(unsigned* r, unsigned addr) {
    asm volatile("ldmatrix.sync.aligned.m8n8.x4.trans.shared.b16 {%0,%1,%2,%3}, [%4];"
        : "=r"(r[0]), "=r"(r[1]), "=r"(r[2]), "=r"(r[3]) : "r"(addr));
}
__device__ __forceinline__ void mma_bf16(float* c, const unsigned* a, const unsigned* b) {
    asm volatile(
        "mma.sync.aligned.m16n8k16.row.col.f32.bf16.bf16.f32 "
        "{%0,%1,%2,%3}, {%4,%5,%6,%7}, {%8,%9}, {%0,%1,%2,%3};"
        : "+f"(c[0]), "+f"(c[1]), "+f"(c[2]), "+f"(c[3])
        : "r"(a[0]), "r"(a[1]), "r"(a[2]), "r"(a[3]), "r"(b[0]), "r"(b[1]));
}
__device__ __forceinline__ void mma_f16(float* c, const unsigned* a, const unsigned* b) {
    asm volatile(
        "mma.sync.aligned.m16n8k16.row.col.f32.f16.f16.f32 "
        "{%0,%1,%2,%3}, {%4,%5,%6,%7}, {%8,%9}, {%0,%1,%2,%3};"
        : "+f"(c[0]), "+f"(c[1]), "+f"(c[2]), "+f"(c[3])
        : "r"(a[0]), "r"(a[1]), "r"(a[2]), "r"(a[3]), "r"(b[0]), "r"(b[1]));
}
__device__ __forceinline__ void splitpack(float p0, float p1, unsigned& hi, unsigned& lo) {
    __nv_bfloat162 h2 = __floats2bfloat162_rn(p0, p1);
    float r0 = p0 - __low2float(h2);
    float r1 = p1 - __high2float(h2);
    __nv_bfloat162 l2 = __floats2bfloat162_rn(r0, r1);
    hi = *(unsigned*)&h2;
    lo = *(unsigned*)&l2;
}
__device__ __forceinline__ void splitpack_h(float p0, float p1, unsigned& hi, unsigned& lo) {
    __half2 h2 = __floats2half2_rn(p0, p1);
    float r0 = p0 - __low2float(h2);
    float r1 = p1 - __high2float(h2);
    __half2 l2 = __floats2half2_rn(r0, r1);
    hi = *(unsigned*)&h2;
    lo = *(unsigned*)&l2;
}
// swizzled byte offset within a (row, c4) cell; c4 = group of 4 elements
__device__ __forceinline__ unsigned swoff(int row, int c4) {
    return (unsigned)(row * 128 + ((c4 * 8) ^ ((row & 7) << 4)));
}

// stage2 smem: Q hi/lo 2x8K, K double buffers 2x16K, V single 16K, kn 2x256B
#define SQHI 0
#define SQLO 8192
#define SKB  16384            // + buf*16384 ; hi at +0, lo at +8192
#define SVHI 49152
#define SVLO 57344
#define SKNN 65536
#define STOT (65536 + 512)

// ---------------------------------------------------------------------------
// 1) merged: blocks [0,NBH) = score+scan; blocks [NBH, NBH+4*NBH) = prep_kv
// ---------------------------------------------------------------------------
__global__ void __launch_bounds__(1024) prep_kernel(
    const float* __restrict__ q, const float* __restrict__ wv,
    const float* __restrict__ q_mask,
    const float* __restrict__ k, const float* __restrict__ v,
    const float* __restrict__ k_mask)
{
    int tid = threadIdx.x;
    if (blockIdx.x >= NBH) {
        // ---------------- prep_kv part: 256 rows per block ----------------
        int pb = blockIdx.x - NBH;
        int bh = pb >> 2, qtr = pb & 3;
        int b = bh / Hc, h = bh % Hc;
        float km = k_mask[b * Lc];
        unsigned char* khi = g_khi + (size_t)bh * PBH;
        unsigned char* klo = g_klo + (size_t)bh * PBH;
        unsigned char* vhi = g_vhi + (size_t)bh * PBH;
        unsigned char* vlo = g_vlo + (size_t)bh * PBH;
        #pragma unroll
        for (int itr = 0; itr < 4; ++itr) {
            int idx = itr * 1024 + tid;
            int row = qtr * 256 + (idx >> 4), c4 = idx & 15;
            size_t goff = ((size_t)((b * Lc + row) * Hc + h)) * Ec + c4 * 4;
            unsigned off = swoff(row, c4);
            float4 kx = *(const float4*)(k + goff);
            {
                unsigned h0, l0_, h1, l1;
                splitpack(kx.x, kx.y, h0, l0_);
                splitpack(kx.z, kx.w, h1, l1);
                *(uint2*)(khi + off) = make_uint2(h0, h1);
                *(uint2*)(klo + off) = make_uint2(l0_, l1);
            }
            {
                float4 x = *(const float4*)(v + goff);
                unsigned h0, l0_, h1, l1;
                splitpack_h(x.x, x.y, h0, l0_);
                splitpack_h(x.z, x.w, h1, l1);
                *(uint2*)(vhi + off) = make_uint2(h0, h1);
                *(uint2*)(vlo + off) = make_uint2(l0_, l1);
            }
            float ps = kx.x * kx.x + kx.y * kx.y + kx.z * kx.z + kx.w * kx.w;
            #pragma unroll
            for (int o = 1; o < 16; o <<= 1) ps += __shfl_xor_sync(0xffffffffu, ps, o);
            if ((tid & 15) == 0) g_kkn[bh * Lc + row] = -km * ps;
        }
        return;
    }

    // ---------------- score + softmax-scan part ----------------
    int bh = blockIdx.x;
    int b = bh / Hc, h = bh % Hc;

    __shared__ float s_sh[Lc];
    __shared__ float w_sh[Ec];
    __shared__ float red[32];
    __shared__ float Msh;

    int lane = tid & 31, warp = tid >> 5;

    if (tid < Ec) w_sh[tid] = wv[h * Ec + tid];
    __syncthreads();
    float qm = q_mask[b * Lc];

    for (int j = warp; j < Lc; j += 32) {
        const float* qrow = q + ((size_t)((b * Lc + j) * Hc + h)) * Ec;
        float p = qrow[lane] * w_sh[lane] + qrow[lane + 32] * w_sh[lane + 32];
        #pragma unroll
        for (int o = 16; o; o >>= 1) p += __shfl_xor_sync(0xffffffffu, p, o);
        if (lane == 0) s_sh[j] = p * qm;
    }
    __syncthreads();

    float m = s_sh[tid];
    #pragma unroll
    for (int o = 16; o; o >>= 1) m = fmaxf(m, __shfl_xor_sync(0xffffffffu, m, o));
    if (lane == 0) red[warp] = m;
    __syncthreads();
    if (warp == 0) {
        float t = red[lane];
        #pragma unroll
        for (int o = 16; o; o >>= 1) t = fmaxf(t, __shfl_xor_sync(0xffffffffu, t, o));
        if (lane == 0) Msh = t;
    }
    __syncthreads();
    float M = Msh;

    float wexp = __expf(s_sh[tid] - M);
    float sc = wexp;
    #pragma unroll
    for (int o = 1; o < 32; o <<= 1) {
        float t = __shfl_up_sync(0xffffffffu, sc, o);
        if (lane >= o) sc += t;
    }
    if (lane == 31) red[warp] = sc;
    __syncthreads();
    if (warp == 0) {
        float v0 = red[lane];
        float scn = v0;
        #pragma unroll
        for (int o = 1; o < 32; o <<= 1) {
            float t = __shfl_up_sync(0xffffffffu, scn, o);
            if (lane >= o) scn += t;
        }
        red[lane] = scn - v0;
    }
    __syncthreads();
    float Z = sc + red[warp];
    g_wexp[bh * Lc + tid] = wexp;
    g_invz[bh * Lc + tid] = 1.0f / Z;
}

// ---------------------------------------------------------------------------
// 2) 16-row sums: g_gq[bh][g*4+r][e]. grid (NBH,16), 256 threads
// ---------------------------------------------------------------------------
__global__ void __launch_bounds__(256) gsum_kernel(const float* __restrict__ q)
{
    int bh = blockIdx.x, g = blockIdx.y;
    int b = bh / Hc, h = bh % Hc;
    int e = threadIdx.x & 63, r = threadIdx.x >> 6;
    int j0 = g * 64 + r * 16;
    float s = 0.f;
    #pragma unroll
    for (int jj = 0; jj < 16; ++jj) {
        int j = j0 + jj;
        s += g_wexp[bh * Lc + j] *
             q[((size_t)((b * Lc + j) * Hc + h)) * Ec + e];
    }
    g_gq[(bh * 64 + g * 4 + r) * Ec + e] = s;
}

// ---------------------------------------------------------------------------
// 3) qhat scan -> smem stage -> vectorized bf16 hi/lo. grid (NBH,16), 256 thr
// ---------------------------------------------------------------------------
__global__ void __launch_bounds__(256) qhat_kernel(const float* __restrict__ q)
{
    __shared__ float sbuf[64][64];
    int bh = blockIdx.x, g = blockIdx.y;
    int b = bh / Hc, h = bh % Hc;
    int e = threadIdx.x & 63, r = threadIdx.x >> 6;
    int gr = g * 4 + r;
    unsigned char* qhi = g_qhi + (size_t)bh * PBH;
    unsigned char* qlo = g_qlo + (size_t)bh * PBH;

    float acc = 0.f;
    const float* gq = g_gq + bh * 64 * Ec + e;
    for (int i = 0; i < gr; ++i) acc += gq[i * Ec];

    int j0 = g * 64 + r * 16;
    #pragma unroll
    for (int jj = 0; jj < 16; ++jj) {
        int j = j0 + jj;
        acc += g_wexp[bh * Lc + j] *
               q[((size_t)((b * Lc + j) * Hc + h)) * Ec + e];
        sbuf[r * 16 + jj][e] = acc * g_invz[bh * Lc + j];
    }
    __syncthreads();

    // phase 2: vectorized split + store
    #pragma unroll
    for (int itr = 0; itr < 4; ++itr) {
        int idx = itr * 256 + threadIdx.x;
        int lr = idx >> 4, c4 = idx & 15;
        float4 x = *(const float4*)&sbuf[lr][c4 * 4];
        unsigned h0, l0_, h1, l1;
        splitpack(x.x, x.y, h0, l0_);
        splitpack(x.z, x.w, h1, l1);
        unsigned off = swoff(g * 64 + lr, c4);
        *(uint2*)(qhi + off) = make_uint2(h0, h1);
        *(uint2*)(qlo + off) = make_uint2(l0_, l1);
    }
}

// ---------------------------------------------------------------------------
// 4) Stage 2: flash attention. S: 3-term split-bf16 MMA.
//    PV: fp16, P single-precision (no split), V 2-term hi/lo -> 64 MMAs/tile.
//    K double-buffered, V single-buffered. 3 CTAs/SM.
//    grid (NBH, NIT) heavy-first, 128 threads (4 warps x 16 rows)
// ---------------------------------------------------------------------------
__global__ void __launch_bounds__(128, 3) stage2_kernel(
    const float* __restrict__ q, const float* __restrict__ k_mask,
    float* __restrict__ out)
{
    extern __shared__ char smem[];
    const unsigned sbase = smem_u32(smem);
    int tid = threadIdx.x, lane = tid & 31, w = tid >> 5;
    int bh = blockIdx.x, b = bh / Hc, h = bh % Hc;
    int it = NIT - 1 - (int)blockIdx.y;   // heavy tiles first
    int i0 = it * BM;
    float twokm = 2.f * k_mask[b * Lc];
    const size_t bhoff = (size_t)bh * PBH;

    // ---- prologue: Q + K0 + V0 + kn0, one commit group ----
    {
        const unsigned char* sq_hi = g_qhi + bhoff + (size_t)i0 * 128;
        const unsigned char* sq_lo = g_qlo + bhoff + (size_t)i0 * 128;
        #pragma unroll
        for (int c = 0; c < 4; ++c) {
            unsigned off = (unsigned)((c * 128 + tid) * 16);
            cpa16(sbase + SQHI + off, sq_hi + off);
            cpa16(sbase + SQLO + off, sq_lo + off);
            cpa16(sbase + SKB + off,        g_khi + bhoff + off);
            cpa16(sbase + SKB + 8192 + off, g_klo + bhoff + off);
            cpa16(sbase + SVHI + off, g_vhi + bhoff + off);
            cpa16(sbase + SVLO + off, g_vlo + bhoff + off);
        }
        if (tid < BN)
            *(float*)(smem + SKNN + tid * 4) = g_kkn[bh * Lc + tid];
        asm volatile("cp.async.commit_group;");
    }

    // ---- per-lane fragment geometry ----
    int a_t = lane >> 3, a_r = lane & 7;
    int a_row = w * 16 + ((a_t & 1) << 3) + a_r;
    unsigned a_rowoff = (unsigned)(a_row * 128);
    unsigned a_x = (unsigned)((a_row & 7) << 4);
    unsigned a_cb = (unsigned)(((a_t >> 1) << 3) * 2);
    int quad = lane >> 3;                 // 0..3 (x4 B-fragment geometry)
    int qlo_ = quad & 1, qhi_ = quad >> 1;
    int b_r = lane & 7;
    unsigned bx = (unsigned)(b_r << 4);
    int rA = lane >> 2;
    int igA = i0 + w * 16 + rA, igB = igA + 8;
    int cA = (lane & 3) << 1;

    float oc[8][4];
    #pragma unroll
    for (int t = 0; t < 8; ++t)
        #pragma unroll
        for (int c = 0; c < 4; ++c) oc[t][c] = 0.f;
    float mA = -INFINITY, mB = -INFINITY, lA = 0.f, lB = 0.f;

    for (int jt = 0; jt <= it; ++jt) {
        int j0 = jt * BN;
        int buf = jt & 1;
        __syncthreads();   // all reads of V(jt-1), K(jt-1) buffer, kn(jt) staged

        // ---- issue V(jt) (jt>=1) and K(jt+1)+kn(jt+1) prefetches ----
        int nIss = 0;
        if (jt >= 1) {
            const size_t tg = bhoff + (size_t)j0 * 128;
            #pragma unroll
            for (int c = 0; c < 4; ++c) {
                unsigned off = (unsigned)((c * 128 + tid) * 16);
                cpa16(sbase + SVHI + off, g_vhi + tg + off);
                cpa16(sbase + SVLO + off, g_vlo + tg + off);
            }
            asm volatile("cp.async.commit_group;");
            ++nIss;
        }
        int kIss = 0;
        if (jt < it) {
            unsigned kb = SKB + (unsigned)(buf ^ 1) * 16384;
            const size_t tg = bhoff + (size_t)(j0 + BN) * 128;
            #pragma unroll
            for (int c = 0; c < 4; ++c) {
                unsigned off = (unsigned)((c * 128 + tid) * 16);
                cpa16(sbase + kb + off,        g_khi + tg + off);
                cpa16(sbase + kb + 8192 + off, g_klo + tg + off);
            }
            if (tid < BN)
                *(float*)(smem + SKNN + (buf ^ 1) * 256 + tid * 4) =
                    g_kkn[bh * Lc + j0 + BN + tid];
            asm volatile("cp.async.commit_group;");
            ++nIss; kIss = 1;
        }
        // wait: allow only the groups issued this iteration to be pending
        if (nIss == 2)      asm volatile("cp.async.wait_group 2;");
        else if (nIss == 1) asm volatile("cp.async.wait_group 1;");
        else                asm volatile("cp.async.wait_group 0;");
        __syncthreads();

        const char* knp = smem + SKNN + buf * 256;
        unsigned KHI = SKB + (unsigned)buf * 16384, KLO = KHI + 8192;

        // ---- S = Qhat . K^T  (3-split bf16, x4 B-fragments) ----
        float sc_[8][4];
        #pragma unroll
        for (int t = 0; t < 8; ++t)
            #pragma unroll
            for (int c = 0; c < 4; ++c) sc_[t][c] = 0.f;

        #pragma unroll
        for (int ks = 0; ks < 4; ++ks) {
            unsigned ah[4], al[4];
            unsigned aoff = a_rowoff + (((unsigned)(ks * 32) + a_cb) ^ a_x);
            ldsm4(ah, sbase + SQHI + aoff);
            ldsm4(al, sbase + SQLO + aoff);
            #pragma unroll
            for (int u = 0; u < 4; ++u) {
                unsigned jroff = (unsigned)((u * 16 + qhi_ * 8 + b_r) * 128);
                unsigned boff = jroff + (((unsigned)(ks * 32 + qlo_ * 16)) ^ bx);
                unsigned kh4[4], kl4[4];
                ldsm4(kh4, sbase + KHI + boff);
                ldsm4(kl4, sbase + KLO + boff);
                mma_bf16(sc_[2 * u],     ah, kh4);
                mma_bf16(sc_[2 * u],     ah, kl4);
                mma_bf16(sc_[2 * u],     al, kh4);
                mma_bf16(sc_[2 * u + 1], ah, kh4 + 2);
                mma_bf16(sc_[2 * u + 1], ah, kl4 + 2);
                mma_bf16(sc_[2 * u + 1], al, kh4 + 2);
            }
        }

        // ---- scores + online softmax (quad lanes share row) ----
        float mxA = -INFINITY, mxB = -INFINITY;
        #pragma unroll
        for (int t = 0; t < 8; ++t) {
            int jb = j0 + t * 8 + cA;
            float k0 = *(const float*)(knp + (t * 8 + cA) * 4);
            float k1 = *(const float*)(knp + (t * 8 + cA + 1) * 4);
            float s0 = fmaf(twokm, sc_[t][0], k0); if (jb     > igA) s0 = -INFINITY;
            float s1 = fmaf(twokm, sc_[t][1], k1); if (jb + 1 > igA) s1 = -INFINITY;
            float s2 = fmaf(twokm, sc_[t][2], k0); if (jb     > igB) s2 = -INFINITY;
            float s3 = fmaf(twokm, sc_[t][3], k1); if (jb + 1 > igB) s3 = -INFINITY;
            sc_[t][0] = s0; sc_[t][1] = s1; sc_[t][2] = s2; sc_[t][3] = s3;
            mxA = fmaxf(mxA, fmaxf(s0, s1));
            mxB = fmaxf(mxB, fmaxf(s2, s3));
        }
        mxA = fmaxf(mxA, __shfl_xor_sync(0xffffffffu, mxA, 1));
        mxA = fmaxf(mxA, __shfl_xor_sync(0xffffffffu, mxA, 2));
        mxB = fmaxf(mxB, __shfl_xor_sync(0xffffffffu, mxB, 1));
        mxB = fmaxf(mxB, __shfl_xor_sync(0xffffffffu, mxB, 2));

        float mnA = fmaxf(mA, mxA), mnB = fmaxf(mB, mxB);
        float scA = __expf(mA - mnA), scB = __expf(mB - mnB);
        mA = mnA; mB = mnB;
        float rsA = 0.f, rsB = 0.f;
        #pragma unroll
        for (int t = 0; t < 8; ++t) {
            float p0 = __expf(sc_[t][0] - mnA);
            float p1 = __expf(sc_[t][1] - mnA);
            float p2 = __expf(sc_[t][2] - mnB);
            float p3 = __expf(sc_[t][3] - mnB);
            sc_[t][0] = p0; sc_[t][1] = p1; sc_[t][2] = p2; sc_[t][3] = p3;
            rsA += p0 + p1; rsB += p2 + p3;
        }
        rsA += __shfl_xor_sync(0xffffffffu, rsA, 1);
        rsA += __shfl_xor_sync(0xffffffffu, rsA, 2);
        rsB += __shfl_xor_sync(0xffffffffu, rsB, 1);
        rsB += __shfl_xor_sync(0xffffffffu, rsB, 2);
        lA = lA * scA + rsA;
        lB = lB * scB + rsB;
        // skip the O-rescale when no row's max moved (warp-convergent test)
        if (!__all_sync(0xffffffffu, (scA == 1.f) & (scB == 1.f))) {
            #pragma unroll
            for (int t = 0; t < 8; ++t) {
                oc[t][0] *= scA; oc[t][1] *= scA;
                oc[t][2] *= scB; oc[t][3] *= scB;
            }
        }

        // ---- wait V(jt) arrival, then O += P . V (fp16: P single, V hi/lo) ----
        if (kIss) asm volatile("cp.async.wait_group 1;");
        else      asm volatile("cp.async.wait_group 0;");
        __syncthreads();

        #pragma unroll
        for (int ks = 0; ks < 4; ++ks) {
            unsigned pah[4];
            {
                __half2 t0 = __floats2half2_rn(sc_[2 * ks][0],     sc_[2 * ks][1]);
                __half2 t1 = __floats2half2_rn(sc_[2 * ks][2],     sc_[2 * ks][3]);
                __half2 t2 = __floats2half2_rn(sc_[2 * ks + 1][0], sc_[2 * ks + 1][1]);
                __half2 t3 = __floats2half2_rn(sc_[2 * ks + 1][2], sc_[2 * ks + 1][3]);
                pah[0] = *(unsigned*)&t0; pah[1] = *(unsigned*)&t1;
                pah[2] = *(unsigned*)&t2; pah[3] = *(unsigned*)&t3;
            }
            unsigned vroff = (unsigned)((ks * 16 + qlo_ * 8 + b_r) * 128);
            #pragma unroll
            for (int u = 0; u < 4; ++u) {
                unsigned voff = vroff + (((unsigned)((2 * u + qhi_) * 16)) ^ bx);
                unsigned vh4[4], vl4[4];
                ldsm4t(vh4, sbase + SVHI + voff);
                ldsm4t(vl4, sbase + SVLO + voff);
                mma_f16(oc[2 * u],     pah, vh4);
                mma_f16(oc[2 * u],     pah, vl4);
                mma_f16(oc[2 * u + 1], pah, vh4 + 2);
                mma_f16(oc[2 * u + 1], pah, vl4 + 2);
            }
        }
    }

    // ---- epilogue: out = queries + O / l ----
    float liA = 1.f / lA, liB = 1.f / lB;
    #pragma unroll
    for (int t = 0; t < 8; ++t) {
        int e = t * 8 + cA;
        size_t offA = ((size_t)((b * Lc + igA) * Hc + h)) * Ec + e;
        size_t offB = ((size_t)((b * Lc + igB) * Hc + h)) * Ec + e;
        float2 qa = *(const float2*)(q + offA);
        float2 qb = *(const float2*)(q + offB);
        *(float2*)(out + offA) = make_float2(qa.x + oc[t][0] * liA,
                                             qa.y + oc[t][1] * liA);
        *(float2*)(out + offB) = make_float2(qb.x + oc[t][2] * liB,
                                             qb.y + oc[t][3] * liB);
    }
}

// ---------------------------------------------------------------------------

extern "C" void kernel_launch(void* const* d_in, const int* in_sizes, int n_in,
                              void* d_out, int out_size)
{
    const float* q  = (const float*)d_in[0];
    const float* k  = (const float*)d_in[1];
    const float* v  = (const float*)d_in[2];
    const float* qm = (const float*)d_in[3];
    const float* kmsk = (const float*)d_in[4];
    const float* w  = (const float*)d_in[5];
    float* out = (float*)d_out;

    cudaFuncSetAttribute(stage2_kernel,
                         cudaFuncAttributeMaxDynamicSharedMemorySize, STOT);

    prep_kernel<<<NBH + NBH * 4, 1024>>>(q, w, qm, k, v, kmsk);
    gsum_kernel<<<dim3(NBH, 16), 256>>>(q);
    qhat_kernel<<<dim3(NBH, 16), 256>>>(q);

    dim3 grid(NBH, NIT);   // y slow => heavy tiles (it = NIT-1-y) first
    stage2_kernel<<<grid, 128, STOT>>>(q, kmsk, out);
}

// round 11
// speedup vs baseline: 1.1750x; 1.0246x over previous
#include <cuda_runtime.h>
#include <cuda_bf16.h>
#include <cuda_fp16.h>
#include <math.h>
#include <float.h>

#define Bc 4
#define Lc 1024
#define Hc 12
#define Ec 64
#define BM 64
#define BN 64
#define NIT (Lc / BM)    // 16 i-tiles
#define NBH (Bc * Hc)    // 48
#define PBH (Lc * 128)   // 131072 bytes per (b,h) per 16-bit array
#define L2E 1.4426950408889634f

// ---------------------------------------------------------------------------
// global scratch (allocation-free rule: __device__ globals)
// Q/K: bf16 hi/lo; V: fp16 hi/lo. All PRE-SWIZZLED like the stage2 smem tiles
// ---------------------------------------------------------------------------
__device__ __align__(16) unsigned char g_qhi[NBH * PBH];
__device__ __align__(16) unsigned char g_qlo[NBH * PBH];
__device__ __align__(16) unsigned char g_khi[NBH * PBH];
__device__ __align__(16) unsigned char g_klo[NBH * PBH];
__device__ __align__(16) unsigned char g_vhi[NBH * PBH];
__device__ __align__(16) unsigned char g_vlo[NBH * PBH];
__device__ float g_wexp[NBH * Lc];
__device__ float g_invz[NBH * Lc];
__device__ float g_kkn[NBH * Lc];          // -km * |k|^2 * log2(e)
__device__ float g_gq[NBH * 64 * Ec];      // 16-row sums [bh][g*4+r][e]

// ---------------------------------------------------------------------------
// helpers
// ---------------------------------------------------------------------------
__device__ __forceinline__ unsigned smem_u32(const void* p) {
    unsigned a;
    asm("{ .reg .u64 t; cvta.to.shared.u64 t, %1; cvt.u32.u64 %0, t; }"
        : "=r"(a) : "l"(p));
    return a;
}
__device__ __forceinline__ void cpa16(unsigned dst, const void* src) {
    asm volatile("cp.async.cg.shared.global [%0], [%1], 16;" :: "r"(dst), "l"(src));
}
__device__ __forceinline__ void ldsm4(unsigned* r, unsigned addr) {
    asm volatile("ldmatrix.sync.aligned.m8n8.x4.shared.b16 {%0,%1,%2,%3}, [%4];"
        : "=r"(r[0]), "=r"(r[1]), "=r"(r[2]), "=r"(r[3]) : "r"(addr));
}
__device__ __forceinline__ void ldsm4t(unsigned* r, unsigned addr) {
    asm volatile("ldmatrix.sync.aligned.m8n8.x4.trans.shared.b16 {%0,%1,%2,%3}, [%4];"
        : "=r"(r[0]), "=r"(r[1]), "=r"(r[2]), "=r"(r[3]) : "r"(addr));
}
__device__ __forceinline__ void mma_bf16(float* c, const unsigned* a, const unsigned* b) {
    asm volatile(
        "mma.sync.aligned.m16n8k16.row.col.f32.bf16.bf16.f32 "
        "{%0,%1,%2,%3}, {%4,%5,%6,%7}, {%8,%9}, {%0,%1,%2,%3};"
        : "+f"(c[0]), "+f"(c[1]), "+f"(c[2]), "+f"(c[3])
        : "r"(a[0]), "r"(a[1]), "r"(a[2]), "r"(a[3]), "r"(b[0]), "r"(b[1]));
}
__device__ __forceinline__ void mma_f16(float* c, const unsigned* a, const unsigned* b) {
    asm volatile(
        "mma.sync.aligned.m16n8k16.row.col.f32.f16.f16.f32 "
        "{%0,%1,%2,%3}, {%4,%5,%6,%7}, {%8,%9}, {%0,%1,%2,%3};"
        : "+f"(c[0]), "+f"(c[1]), "+f"(c[2]), "+f"(c[3])
        : "r"(a[0]), "r"(a[1]), "r"(a[2]), "r"(a[3]), "r"(b[0]), "r"(b[1]));
}
__device__ __forceinline__ unsigned h2exp2(unsigned x) {
    unsigned d;
    asm("ex2.approx.f16x2 %0, %1;" : "=r"(d) : "r"(x));
    return d;
}
__device__ __forceinline__ float ex2f(float x) {
    float d;
    asm("ex2.approx.f32 %0, %1;" : "=f"(d) : "f"(x));
    return d;
}
__device__ __forceinline__ void splitpack(float p0, float p1, unsigned& hi, unsigned& lo) {
    __nv_bfloat162 h2 = __floats2bfloat162_rn(p0, p1);
    float r0 = p0 - __low2float(h2);
    float r1 = p1 - __high2float(h2);
    __nv_bfloat162 l2 = __floats2bfloat162_rn(r0, r1);
    hi = *(unsigned*)&h2;
    lo = *(unsigned*)&l2;
}
__device__ __forceinline__ void splitpack_h(float p0, float p1, unsigned& hi, unsigned& lo) {
    __half2 h2 = __floats2half2_rn(p0, p1);
    float r0 = p0 - __low2float(h2);
    float r1 = p1 - __high2float(h2);
    __half2 l2 = __floats2half2_rn(r0, r1);
    hi = *(unsigned*)&h2;
    lo = *(unsigned*)&l2;
}
// swizzled byte offset within a (row, c4) cell; c4 = group of 4 elements
__device__ __forceinline__ unsigned swoff(int row, int c4) {
    return (unsigned)(row * 128 + ((c4 * 8) ^ ((row & 7) << 4)));
}

// stage2 smem: Q hi/lo 2x8K, K double buffers 2x16K, V single 16K, kn 2x256B
#define SQHI 0
#define SQLO 8192
#define SKB  16384            // + buf*16384 ; hi at +0, lo at +8192
#define SVHI 49152
#define SVLO 57344
#define SKNN 65536
#define STOT (65536 + 512)

// ---------------------------------------------------------------------------
// 1) merged: blocks [0,NBH) = score+scan; blocks [NBH, NBH+4*NBH) = prep_kv
// ---------------------------------------------------------------------------
__global__ void __launch_bounds__(1024) prep_kernel(
    const float* __restrict__ q, const float* __restrict__ wv,
    const float* __restrict__ q_mask,
    const float* __restrict__ k, const float* __restrict__ v,
    const float* __restrict__ k_mask)
{
    int tid = threadIdx.x;
    if (blockIdx.x >= NBH) {
        // ---------------- prep_kv part: 256 rows per block ----------------
        int pb = blockIdx.x - NBH;
        int bh = pb >> 2, qtr = pb & 3;
        int b = bh / Hc, h = bh % Hc;
        float km = k_mask[b * Lc];
        unsigned char* khi = g_khi + (size_t)bh * PBH;
        unsigned char* klo = g_klo + (size_t)bh * PBH;
        unsigned char* vhi = g_vhi + (size_t)bh * PBH;
        unsigned char* vlo = g_vlo + (size_t)bh * PBH;
        #pragma unroll
        for (int itr = 0; itr < 4; ++itr) {
            int idx = itr * 1024 + tid;
            int row = qtr * 256 + (idx >> 4), c4 = idx & 15;
            size_t goff = ((size_t)((b * Lc + row) * Hc + h)) * Ec + c4 * 4;
            unsigned off = swoff(row, c4);
            float4 kx = *(const float4*)(k + goff);
            {
                unsigned h0, l0_, h1, l1;
                splitpack(kx.x, kx.y, h0, l0_);
                splitpack(kx.z, kx.w, h1, l1);
                *(uint2*)(khi + off) = make_uint2(h0, h1);
                *(uint2*)(klo + off) = make_uint2(l0_, l1);
            }
            {
                float4 x = *(const float4*)(v + goff);
                unsigned h0, l0_, h1, l1;
                splitpack_h(x.x, x.y, h0, l0_);
                splitpack_h(x.z, x.w, h1, l1);
                *(uint2*)(vhi + off) = make_uint2(h0, h1);
                *(uint2*)(vlo + off) = make_uint2(l0_, l1);
            }
            float ps = kx.x * kx.x + kx.y * kx.y + kx.z * kx.z + kx.w * kx.w;
            #pragma unroll
            for (int o = 1; o < 16; o <<= 1) ps += __shfl_xor_sync(0xffffffffu, ps, o);
            if ((tid & 15) == 0) g_kkn[bh * Lc + row] = -km * ps * L2E;
        }
        return;
    }

    // ---------------- score + softmax-scan part ----------------
    int bh = blockIdx.x;
    int b = bh / Hc, h = bh % Hc;

    __shared__ float s_sh[Lc];
    __shared__ float w_sh[Ec];
    __shared__ float red[32];
    __shared__ float Msh;

    int lane = tid & 31, warp = tid >> 5;

    if (tid < Ec) w_sh[tid] = wv[h * Ec + tid];
    __syncthreads();
    float qm = q_mask[b * Lc];

    for (int j = warp; j < Lc; j += 32) {
        const float* qrow = q + ((size_t)((b * Lc + j) * Hc + h)) * Ec;
        float p = qrow[lane] * w_sh[lane] + qrow[lane + 32] * w_sh[lane + 32];
        #pragma unroll
        for (int o = 16; o; o >>= 1) p += __shfl_xor_sync(0xffffffffu, p, o);
        if (lane == 0) s_sh[j] = p * qm;
    }
    __syncthreads();

    float m = s_sh[tid];
    #pragma unroll
    for (int o = 16; o; o >>= 1) m = fmaxf(m, __shfl_xor_sync(0xffffffffu, m, o));
    if (lane == 0) red[warp] = m;
    __syncthreads();
    if (warp == 0) {
        float t = red[lane];
        #pragma unroll
        for (int o = 16; o; o >>= 1) t = fmaxf(t, __shfl_xor_sync(0xffffffffu, t, o));
        if (lane == 0) Msh = t;
    }
    __syncthreads();
    float M = Msh;

    float wexp = __expf(s_sh[tid] - M);
    float sc = wexp;
    #pragma unroll
    for (int o = 1; o < 32; o <<= 1) {
        float t = __shfl_up_sync(0xffffffffu, sc, o);
        if (lane >= o) sc += t;
    }
    if (lane == 31) red[warp] = sc;
    __syncthreads();
    if (warp == 0) {
        float v0 = red[lane];
        float scn = v0;
        #pragma unroll
        for (int o = 1; o < 32; o <<= 1) {
            float t = __shfl_up_sync(0xffffffffu, scn, o);
            if (lane >= o) scn += t;
        }
        red[lane] = scn - v0;
    }
    __syncthreads();
    float Z = sc + red[warp];
    g_wexp[bh * Lc + tid] = wexp;
    g_invz[bh * Lc + tid] = 1.0f / Z;
}

// ---------------------------------------------------------------------------
// 2) 16-row sums: g_gq[bh][g*4+r][e]. grid (NBH,16), 256 threads
// ---------------------------------------------------------------------------
__global__ void __launch_bounds__(256) gsum_kernel(const float* __restrict__ q)
{
    int bh = blockIdx.x, g = blockIdx.y;
    int b = bh / Hc, h = bh % Hc;
    int e = threadIdx.x & 63, r = threadIdx.x >> 6;
    int j0 = g * 64 + r * 16;
    float s = 0.f;
    #pragma unroll
    for (int jj = 0; jj < 16; ++jj) {
        int j = j0 + jj;
        s += g_wexp[bh * Lc + j] *
             q[((size_t)((b * Lc + j) * Hc + h)) * Ec + e];
    }
    g_gq[(bh * 64 + g * 4 + r) * Ec + e] = s;
}

// ---------------------------------------------------------------------------
// 3) qhat scan -> smem stage -> vectorized bf16 hi/lo. grid (NBH,16), 256 thr
// ---------------------------------------------------------------------------
__global__ void __launch_bounds__(256) qhat_kernel(const float* __restrict__ q)
{
    __shared__ float sbuf[64][64];
    int bh = blockIdx.x, g = blockIdx.y;
    int b = bh / Hc, h = bh % Hc;
    int e = threadIdx.x & 63, r = threadIdx.x >> 6;
    int gr = g * 4 + r;
    unsigned char* qhi = g_qhi + (size_t)bh * PBH;
    unsigned char* qlo = g_qlo + (size_t)bh * PBH;

    float acc = 0.f;
    const float* gq = g_gq + bh * 64 * Ec + e;
    for (int i = 0; i < gr; ++i) acc += gq[i * Ec];

    int j0 = g * 64 + r * 16;
    #pragma unroll
    for (int jj = 0; jj < 16; ++jj) {
        int j = j0 + jj;
        acc += g_wexp[bh * Lc + j] *
               q[((size_t)((b * Lc + j) * Hc + h)) * Ec + e];
        sbuf[r * 16 + jj][e] = acc * g_invz[bh * Lc + j];
    }
    __syncthreads();

    // phase 2: vectorized split + store
    #pragma unroll
    for (int itr = 0; itr < 4; ++itr) {
        int idx = itr * 256 + threadIdx.x;
        int lr = idx >> 4, c4 = idx & 15;
        float4 x = *(const float4*)&sbuf[lr][c4 * 4];
        unsigned h0, l0_, h1, l1;
        splitpack(x.x, x.y, h0, l0_);
        splitpack(x.z, x.w, h1, l1);
        unsigned off = swoff(g * 64 + lr, c4);
        *(uint2*)(qhi + off) = make_uint2(h0, h1);
        *(uint2*)(qlo + off) = make_uint2(l0_, l1);
    }
}

// ---------------------------------------------------------------------------
// 4) Stage 2: flash attention. S: 3-term split-bf16 MMA, log2-domain scores.
//    softmax exp via ex2.approx.f16x2 (packed, outputs are PV A-fragments).
//    PV: fp16, V 2-term hi/lo. K double-buffered, V single-buffered.
//    grid (NBH, NIT) heavy-first, 128 threads (4 warps x 16 rows), 3 CTAs/SM
// ---------------------------------------------------------------------------
__global__ void __launch_bounds__(128, 3) stage2_kernel(
    const float* __restrict__ q, const float* __restrict__ k_mask,
    float* __restrict__ out)
{
    extern __shared__ char smem[];
    const unsigned sbase = smem_u32(smem);
    int tid = threadIdx.x, lane = tid & 31, w = tid >> 5;
    int bh = blockIdx.x, b = bh / Hc, h = bh % Hc;
    int it = NIT - 1 - (int)blockIdx.y;   // heavy tiles first
    int i0 = it * BM;
    float twokm = 2.f * k_mask[b * Lc] * L2E;   // log2-domain scale
    const size_t bhoff = (size_t)bh * PBH;

    // ---- prologue: Q + K0 + V0 + kn0, one commit group ----
    {
        const unsigned char* sq_hi = g_qhi + bhoff + (size_t)i0 * 128;
        const unsigned char* sq_lo = g_qlo + bhoff + (size_t)i0 * 128;
        #pragma unroll
        for (int c = 0; c < 4; ++c) {
            unsigned off = (unsigned)((c * 128 + tid) * 16);
            cpa16(sbase + SQHI + off, sq_hi + off);
            cpa16(sbase + SQLO + off, sq_lo + off);
            cpa16(sbase + SKB + off,        g_khi + bhoff + off);
            cpa16(sbase + SKB + 8192 + off, g_klo + bhoff + off);
            cpa16(sbase + SVHI + off, g_vhi + bhoff + off);
            cpa16(sbase + SVLO + off, g_vlo + bhoff + off);
        }
        if (tid < BN)
            *(float*)(smem + SKNN + tid * 4) = g_kkn[bh * Lc + tid];
        asm volatile("cp.async.commit_group;");
    }

    // ---- per-lane fragment geometry ----
    int a_t = lane >> 3, a_r = lane & 7;
    int a_row = w * 16 + ((a_t & 1) << 3) + a_r;
    unsigned a_rowoff = (unsigned)(a_row * 128);
    unsigned a_x = (unsigned)((a_row & 7) << 4);
    unsigned a_cb = (unsigned)(((a_t >> 1) << 3) * 2);
    int quad = lane >> 3;                 // 0..3 (x4 B-fragment geometry)
    int qlo_ = quad & 1, qhi_ = quad >> 1;
    int b_r = lane & 7;
    unsigned bx = (unsigned)(b_r << 4);
    int rA = lane >> 2;
    int igA = i0 + w * 16 + rA, igB = igA + 8;
    int cA = (lane & 3) << 1;

    float oc[8][4];
    #pragma unroll
    for (int t = 0; t < 8; ++t)
        #pragma unroll
        for (int c = 0; c < 4; ++c) oc[t][c] = 0.f;
    float mA = -INFINITY, mB = -INFINITY, lA = 0.f, lB = 0.f;

    for (int jt = 0; jt <= it; ++jt) {
        int j0 = jt * BN;
        int buf = jt & 1;
        __syncthreads();   // all reads of V(jt-1), K(jt-1) buffer, kn(jt) staged

        // ---- issue V(jt) (jt>=1) and K(jt+1)+kn(jt+1) prefetches ----
        int nIss = 0;
        if (jt >= 1) {
            const size_t tg = bhoff + (size_t)j0 * 128;
            #pragma unroll
            for (int c = 0; c < 4; ++c) {
                unsigned off = (unsigned)((c * 128 + tid) * 16);
                cpa16(sbase + SVHI + off, g_vhi + tg + off);
                cpa16(sbase + SVLO + off, g_vlo + tg + off);
            }
            asm volatile("cp.async.commit_group;");
            ++nIss;
        }
        int kIss = 0;
        if (jt < it) {
            unsigned kb = SKB + (unsigned)(buf ^ 1) * 16384;
            const size_t tg = bhoff + (size_t)(j0 + BN) * 128;
            #pragma unroll
            for (int c = 0; c < 4; ++c) {
                unsigned off = (unsigned)((c * 128 + tid) * 16);
                cpa16(sbase + kb + off,        g_khi + tg + off);
                cpa16(sbase + kb + 8192 + off, g_klo + tg + off);
            }
            if (tid < BN)
                *(float*)(smem + SKNN + (buf ^ 1) * 256 + tid * 4) =
                    g_kkn[bh * Lc + j0 + BN + tid];
            asm volatile("cp.async.commit_group;");
            ++nIss; kIss = 1;
        }
        // wait: allow only the groups issued this iteration to be pending
        if (nIss == 2)      asm volatile("cp.async.wait_group 2;");
        else if (nIss == 1) asm volatile("cp.async.wait_group 1;");
        else                asm volatile("cp.async.wait_group 0;");
        __syncthreads();

        const char* knp = smem + SKNN + buf * 256;
        unsigned KHI = SKB + (unsigned)buf * 16384, KLO = KHI + 8192;

        // ---- S = Qhat . K^T  (3-split bf16, x4 B-fragments) ----
        float sc_[8][4];
        #pragma unroll
        for (int t = 0; t < 8; ++t)
            #pragma unroll
            for (int c = 0; c < 4; ++c) sc_[t][c] = 0.f;

        #pragma unroll
        for (int ks = 0; ks < 4; ++ks) {
            unsigned ah[4], al[4];
            unsigned aoff = a_rowoff + (((unsigned)(ks * 32) + a_cb) ^ a_x);
            ldsm4(ah, sbase + SQHI + aoff);
            ldsm4(al, sbase + SQLO + aoff);
            #pragma unroll
            for (int u = 0; u < 4; ++u) {
                unsigned jroff = (unsigned)((u * 16 + qhi_ * 8 + b_r) * 128);
                unsigned boff = jroff + (((unsigned)(ks * 32 + qlo_ * 16)) ^ bx);
                unsigned kh4[4], kl4[4];
                ldsm4(kh4, sbase + KHI + boff);
                ldsm4(kl4, sbase + KLO + boff);
                mma_bf16(sc_[2 * u],     ah, kh4);
                mma_bf16(sc_[2 * u],     ah, kl4);
                mma_bf16(sc_[2 * u],     al, kh4);
                mma_bf16(sc_[2 * u + 1], ah, kh4 + 2);
                mma_bf16(sc_[2 * u + 1], ah, kl4 + 2);
                mma_bf16(sc_[2 * u + 1], al, kh4 + 2);
            }
        }

        // ---- scores (log2 domain) + online softmax (quad lanes share row) ----
        float mxA = -INFINITY, mxB = -INFINITY;
        #pragma unroll
        for (int t = 0; t < 8; ++t) {
            int jb = j0 + t * 8 + cA;
            float k0 = *(const float*)(knp + (t * 8 + cA) * 4);
            float k1 = *(const float*)(knp + (t * 8 + cA + 1) * 4);
            float s0 = fmaf(twokm, sc_[t][0], k0); if (jb     > igA) s0 = -INFINITY;
            float s1 = fmaf(twokm, sc_[t][1], k1); if (jb + 1 > igA) s1 = -INFINITY;
            float s2 = fmaf(twokm, sc_[t][2], k0); if (jb     > igB) s2 = -INFINITY;
            float s3 = fmaf(twokm, sc_[t][3], k1); if (jb + 1 > igB) s3 = -INFINITY;
            sc_[t][0] = s0; sc_[t][1] = s1; sc_[t][2] = s2; sc_[t][3] = s3;
            mxA = fmaxf(mxA, fmaxf(s0, s1));
            mxB = fmaxf(mxB, fmaxf(s2, s3));
        }
        mxA = fmaxf(mxA, __shfl_xor_sync(0xffffffffu, mxA, 1));
        mxA = fmaxf(mxA, __shfl_xor_sync(0xffffffffu, mxA, 2));
        mxB = fmaxf(mxB, __shfl_xor_sync(0xffffffffu, mxB, 1));
        mxB = fmaxf(mxB, __shfl_xor_sync(0xffffffffu, mxB, 2));

        float mnA = fmaxf(mA, mxA), mnB = fmaxf(mB, mxB);
        float scA = ex2f(mA - mnA), scB = ex2f(mB - mnB);
        mA = mnA; mB = mnB;

        // packed fp16 exp: p = 2^(s - mn). Outputs ARE the PV A-fragments.
        unsigned pA[8], pB[8];
        float rsA = 0.f, rsB = 0.f;
        #pragma unroll
        for (int t = 0; t < 8; ++t) {
            __half2 hA = __floats2half2_rn(sc_[t][0] - mnA, sc_[t][1] - mnA);
            __half2 hB = __floats2half2_rn(sc_[t][2] - mnB, sc_[t][3] - mnB);
            pA[t] = h2exp2(*(unsigned*)&hA);
            pB[t] = h2exp2(*(unsigned*)&hB);
            float2 fa = __half22float2(*(__half2*)&pA[t]);
            float2 fb = __half22float2(*(__half2*)&pB[t]);
            rsA += fa.x + fa.y;
            rsB += fb.x + fb.y;
        }
        rsA += __shfl_xor_sync(0xffffffffu, rsA, 1);
        rsA += __shfl_xor_sync(0xffffffffu, rsA, 2);
        rsB += __shfl_xor_sync(0xffffffffu, rsB, 1);
        rsB += __shfl_xor_sync(0xffffffffu, rsB, 2);
        lA = lA * scA + rsA;
        lB = lB * scB + rsB;
        // skip the O-rescale when no row's max moved (warp-convergent test)
        if (!__all_sync(0xffffffffu, (scA == 1.f) & (scB == 1.f))) {
            #pragma unroll
            for (int t = 0; t < 8; ++t) {
                oc[t][0] *= scA; oc[t][1] *= scA;
                oc[t][2] *= scB; oc[t][3] *= scB;
            }
        }

        // ---- wait V(jt) arrival, then O += P . V (fp16: P single, V hi/lo) ----
        if (kIss) asm volatile("cp.async.wait_group 1;");
        else      asm volatile("cp.async.wait_group 0;");
        __syncthreads();

        #pragma unroll
        for (int ks = 0; ks < 4; ++ks) {
            unsigned pah[4];
            pah[0] = pA[2 * ks];     pah[1] = pB[2 * ks];
            pah[2] = pA[2 * ks + 1]; pah[3] = pB[2 * ks + 1];
            unsigned vroff = (unsigned)((ks * 16 + qlo_ * 8 + b_r) * 128);
            #pragma unroll
            for (int u = 0; u < 4; ++u) {
                unsigned voff = vroff + (((unsigned)((2 * u + qhi_) * 16)) ^ bx);
                unsigned vh4[4], vl4[4];
                ldsm4t(vh4, sbase + SVHI + voff);
                ldsm4t(vl4, sbase + SVLO + voff);
                mma_f16(oc[2 * u],     pah, vh4);
                mma_f16(oc[2 * u],     pah, vl4);
                mma_f16(oc[2 * u + 1], pah, vh4 + 2);
                mma_f16(oc[2 * u + 1], pah, vl4 + 2);
            }
        }
    }

    // ---- epilogue: out = queries + O / l ----
    float liA = 1.f / lA, liB = 1.f / lB;
    #pragma unroll
    for (int t = 0; t < 8; ++t) {
        int e = t * 8 + cA;
        size_t offA = ((size_t)((b * Lc + igA) * Hc + h)) * Ec + e;
        size_t offB = ((size_t)((b * Lc + igB) * Hc + h)) * Ec + e;
        float2 qa = *(const float2*)(q + offA);
        float2 qb = *(const float2*)(q + offB);
        *(float2*)(out + offA) = make_float2(qa.x + oc[t][0] * liA,
                                             qa.y + oc[t][1] * liA);
        *(float2*)(out + offB) = make_float2(qb.x + oc[t][2] * liB,
                                             qb.y + oc[t][3] * liB);
    }
}

// ---------------------------------------------------------------------------

extern "C" void kernel_launch(void* const* d_in, const int* in_sizes, int n_in,
                              void* d_out, int out_size)
{
    const float* q  = (const float*)d_in[0];
    const float* k  = (const float*)d_in[1];
    const float* v  = (const float*)d_in[2];
    const float* qm = (const float*)d_in[3];
    const float* kmsk = (const float*)d_in[4];
    const float* w  = (const float*)d_in[5];
    float* out = (float*)d_out;

    cudaFuncSetAttribute(stage2_kernel,
                         cudaFuncAttributeMaxDynamicSharedMemorySize, STOT);

    prep_kernel<<<NBH + NBH * 4, 1024>>>(q, w, qm, k, v, kmsk);
    gsum_kernel<<<dim3(NBH, 16), 256>>>(q);
    qhat_kernel<<<dim3(NBH, 16), 256>>>(q);

    dim3 grid(NBH, NIT);   // y slow => heavy tiles (it = NIT-1-y) first
    stage2_kernel<<<grid, 128, STOT>>>(q, kmsk, out);
}

// round 12
// speedup vs baseline: 1.3375x; 1.1383x over previous
#include <cuda_runtime.h>
#include <cuda_bf16.h>
#include <cuda_fp16.h>
#include <math.h>
#include <float.h>

#define Bc 4
#define Lc 1024
#define Hc 12
#define Ec 64
#define BM 64
#define BN 64
#define NIT (Lc / BM)    // 16 i-tiles
#define NBH (Bc * Hc)    // 48
#define PBH (Lc * 128)   // 131072 bytes per (b,h) per 16-bit array
#define L2E 1.4426950408889634f

// ---------------------------------------------------------------------------
// global scratch (allocation-free rule: __device__ globals)
// Q/K: bf16 hi/lo; V: plain fp16. All PRE-SWIZZLED like the stage2 smem tiles
// ---------------------------------------------------------------------------
__device__ __align__(16) unsigned char g_qhi[NBH * PBH];
__device__ __align__(16) unsigned char g_qlo[NBH * PBH];
__device__ __align__(16) unsigned char g_khi[NBH * PBH];
__device__ __align__(16) unsigned char g_klo[NBH * PBH];
__device__ __align__(16) unsigned char g_vhi[NBH * PBH];
__device__ float g_wexp[NBH * Lc];
__device__ float g_invz[NBH * Lc];
__device__ float g_kkn[NBH * Lc];          // -km * |k|^2 * log2(e)
__device__ float g_gq[NBH * 64 * Ec];      // 16-row sums [bh][g*4+r][e]

// ---------------------------------------------------------------------------
// helpers
// ---------------------------------------------------------------------------
__device__ __forceinline__ unsigned smem_u32(const void* p) {
    unsigned a;
    asm("{ .reg .u64 t; cvta.to.shared.u64 t, %1; cvt.u32.u64 %0, t; }"
        : "=r"(a) : "l"(p));
    return a;
}
__device__ __forceinline__ void cpa16(unsigned dst, const void* src) {
    asm volatile("cp.async.cg.shared.global [%0], [%1], 16;" :: "r"(dst), "l"(src));
}
__device__ __forceinline__ void ldsm4(unsigned* r, unsigned addr) {
    asm volatile("ldmatrix.sync.aligned.m8n8.x4.shared.b16 {%0,%1,%2,%3}, [%4];"
        : "=r"(r[0]), "=r"(r[1]), "=r"(r[2]), "=r"(r[3]) : "r"(addr));
}
__device__ __forceinline__ void ldsm4t(unsigned* r, unsigned addr) {
    asm volatile("ldmatrix.sync.aligned.m8n8.x4.trans.shared.b16 {%0,%1,%2,%3}, [%4];"
        : "=r"(r[0]), "=r"(r[1]), "=r"(r[2]), "=r"(r[3]) : "r"(addr));
}
__device__ __forceinline__ void mma_bf16(float* c, const unsigned* a, const unsigned* b) {
    asm volatile(
        "mma.sync.aligned.m16n8k16.row.col.f32.bf16.bf16.f32 "
        "{%0,%1,%2,%3}, {%4,%5,%6,%7}, {%8,%9}, {%0,%1,%2,%3};"
        : "+f"(c[0]), "+f"(c[1]), "+f"(c[2]), "+f"(c[3])
        : "r"(a[0]), "r"(a[1]), "r"(a[2]), "r"(a[3]), "r"(b[0]), "r"(b[1]));
}
__device__ __forceinline__ void mma_f16(float* c, const unsigned* a, const unsigned* b) {
    asm volatile(
        "mma.sync.aligned.m16n8k16.row.col.f32.f16.f16.f32 "
        "{%0,%1,%2,%3}, {%4,%5,%6,%7}, {%8,%9}, {%0,%1,%2,%3};"
        : "+f"(c[0]), "+f"(c[1]), "+f"(c[2]), "+f"(c[3])
        : "r"(a[0]), "r"(a[1]), "r"(a[2]), "r"(a[3]), "r"(b[0]), "r"(b[1]));
}
__device__ __forceinline__ unsigned h2exp2(unsigned x) {
    unsigned d;
    asm("ex2.approx.f16x2 %0, %1;" : "=r"(d) : "r"(x));
    return d;
}
__device__ __forceinline__ float ex2f(float x) {
    float d;
    asm("ex2.approx.f32 %0, %1;" : "=f"(d) : "f"(x));
    return d;
}
__device__ __forceinline__ void splitpack(float p0, float p1, unsigned& hi, unsigned& lo) {
    __nv_bfloat162 h2 = __floats2bfloat162_rn(p0, p1);
    float r0 = p0 - __low2float(h2);
    float r1 = p1 - __high2float(h2);
    __nv_bfloat162 l2 = __floats2bfloat162_rn(r0, r1);
    hi = *(unsigned*)&h2;
    lo = *(unsigned*)&l2;
}
// swizzled byte offset within a (row, c4) cell; c4 = group of 4 elements
__device__ __forceinline__ unsigned swoff(int row, int c4) {
    return (unsigned)(row * 128 + ((c4 * 8) ^ ((row & 7) << 4)));
}

// stage2 smem: Q hi/lo 2x8K; double-buffered {Khi 8K, Klo 8K, V 8K} x2; kn x2
#define SQHI 0
#define SQLO 8192
#define SKV  16384            // + buf*24576 ; Khi +0, Klo +8192, V +16384
#define SKNN 65536
#define STOT (65536 + 512)

// ---------------------------------------------------------------------------
// 1) merged: blocks [0,NBH) = score+scan; blocks [NBH, NBH+4*NBH) = prep_kv
// ---------------------------------------------------------------------------
__global__ void __launch_bounds__(1024) prep_kernel(
    const float* __restrict__ q, const float* __restrict__ wv,
    const float* __restrict__ q_mask,
    const float* __restrict__ k, const float* __restrict__ v,
    const float* __restrict__ k_mask)
{
    int tid = threadIdx.x;
    if (blockIdx.x >= NBH) {
        // ---------------- prep_kv part: 256 rows per block ----------------
        int pb = blockIdx.x - NBH;
        int bh = pb >> 2, qtr = pb & 3;
        int b = bh / Hc, h = bh % Hc;
        float km = k_mask[b * Lc];
        unsigned char* khi = g_khi + (size_t)bh * PBH;
        unsigned char* klo = g_klo + (size_t)bh * PBH;
        unsigned char* vhi = g_vhi + (size_t)bh * PBH;
        #pragma unroll
        for (int itr = 0; itr < 4; ++itr) {
            int idx = itr * 1024 + tid;
            int row = qtr * 256 + (idx >> 4), c4 = idx & 15;
            size_t goff = ((size_t)((b * Lc + row) * Hc + h)) * Ec + c4 * 4;
            unsigned off = swoff(row, c4);
            float4 kx = *(const float4*)(k + goff);
            {
                unsigned h0, l0_, h1, l1;
                splitpack(kx.x, kx.y, h0, l0_);
                splitpack(kx.z, kx.w, h1, l1);
                *(uint2*)(khi + off) = make_uint2(h0, h1);
                *(uint2*)(klo + off) = make_uint2(l0_, l1);
            }
            {
                float4 x = *(const float4*)(v + goff);
                __half2 a2 = __floats2half2_rn(x.x, x.y);
                __half2 b2 = __floats2half2_rn(x.z, x.w);
                *(uint2*)(vhi + off) = make_uint2(*(unsigned*)&a2, *(unsigned*)&b2);
            }
            float ps = kx.x * kx.x + kx.y * kx.y + kx.z * kx.z + kx.w * kx.w;
            #pragma unroll
            for (int o = 1; o < 16; o <<= 1) ps += __shfl_xor_sync(0xffffffffu, ps, o);
            if ((tid & 15) == 0) g_kkn[bh * Lc + row] = -km * ps * L2E;
        }
        return;
    }

    // ---------------- score + softmax-scan part ----------------
    int bh = blockIdx.x;
    int b = bh / Hc, h = bh % Hc;

    __shared__ float s_sh[Lc];
    __shared__ float w_sh[Ec];
    __shared__ float red[32];
    __shared__ float Msh;

    int lane = tid & 31, warp = tid >> 5;

    if (tid < Ec) w_sh[tid] = wv[h * Ec + tid];
    __syncthreads();
    float qm = q_mask[b * Lc];

    for (int j = warp; j < Lc; j += 32) {
        const float* qrow = q + ((size_t)((b * Lc + j) * Hc + h)) * Ec;
        float p = qrow[lane] * w_sh[lane] + qrow[lane + 32] * w_sh[lane + 32];
        #pragma unroll
        for (int o = 16; o; o >>= 1) p += __shfl_xor_sync(0xffffffffu, p, o);
        if (lane == 0) s_sh[j] = p * qm;
    }
    __syncthreads();

    float m = s_sh[tid];
    #pragma unroll
    for (int o = 16; o; o >>= 1) m = fmaxf(m, __shfl_xor_sync(0xffffffffu, m, o));
    if (lane == 0) red[warp] = m;
    __syncthreads();
    if (warp == 0) {
        float t = red[lane];
        #pragma unroll
        for (int o = 16; o; o >>= 1) t = fmaxf(t, __shfl_xor_sync(0xffffffffu, t, o));
        if (lane == 0) Msh = t;
    }
    __syncthreads();
    float M = Msh;

    float wexp = __expf(s_sh[tid] - M);
    float sc = wexp;
    #pragma unroll
    for (int o = 1; o < 32; o <<= 1) {
        float t = __shfl_up_sync(0xffffffffu, sc, o);
        if (lane >= o) sc += t;
    }
    if (lane == 31) red[warp] = sc;
    __syncthreads();
    if (warp == 0) {
        float v0 = red[lane];
        float scn = v0;
        #pragma unroll
        for (int o = 1; o < 32; o <<= 1) {
            float t = __shfl_up_sync(0xffffffffu, scn, o);
            if (lane >= o) scn += t;
        }
        red[lane] = scn - v0;
    }
    __syncthreads();
    float Z = sc + red[warp];
    g_wexp[bh * Lc + tid] = wexp;
    g_invz[bh * Lc + tid] = 1.0f / Z;
}

// ---------------------------------------------------------------------------
// 2) 16-row sums: g_gq[bh][g*4+r][e]. grid (NBH,16), 256 threads
// ---------------------------------------------------------------------------
__global__ void __launch_bounds__(256) gsum_kernel(const float* __restrict__ q)
{
    int bh = blockIdx.x, g = blockIdx.y;
    int b = bh / Hc, h = bh % Hc;
    int e = threadIdx.x & 63, r = threadIdx.x >> 6;
    int j0 = g * 64 + r * 16;
    float s = 0.f;
    #pragma unroll
    for (int jj = 0; jj < 16; ++jj) {
        int j = j0 + jj;
        s += g_wexp[bh * Lc + j] *
             q[((size_t)((b * Lc + j) * Hc + h)) * Ec + e];
    }
    g_gq[(bh * 64 + g * 4 + r) * Ec + e] = s;
}

// ---------------------------------------------------------------------------
// 3) qhat scan -> smem stage -> vectorized bf16 hi/lo. grid (NBH,16), 256 thr
// ---------------------------------------------------------------------------
__global__ void __launch_bounds__(256) qhat_kernel(const float* __restrict__ q)
{
    __shared__ float sbuf[64][64];
    int bh = blockIdx.x, g = blockIdx.y;
    int b = bh / Hc, h = bh % Hc;
    int e = threadIdx.x & 63, r = threadIdx.x >> 6;
    int gr = g * 4 + r;
    unsigned char* qhi = g_qhi + (size_t)bh * PBH;
    unsigned char* qlo = g_qlo + (size_t)bh * PBH;

    float acc = 0.f;
    const float* gq = g_gq + bh * 64 * Ec + e;
    for (int i = 0; i < gr; ++i) acc += gq[i * Ec];

    int j0 = g * 64 + r * 16;
    #pragma unroll
    for (int jj = 0; jj < 16; ++jj) {
        int j = j0 + jj;
        acc += g_wexp[bh * Lc + j] *
               q[((size_t)((b * Lc + j) * Hc + h)) * Ec + e];
        sbuf[r * 16 + jj][e] = acc * g_invz[bh * Lc + j];
    }
    __syncthreads();

    // phase 2: vectorized split + store
    #pragma unroll
    for (int itr = 0; itr < 4; ++itr) {
        int idx = itr * 256 + threadIdx.x;
        int lr = idx >> 4, c4 = idx & 15;
        float4 x = *(const float4*)&sbuf[lr][c4 * 4];
        unsigned h0, l0_, h1, l1;
        splitpack(x.x, x.y, h0, l0_);
        splitpack(x.z, x.w, h1, l1);
        unsigned off = swoff(g * 64 + lr, c4);
        *(uint2*)(qhi + off) = make_uint2(h0, h1);
        *(uint2*)(qlo + off) = make_uint2(l0_, l1);
    }
}

// ---------------------------------------------------------------------------
// 4) Stage 2: flash attention. S: 3-term split-bf16 MMA, log2-domain scores.
//    softmax exp via ex2.approx.f16x2 (outputs are PV A-fragments).
//    PV: plain fp16 V (32 MMAs/tile). K+V double-buffered together.
//    grid (NBH, NIT) heavy-first, 128 threads (4 warps x 16 rows), 3 CTAs/SM
// ---------------------------------------------------------------------------
__global__ void __launch_bounds__(128, 3) stage2_kernel(
    const float* __restrict__ q, const float* __restrict__ k_mask,
    float* __restrict__ out)
{
    extern __shared__ char smem[];
    const unsigned sbase = smem_u32(smem);
    int tid = threadIdx.x, lane = tid & 31, w = tid >> 5;
    int bh = blockIdx.x, b = bh / Hc, h = bh % Hc;
    int it = NIT - 1 - (int)blockIdx.y;   // heavy tiles first
    int i0 = it * BM;
    float twokm = 2.f * k_mask[b * Lc] * L2E;   // log2-domain scale
    const size_t bhoff = (size_t)bh * PBH;

    // ---- prologue: Q + K0 + V0 + kn0, one commit group ----
    {
        const unsigned char* sq_hi = g_qhi + bhoff + (size_t)i0 * 128;
        const unsigned char* sq_lo = g_qlo + bhoff + (size_t)i0 * 128;
        #pragma unroll
        for (int c = 0; c < 4; ++c) {
            unsigned off = (unsigned)((c * 128 + tid) * 16);
            cpa16(sbase + SQHI + off, sq_hi + off);
            cpa16(sbase + SQLO + off, sq_lo + off);
            cpa16(sbase + SKV + off,         g_khi + bhoff + off);
            cpa16(sbase + SKV + 8192 + off,  g_klo + bhoff + off);
            cpa16(sbase + SKV + 16384 + off, g_vhi + bhoff + off);
        }
        if (tid < BN)
            *(float*)(smem + SKNN + tid * 4) = g_kkn[bh * Lc + tid];
        asm volatile("cp.async.commit_group;");
    }

    // ---- per-lane fragment geometry ----
    int a_t = lane >> 3, a_r = lane & 7;
    int a_row = w * 16 + ((a_t & 1) << 3) + a_r;
    unsigned a_rowoff = (unsigned)(a_row * 128);
    unsigned a_x = (unsigned)((a_row & 7) << 4);
    unsigned a_cb = (unsigned)(((a_t >> 1) << 3) * 2);
    int quad = lane >> 3;                 // 0..3 (x4 B-fragment geometry)
    int qlo_ = quad & 1, qhi_ = quad >> 1;
    int b_r = lane & 7;
    unsigned bx = (unsigned)(b_r << 4);
    int rA = lane >> 2;
    int igA = i0 + w * 16 + rA, igB = igA + 8;
    int cA = (lane & 3) << 1;

    float oc[8][4];
    #pragma unroll
    for (int t = 0; t < 8; ++t)
        #pragma unroll
        for (int c = 0; c < 4; ++c) oc[t][c] = 0.f;
    float mA = -INFINITY, mB = -INFINITY, lA = 0.f, lB = 0.f;

    for (int jt = 0; jt <= it; ++jt) {
        int j0 = jt * BN;
        int buf = jt & 1;
        __syncthreads();   // all warps done reading buffer buf^1 (tile jt-1)

        // ---- prefetch K,V,kn of tile jt+1 into the other buffer ----
        int kIss = 0;
        if (jt < it) {
            unsigned kb = SKV + (unsigned)(buf ^ 1) * 24576;
            const size_t tg = bhoff + (size_t)(j0 + BN) * 128;
            #pragma unroll
            for (int c = 0; c < 4; ++c) {
                unsigned off = (unsigned)((c * 128 + tid) * 16);
                cpa16(sbase + kb + off,         g_khi + tg + off);
                cpa16(sbase + kb + 8192 + off,  g_klo + tg + off);
                cpa16(sbase + kb + 16384 + off, g_vhi + tg + off);
            }
            if (tid < BN)
                *(float*)(smem + SKNN + (buf ^ 1) * 256 + tid * 4) =
                    g_kkn[bh * Lc + j0 + BN + tid];
            asm volatile("cp.async.commit_group;");
            kIss = 1;
        }
        if (kIss) asm volatile("cp.async.wait_group 1;");
        else      asm volatile("cp.async.wait_group 0;");
        __syncthreads();   // tile jt fully resident

        const char* knp = smem + SKNN + buf * 256;
        unsigned kvb = SKV + (unsigned)buf * 24576;
        unsigned KHI = kvb, KLO = kvb + 8192, SV = kvb + 16384;

        // ---- S = Qhat . K^T  (3-split bf16, x4 B-fragments) ----
        float sc_[8][4];
        #pragma unroll
        for (int t = 0; t < 8; ++t)
            #pragma unroll
            for (int c = 0; c < 4; ++c) sc_[t][c] = 0.f;

        #pragma unroll
        for (int ks = 0; ks < 4; ++ks) {
            unsigned ah[4], al[4];
            unsigned aoff = a_rowoff + (((unsigned)(ks * 32) + a_cb) ^ a_x);
            ldsm4(ah, sbase + SQHI + aoff);
            ldsm4(al, sbase + SQLO + aoff);
            #pragma unroll
            for (int u = 0; u < 4; ++u) {
                unsigned jroff = (unsigned)((u * 16 + qhi_ * 8 + b_r) * 128);
                unsigned boff = jroff + (((unsigned)(ks * 32 + qlo_ * 16)) ^ bx);
                unsigned kh4[4], kl4[4];
                ldsm4(kh4, sbase + KHI + boff);
                ldsm4(kl4, sbase + KLO + boff);
                mma_bf16(sc_[2 * u],     ah, kh4);
                mma_bf16(sc_[2 * u],     ah, kl4);
                mma_bf16(sc_[2 * u],     al, kh4);
                mma_bf16(sc_[2 * u + 1], ah, kh4 + 2);
                mma_bf16(sc_[2 * u + 1], ah, kl4 + 2);
                mma_bf16(sc_[2 * u + 1], al, kh4 + 2);
            }
        }

        // ---- scores (log2 domain) + online softmax (quad lanes share row) ----
        float mxA = -INFINITY, mxB = -INFINITY;
        #pragma unroll
        for (int t = 0; t < 8; ++t) {
            int jb = j0 + t * 8 + cA;
            float k0 = *(const float*)(knp + (t * 8 + cA) * 4);
            float k1 = *(const float*)(knp + (t * 8 + cA + 1) * 4);
            float s0 = fmaf(twokm, sc_[t][0], k0); if (jb     > igA) s0 = -INFINITY;
            float s1 = fmaf(twokm, sc_[t][1], k1); if (jb + 1 > igA) s1 = -INFINITY;
            float s2 = fmaf(twokm, sc_[t][2], k0); if (jb     > igB) s2 = -INFINITY;
            float s3 = fmaf(twokm, sc_[t][3], k1); if (jb + 1 > igB) s3 = -INFINITY;
            sc_[t][0] = s0; sc_[t][1] = s1; sc_[t][2] = s2; sc_[t][3] = s3;
            mxA = fmaxf(mxA, fmaxf(s0, s1));
            mxB = fmaxf(mxB, fmaxf(s2, s3));
        }
        mxA = fmaxf(mxA, __shfl_xor_sync(0xffffffffu, mxA, 1));
        mxA = fmaxf(mxA, __shfl_xor_sync(0xffffffffu, mxA, 2));
        mxB = fmaxf(mxB, __shfl_xor_sync(0xffffffffu, mxB, 1));
        mxB = fmaxf(mxB, __shfl_xor_sync(0xffffffffu, mxB, 2));

        float mnA = fmaxf(mA, mxA), mnB = fmaxf(mB, mxB);
        float scA = ex2f(mA - mnA), scB = ex2f(mB - mnB);
        mA = mnA; mB = mnB;

        // packed fp16 exp: p = 2^(s - mn). Outputs ARE the PV A-fragments.
        unsigned pA[8], pB[8];
        float rsA = 0.f, rsB = 0.f;
        #pragma unroll
        for (int t = 0; t < 8; ++t) {
            __half2 hA = __floats2half2_rn(sc_[t][0] - mnA, sc_[t][1] - mnA);
            __half2 hB = __floats2half2_rn(sc_[t][2] - mnB, sc_[t][3] - mnB);
            pA[t] = h2exp2(*(unsigned*)&hA);
            pB[t] = h2exp2(*(unsigned*)&hB);
            float2 fa = __half22float2(*(__half2*)&pA[t]);
            float2 fb = __half22float2(*(__half2*)&pB[t]);
            rsA += fa.x + fa.y;
            rsB += fb.x + fb.y;
        }
        rsA += __shfl_xor_sync(0xffffffffu, rsA, 1);
        rsA += __shfl_xor_sync(0xffffffffu, rsA, 2);
        rsB += __shfl_xor_sync(0xffffffffu, rsB, 1);
        rsB += __shfl_xor_sync(0xffffffffu, rsB, 2);
        lA = lA * scA + rsA;
        lB = lB * scB + rsB;
        // skip the O-rescale when no row's max moved (warp-convergent test)
        if (!__all_sync(0xffffffffu, (scA == 1.f) & (scB == 1.f))) {
            #pragma unroll
            for (int t = 0; t < 8; ++t) {
                oc[t][0] *= scA; oc[t][1] *= scA;
                oc[t][2] *= scB; oc[t][3] *= scB;
            }
        }

        // ---- O += P . V  (plain fp16 V, x4t fragments) ----
        #pragma unroll
        for (int ks = 0; ks < 4; ++ks) {
            unsigned pah[4];
            pah[0] = pA[2 * ks];     pah[1] = pB[2 * ks];
            pah[2] = pA[2 * ks + 1]; pah[3] = pB[2 * ks + 1];
            unsigned vroff = (unsigned)((ks * 16 + qlo_ * 8 + b_r) * 128);
            #pragma unroll
            for (int u = 0; u < 4; ++u) {
                unsigned voff = vroff + (((unsigned)((2 * u + qhi_) * 16)) ^ bx);
                unsigned vh4[4];
                ldsm4t(vh4, sbase + SV + voff);
                mma_f16(oc[2 * u],     pah, vh4);
                mma_f16(oc[2 * u + 1], pah, vh4 + 2);
            }
        }
    }

    // ---- epilogue: out = queries + O / l ----
    float liA = 1.f / lA, liB = 1.f / lB;
    #pragma unroll
    for (int t = 0; t < 8; ++t) {
        int e = t * 8 + cA;
        size_t offA = ((size_t)((b * Lc + igA) * Hc + h)) * Ec + e;
        size_t offB = ((size_t)((b * Lc + igB) * Hc + h)) * Ec + e;
        float2 qa = *(const float2*)(q + offA);
        float2 qb = *(const float2*)(q + offB);
        *(float2*)(out + offA) = make_float2(qa.x + oc[t][0] * liA,
                                             qa.y + oc[t][1] * liA);
        *(float2*)(out + offB) = make_float2(qb.x + oc[t][2] * liB,
                                             qb.y + oc[t][3] * liB);
    }
}

// ---------------------------------------------------------------------------

extern "C" void kernel_launch(void* const* d_in, const int* in_sizes, int n_in,
                              void* d_out, int out_size)
{
    const float* q  = (const float*)d_in[0];
    const float* k  = (const float*)d_in[1];
    const float* v  = (const float*)d_in[2];
    const float* qm = (const float*)d_in[3];
    const float* kmsk = (const float*)d_in[4];
    const float* w  = (const float*)d_in[5];
    float* out = (float*)d_out;

    cudaFuncSetAttribute(stage2_kernel,
                         cudaFuncAttributeMaxDynamicSharedMemorySize, STOT);

    prep_kernel<<<NBH + NBH * 4, 1024>>>(q, w, qm, k, v, kmsk);
    gsum_kernel<<<dim3(NBH, 16), 256>>>(q);
    qhat_kernel<<<dim3(NBH, 16), 256>>>(q);

    dim3 grid(NBH, NIT);   // y slow => heavy tiles (it = NIT-1-y) first
    stage2_kernel<<<grid, 128, STOT>>>(q, kmsk, out);
}

// round 13
// speedup vs baseline: 1.3792x; 1.0312x over previous
#include <cuda_runtime.h>
#include <cuda_bf16.h>
#include <cuda_fp16.h>
#include <math.h>
#include <float.h>

#define Bc 4
#define Lc 1024
#define Hc 12
#define Ec 64
#define BM 64
#define BN 64
#define NIT (Lc / BM)    // 16 i-tiles
#define NBH (Bc * Hc)    // 48
#define PBH (Lc * 128)   // 131072 bytes per (b,h) per 16-bit array
#define L2E 1.4426950408889634f

// ---------------------------------------------------------------------------
// global scratch (allocation-free rule: __device__ globals)
// Q/K: bf16 hi/lo; V: plain fp16. All PRE-SWIZZLED like the stage2 smem tiles
// ---------------------------------------------------------------------------
__device__ __align__(16) unsigned char g_qhi[NBH * PBH];
__device__ __align__(16) unsigned char g_qlo[NBH * PBH];
__device__ __align__(16) unsigned char g_khi[NBH * PBH];
__device__ __align__(16) unsigned char g_klo[NBH * PBH];
__device__ __align__(16) unsigned char g_vhi[NBH * PBH];
__device__ float g_wexp[NBH * Lc];
__device__ float g_invz[NBH * Lc];
__device__ float g_kkn[NBH * Lc];          // -km * |k|^2 * log2(e)
__device__ float g_gqp[NBH * 64 * Ec];     // EXCLUSIVE prefix of 16-row sums

// ---------------------------------------------------------------------------
// helpers
// ---------------------------------------------------------------------------
__device__ __forceinline__ unsigned smem_u32(const void* p) {
    unsigned a;
    asm("{ .reg .u64 t; cvta.to.shared.u64 t, %1; cvt.u32.u64 %0, t; }"
        : "=r"(a) : "l"(p));
    return a;
}
__device__ __forceinline__ void cpa16(unsigned dst, const void* src) {
    asm volatile("cp.async.cg.shared.global [%0], [%1], 16;" :: "r"(dst), "l"(src));
}
__device__ __forceinline__ void ldsm4(unsigned* r, unsigned addr) {
    asm volatile("ldmatrix.sync.aligned.m8n8.x4.shared.b16 {%0,%1,%2,%3}, [%4];"
        : "=r"(r[0]), "=r"(r[1]), "=r"(r[2]), "=r"(r[3]) : "r"(addr));
}
__device__ __forceinline__ void ldsm4t(unsigned* r, unsigned addr) {
    asm volatile("ldmatrix.sync.aligned.m8n8.x4.trans.shared.b16 {%0,%1,%2,%3}, [%4];"
        : "=r"(r[0]), "=r"(r[1]), "=r"(r[2]), "=r"(r[3]) : "r"(addr));
}
__device__ __forceinline__ void mma_bf16(float* c, const unsigned* a, const unsigned* b) {
    asm volatile(
        "mma.sync.aligned.m16n8k16.row.col.f32.bf16.bf16.f32 "
        "{%0,%1,%2,%3}, {%4,%5,%6,%7}, {%8,%9}, {%0,%1,%2,%3};"
        : "+f"(c[0]), "+f"(c[1]), "+f"(c[2]), "+f"(c[3])
        : "r"(a[0]), "r"(a[1]), "r"(a[2]), "r"(a[3]), "r"(b[0]), "r"(b[1]));
}
__device__ __forceinline__ void mma_f16(float* c, const unsigned* a, const unsigned* b) {
    asm volatile(
        "mma.sync.aligned.m16n8k16.row.col.f32.f16.f16.f32 "
        "{%0,%1,%2,%3}, {%4,%5,%6,%7}, {%8,%9}, {%0,%1,%2,%3};"
        : "+f"(c[0]), "+f"(c[1]), "+f"(c[2]), "+f"(c[3])
        : "r"(a[0]), "r"(a[1]), "r"(a[2]), "r"(a[3]), "r"(b[0]), "r"(b[1]));
}
__device__ __forceinline__ unsigned h2exp2(unsigned x) {
    unsigned d;
    asm("ex2.approx.f16x2 %0, %1;" : "=r"(d) : "r"(x));
    return d;
}
__device__ __forceinline__ float ex2f(float x) {
    float d;
    asm("ex2.approx.f32 %0, %1;" : "=f"(d) : "f"(x));
    return d;
}
__device__ __forceinline__ void splitpack(float p0, float p1, unsigned& hi, unsigned& lo) {
    __nv_bfloat162 h2 = __floats2bfloat162_rn(p0, p1);
    float r0 = p0 - __low2float(h2);
    float r1 = p1 - __high2float(h2);
    __nv_bfloat162 l2 = __floats2bfloat162_rn(r0, r1);
    hi = *(unsigned*)&h2;
    lo = *(unsigned*)&l2;
}
// swizzled byte offset within a (row, c4) cell; c4 = group of 4 elements
__device__ __forceinline__ unsigned swoff(int row, int c4) {
    return (unsigned)(row * 128 + ((c4 * 8) ^ ((row & 7) << 4)));
}

// stage2 smem: Q hi/lo 2x8K; double-buffered {Khi 8K, Klo 8K, V 8K} x2; kn x2
#define SQHI 0
#define SQLO 8192
#define SKV  16384            // + buf*24576 ; Khi +0, Klo +8192, V +16384
#define SKNN 65536
#define STOT (65536 + 512)

// ---------------------------------------------------------------------------
// 1) merged: blocks [0,NBH) = score+scan+group-sums+prefix;
//            blocks [NBH, NBH+4*NBH) = prep_kv
// ---------------------------------------------------------------------------
__global__ void __launch_bounds__(1024) prep_kernel(
    const float* __restrict__ q, const float* __restrict__ wv,
    const float* __restrict__ q_mask,
    const float* __restrict__ k, const float* __restrict__ v,
    const float* __restrict__ k_mask)
{
    int tid = threadIdx.x;
    if (blockIdx.x >= NBH) {
        // ---------------- prep_kv part: 256 rows per block ----------------
        int pb = blockIdx.x - NBH;
        int bh = pb >> 2, qtr = pb & 3;
        int b = bh / Hc, h = bh % Hc;
        float km = k_mask[b * Lc];
        unsigned char* khi = g_khi + (size_t)bh * PBH;
        unsigned char* klo = g_klo + (size_t)bh * PBH;
        unsigned char* vhi = g_vhi + (size_t)bh * PBH;
        #pragma unroll
        for (int itr = 0; itr < 4; ++itr) {
            int idx = itr * 1024 + tid;
            int row = qtr * 256 + (idx >> 4), c4 = idx & 15;
            size_t goff = ((size_t)((b * Lc + row) * Hc + h)) * Ec + c4 * 4;
            unsigned off = swoff(row, c4);
            float4 kx = *(const float4*)(k + goff);
            {
                unsigned h0, l0_, h1, l1;
                splitpack(kx.x, kx.y, h0, l0_);
                splitpack(kx.z, kx.w, h1, l1);
                *(uint2*)(khi + off) = make_uint2(h0, h1);
                *(uint2*)(klo + off) = make_uint2(l0_, l1);
            }
            {
                float4 x = *(const float4*)(v + goff);
                __half2 a2 = __floats2half2_rn(x.x, x.y);
                __half2 b2 = __floats2half2_rn(x.z, x.w);
                *(uint2*)(vhi + off) = make_uint2(*(unsigned*)&a2, *(unsigned*)&b2);
            }
            float ps = kx.x * kx.x + kx.y * kx.y + kx.z * kx.z + kx.w * kx.w;
            #pragma unroll
            for (int o = 1; o < 16; o <<= 1) ps += __shfl_xor_sync(0xffffffffu, ps, o);
            if ((tid & 15) == 0) g_kkn[bh * Lc + row] = -km * ps * L2E;
        }
        return;
    }

    // ---------------- score + softmax-scan + group sums ----------------
    int bh = blockIdx.x;
    int b = bh / Hc, h = bh % Hc;

    __shared__ float s_sh[Lc];          // scores, then wexp
    __shared__ float gq_sh[64][Ec];     // 16-row sums, then exclusive prefix
    __shared__ float w_sh[Ec];
    __shared__ float red[32];
    __shared__ float Msh;

    int lane = tid & 31, warp = tid >> 5;

    if (tid < Ec) w_sh[tid] = wv[h * Ec + tid];
    __syncthreads();
    float qm = q_mask[b * Lc];

    for (int j = warp; j < Lc; j += 32) {
        const float* qrow = q + ((size_t)((b * Lc + j) * Hc + h)) * Ec;
        float p = qrow[lane] * w_sh[lane] + qrow[lane + 32] * w_sh[lane + 32];
        #pragma unroll
        for (int o = 16; o; o >>= 1) p += __shfl_xor_sync(0xffffffffu, p, o);
        if (lane == 0) s_sh[j] = p * qm;
    }
    __syncthreads();

    float m = s_sh[tid];
    #pragma unroll
    for (int o = 16; o; o >>= 1) m = fmaxf(m, __shfl_xor_sync(0xffffffffu, m, o));
    if (lane == 0) red[warp] = m;
    __syncthreads();
    if (warp == 0) {
        float t = red[lane];
        #pragma unroll
        for (int o = 16; o; o >>= 1) t = fmaxf(t, __shfl_xor_sync(0xffffffffu, t, o));
        if (lane == 0) Msh = t;
    }
    __syncthreads();
    float M = Msh;

    float wexp = __expf(s_sh[tid] - M);
    float sc = wexp;
    #pragma unroll
    for (int o = 1; o < 32; o <<= 1) {
        float t = __shfl_up_sync(0xffffffffu, sc, o);
        if (lane >= o) sc += t;
    }
    if (lane == 31) red[warp] = sc;
    __syncthreads();
    if (warp == 0) {
        float v0 = red[lane];
        float scn = v0;
        #pragma unroll
        for (int o = 1; o < 32; o <<= 1) {
            float t = __shfl_up_sync(0xffffffffu, scn, o);
            if (lane >= o) scn += t;
        }
        red[lane] = scn - v0;
    }
    __syncthreads();
    float Z = sc + red[warp];
    g_wexp[bh * Lc + tid] = wexp;
    g_invz[bh * Lc + tid] = 1.0f / Z;
    s_sh[tid] = wexp;      // each thread overwrites its own element
    __syncthreads();

    // ---- 16-row group sums: gq_sh[gr][e] = sum_{jj<16} wexp * q ----
    {
        int e = tid & 63, rb = tid >> 6;      // rb: 0..15
        const float* qcol = q + (((size_t)(b * Lc)) * Hc + h) * Ec + e;
        #pragma unroll
        for (int p = 0; p < 4; ++p) {
            int gr = p * 16 + rb;
            int j0 = gr * 16;
            float acc = 0.f;
            #pragma unroll
            for (int jj = 0; jj < 16; ++jj)
                acc += s_sh[j0 + jj] * qcol[(size_t)(j0 + jj) * (Hc * Ec)];
            gq_sh[gr][e] = acc;
        }
    }
    __syncthreads();

    // ---- exclusive prefix over the 64 groups (per e-lane) ----
    if (tid < Ec) {
        float run = 0.f;
        #pragma unroll
        for (int gr = 0; gr < 64; ++gr) {
            float t = gq_sh[gr][tid];
            gq_sh[gr][tid] = run;
            run += t;
        }
    }
    __syncthreads();

    // ---- write prefix to global ----
    {
        int e = tid & 63, rb = tid >> 6;
        #pragma unroll
        for (int p = 0; p < 4; ++p) {
            int gr = p * 16 + rb;
            g_gqp[(bh * 64 + gr) * Ec + e] = gq_sh[gr][e];
        }
    }
}

// ---------------------------------------------------------------------------
// 2) qhat scan (base from g_gqp) -> smem stage -> vectorized bf16 hi/lo
//    grid (NBH, 16), 256 threads
// ---------------------------------------------------------------------------
__global__ void __launch_bounds__(256) qhat_kernel(const float* __restrict__ q)
{
    __shared__ float sbuf[64][64];
    int bh = blockIdx.x, g = blockIdx.y;
    int b = bh / Hc, h = bh % Hc;
    int e = threadIdx.x & 63, r = threadIdx.x >> 6;
    int gr = g * 4 + r;
    unsigned char* qhi = g_qhi + (size_t)bh * PBH;
    unsigned char* qlo = g_qlo + (size_t)bh * PBH;

    float acc = g_gqp[(bh * 64 + gr) * Ec + e];

    int j0 = gr * 16;
    #pragma unroll
    for (int jj = 0; jj < 16; ++jj) {
        int j = j0 + jj;
        acc += g_wexp[bh * Lc + j] *
               q[((size_t)((b * Lc + j) * Hc + h)) * Ec + e];
        sbuf[r * 16 + jj][e] = acc * g_invz[bh * Lc + j];
    }
    __syncthreads();

    // phase 2: vectorized split + store
    #pragma unroll
    for (int itr = 0; itr < 4; ++itr) {
        int idx = itr * 256 + threadIdx.x;
        int lr = idx >> 4, c4 = idx & 15;
        float4 x = *(const float4*)&sbuf[lr][c4 * 4];
        unsigned h0, l0_, h1, l1;
        splitpack(x.x, x.y, h0, l0_);
        splitpack(x.z, x.w, h1, l1);
        unsigned off = swoff(g * 64 + lr, c4);
        *(uint2*)(qhi + off) = make_uint2(h0, h1);
        *(uint2*)(qlo + off) = make_uint2(l0_, l1);
    }
}

// ---------------------------------------------------------------------------
// 3) Stage 2: flash attention. S: 3-term split-bf16 MMA, log2-domain scores.
//    softmax exp via ex2.approx.f16x2 (outputs are PV A-fragments).
//    PV: plain fp16 V (32 MMAs/tile). K+V double-buffered together.
//    grid (NBH, NIT) heavy-first, 128 threads (4 warps x 16 rows), 3 CTAs/SM
// ---------------------------------------------------------------------------
__global__ void __launch_bounds__(128, 3) stage2_kernel(
    const float* __restrict__ q, const float* __restrict__ k_mask,
    float* __restrict__ out)
{
    extern __shared__ char smem[];
    const unsigned sbase = smem_u32(smem);
    int tid = threadIdx.x, lane = tid & 31, w = tid >> 5;
    int bh = blockIdx.x, b = bh / Hc, h = bh % Hc;
    int it = NIT - 1 - (int)blockIdx.y;   // heavy tiles first
    int i0 = it * BM;
    float twokm = 2.f * k_mask[b * Lc] * L2E;   // log2-domain scale
    const size_t bhoff = (size_t)bh * PBH;

    // ---- prologue: Q + K0 + V0 + kn0, one commit group ----
    {
        const unsigned char* sq_hi = g_qhi + bhoff + (size_t)i0 * 128;
        const unsigned char* sq_lo = g_qlo + bhoff + (size_t)i0 * 128;
        #pragma unroll
        for (int c = 0; c < 4; ++c) {
            unsigned off = (unsigned)((c * 128 + tid) * 16);
            cpa16(sbase + SQHI + off, sq_hi + off);
            cpa16(sbase + SQLO + off, sq_lo + off);
            cpa16(sbase + SKV + off,         g_khi + bhoff + off);
            cpa16(sbase + SKV + 8192 + off,  g_klo + bhoff + off);
            cpa16(sbase + SKV + 16384 + off, g_vhi + bhoff + off);
        }
        if (tid < BN)
            *(float*)(smem + SKNN + tid * 4) = g_kkn[bh * Lc + tid];
        asm volatile("cp.async.commit_group;");
    }

    // ---- per-lane fragment geometry ----
    int a_t = lane >> 3, a_r = lane & 7;
    int a_row = w * 16 + ((a_t & 1) << 3) + a_r;
    unsigned a_rowoff = (unsigned)(a_row * 128);
    unsigned a_x = (unsigned)((a_row & 7) << 4);
    unsigned a_cb = (unsigned)(((a_t >> 1) << 3) * 2);
    int quad = lane >> 3;                 // 0..3 (x4 B-fragment geometry)
    int qlo_ = quad & 1, qhi_ = quad >> 1;
    int b_r = lane & 7;
    unsigned bx = (unsigned)(b_r << 4);
    int rA = lane >> 2;
    int igA = i0 + w * 16 + rA, igB = igA + 8;
    int cA = (lane & 3) << 1;

    float oc[8][4];
    #pragma unroll
    for (int t = 0; t < 8; ++t)
        #pragma unroll
        for (int c = 0; c < 4; ++c) oc[t][c] = 0.f;
    float mA = -INFINITY, mB = -INFINITY, lA = 0.f, lB = 0.f;

    for (int jt = 0; jt <= it; ++jt) {
        int j0 = jt * BN;
        int buf = jt & 1;
        __syncthreads();   // all warps done reading buffer buf^1 (tile jt-1)

        // ---- prefetch K,V,kn of tile jt+1 into the other buffer ----
        int kIss = 0;
        if (jt < it) {
            unsigned kb = SKV + (unsigned)(buf ^ 1) * 24576;
            const size_t tg = bhoff + (size_t)(j0 + BN) * 128;
            #pragma unroll
            for (int c = 0; c < 4; ++c) {
                unsigned off = (unsigned)((c * 128 + tid) * 16);
                cpa16(sbase + kb + off,         g_khi + tg + off);
                cpa16(sbase + kb + 8192 + off,  g_klo + tg + off);
                cpa16(sbase + kb + 16384 + off, g_vhi + tg + off);
            }
            if (tid < BN)
                *(float*)(smem + SKNN + (buf ^ 1) * 256 + tid * 4) =
                    g_kkn[bh * Lc + j0 + BN + tid];
            asm volatile("cp.async.commit_group;");
            kIss = 1;
        }
        if (kIss) asm volatile("cp.async.wait_group 1;");
        else      asm volatile("cp.async.wait_group 0;");
        __syncthreads();   // tile jt fully resident

        const char* knp = smem + SKNN + buf * 256;
        unsigned kvb = SKV + (unsigned)buf * 24576;
        unsigned KHI = kvb, KLO = kvb + 8192, SV = kvb + 16384;

        // ---- S = Qhat . K^T  (3-split bf16, x4 B-fragments) ----
        float sc_[8][4];
        #pragma unroll
        for (int t = 0; t < 8; ++t)
            #pragma unroll
            for (int c = 0; c < 4; ++c) sc_[t][c] = 0.f;

        #pragma unroll
        for (int ks = 0; ks < 4; ++ks) {
            unsigned ah[4], al[4];
            unsigned aoff = a_rowoff + (((unsigned)(ks * 32) + a_cb) ^ a_x);
            ldsm4(ah, sbase + SQHI + aoff);
            ldsm4(al, sbase + SQLO + aoff);
            #pragma unroll
            for (int u = 0; u < 4; ++u) {
                unsigned jroff = (unsigned)((u * 16 + qhi_ * 8 + b_r) * 128);
                unsigned boff = jroff + (((unsigned)(ks * 32 + qlo_ * 16)) ^ bx);
                unsigned kh4[4], kl4[4];
                ldsm4(kh4, sbase + KHI + boff);
                ldsm4(kl4, sbase + KLO + boff);
                mma_bf16(sc_[2 * u],     ah, kh4);
                mma_bf16(sc_[2 * u],     ah, kl4);
                mma_bf16(sc_[2 * u],     al, kh4);
                mma_bf16(sc_[2 * u + 1], ah, kh4 + 2);
                mma_bf16(sc_[2 * u + 1], ah, kl4 + 2);
                mma_bf16(sc_[2 * u + 1], al, kh4 + 2);
            }
        }

        // ---- scores (log2 domain) + online softmax (quad lanes share row) ----
        float mxA = -INFINITY, mxB = -INFINITY;
        #pragma unroll
        for (int t = 0; t < 8; ++t) {
            int jb = j0 + t * 8 + cA;
            float k0 = *(const float*)(knp + (t * 8 + cA) * 4);
            float k1 = *(const float*)(knp + (t * 8 + cA + 1) * 4);
            float s0 = fmaf(twokm, sc_[t][0], k0); if (jb     > igA) s0 = -INFINITY;
            float s1 = fmaf(twokm, sc_[t][1], k1); if (jb + 1 > igA) s1 = -INFINITY;
            float s2 = fmaf(twokm, sc_[t][2], k0); if (jb     > igB) s2 = -INFINITY;
            float s3 = fmaf(twokm, sc_[t][3], k1); if (jb + 1 > igB) s3 = -INFINITY;
            sc_[t][0] = s0; sc_[t][1] = s1; sc_[t][2] = s2; sc_[t][3] = s3;
            mxA = fmaxf(mxA, fmaxf(s0, s1));
            mxB = fmaxf(mxB, fmaxf(s2, s3));
        }
        mxA = fmaxf(mxA, __shfl_xor_sync(0xffffffffu, mxA, 1));
        mxA = fmaxf(mxA, __shfl_xor_sync(0xffffffffu, mxA, 2));
        mxB = fmaxf(mxB, __shfl_xor_sync(0xffffffffu, mxB, 1));
        mxB = fmaxf(mxB, __shfl_xor_sync(0xffffffffu, mxB, 2));

        float mnA = fmaxf(mA, mxA), mnB = fmaxf(mB, mxB);
        float scA = ex2f(mA - mnA), scB = ex2f(mB - mnB);
        mA = mnA; mB = mnB;

        // packed fp16 exp: p = 2^(s - mn). Outputs ARE the PV A-fragments.
        unsigned pA[8], pB[8];
        float rsA = 0.f, rsB = 0.f;
        #pragma unroll
        for (int t = 0; t < 8; ++t) {
            __half2 hA = __floats2half2_rn(sc_[t][0] - mnA, sc_[t][1] - mnA);
            __half2 hB = __floats2half2_rn(sc_[t][2] - mnB, sc_[t][3] - mnB);
            pA[t] = h2exp2(*(unsigned*)&hA);
            pB[t] = h2exp2(*(unsigned*)&hB);
            float2 fa = __half22float2(*(__half2*)&pA[t]);
            float2 fb = __half22float2(*(__half2*)&pB[t]);
            rsA += fa.x + fa.y;
            rsB += fb.x + fb.y;
        }
        rsA += __shfl_xor_sync(0xffffffffu, rsA, 1);
        rsA += __shfl_xor_sync(0xffffffffu, rsA, 2);
        rsB += __shfl_xor_sync(0xffffffffu, rsB, 1);
        rsB += __shfl_xor_sync(0xffffffffu, rsB, 2);
        lA = lA * scA + rsA;
        lB = lB * scB + rsB;
        // skip the O-rescale when no row's max moved (warp-convergent test)
        if (!__all_sync(0xffffffffu, (scA == 1.f) & (scB == 1.f))) {
            #pragma unroll
            for (int t = 0; t < 8; ++t) {
                oc[t][0] *= scA; oc[t][1] *= scA;
                oc[t][2] *= scB; oc[t][3] *= scB;
            }
        }

        // ---- O += P . V  (plain fp16 V, x4t fragments) ----
        #pragma unroll
        for (int ks = 0; ks < 4; ++ks) {
            unsigned pah[4];
            pah[0] = pA[2 * ks];     pah[1] = pB[2 * ks];
            pah[2] = pA[2 * ks + 1]; pah[3] = pB[2 * ks + 1];
            unsigned vroff = (unsigned)((ks * 16 + qlo_ * 8 + b_r) * 128);
            #pragma unroll
            for (int u = 0; u < 4; ++u) {
                unsigned voff = vroff + (((unsigned)((2 * u + qhi_) * 16)) ^ bx);
                unsigned vh4[4];
                ldsm4t(vh4, sbase + SV + voff);
                mma_f16(oc[2 * u],     pah, vh4);
                mma_f16(oc[2 * u + 1], pah, vh4 + 2);
            }
        }
    }

    // ---- epilogue: out = queries + O / l ----
    float liA = 1.f / lA, liB = 1.f / lB;
    #pragma unroll
    for (int t = 0; t < 8; ++t) {
        int e = t * 8 + cA;
        size_t offA = ((size_t)((b * Lc + igA) * Hc + h)) * Ec + e;
        size_t offB = ((size_t)((b * Lc + igB) * Hc + h)) * Ec + e;
        float2 qa = *(const float2*)(q + offA);
        float2 qb = *(const float2*)(q + offB);
        *(float2*)(out + offA) = make_float2(qa.x + oc[t][0] * liA,
                                             qa.y + oc[t][1] * liA);
        *(float2*)(out + offB) = make_float2(qb.x + oc[t][2] * liB,
                                             qb.y + oc[t][3] * liB);
    }
}

// ---------------------------------------------------------------------------

extern "C" void kernel_launch(void* const* d_in, const int* in_sizes, int n_in,
                              void* d_out, int out_size)
{
    const float* q  = (const float*)d_in[0];
    const float* k  = (const float*)d_in[1];
    const float* v  = (const float*)d_in[2];
    const float* qm = (const float*)d_in[3];
    const float* kmsk = (const float*)d_in[4];
    const float* w  = (const float*)d_in[5];
    float* out = (float*)d_out;

    cudaFuncSetAttribute(stage2_kernel,
                         cudaFuncAttributeMaxDynamicSharedMemorySize, STOT);

    prep_kernel<<<NBH + NBH * 4, 1024>>>(q, w, qm, k, v, kmsk);
    qhat_kernel<<<dim3(NBH, 16), 256>>>(q);

    dim3 grid(NBH, NIT);   // y slow => heavy tiles (it = NIT-1-y) first
    stage2_kernel<<<grid, 128, STOT>>>(q, kmsk, out);
}

// round 14
// speedup vs baseline: 1.4609x; 1.0593x over previous
#include <cuda_runtime.h>
#include <cuda_bf16.h>
#include <cuda_fp16.h>
#include <math.h>
#include <float.h>

#define Bc 4
#define Lc 1024
#define Hc 12
#define Ec 64
#define BM 64
#define BN 64
#define NIT (Lc / BM)    // 16 i-tiles
#define NBH (Bc * Hc)    // 48
#define PBH (Lc * 128)   // 131072 bytes per (b,h) per 16-bit array
#define L2E 1.4426950408889634f

// ---------------------------------------------------------------------------
// global scratch (allocation-free rule: __device__ globals)
// K: bf16 hi/lo; V: plain fp16. PRE-SWIZZLED like the stage2 smem tiles.
// Q-hat is computed inside stage2 (fused scan) — no global image needed.
// ---------------------------------------------------------------------------
__device__ __align__(16) unsigned char g_khi[NBH * PBH];
__device__ __align__(16) unsigned char g_klo[NBH * PBH];
__device__ __align__(16) unsigned char g_vhi[NBH * PBH];
__device__ float g_wexp[NBH * Lc];
__device__ float g_invz[NBH * Lc];
__device__ float g_kkn[NBH * Lc];          // -km * |k|^2 * log2(e)
__device__ float g_gqp[NBH * 64 * Ec];     // EXCLUSIVE prefix of 16-row sums

// ---------------------------------------------------------------------------
// helpers
// ---------------------------------------------------------------------------
__device__ __forceinline__ unsigned smem_u32(const void* p) {
    unsigned a;
    asm("{ .reg .u64 t; cvta.to.shared.u64 t, %1; cvt.u32.u64 %0, t; }"
        : "=r"(a) : "l"(p));
    return a;
}
__device__ __forceinline__ void cpa16(unsigned dst, const void* src) {
    asm volatile("cp.async.cg.shared.global [%0], [%1], 16;" :: "r"(dst), "l"(src));
}
__device__ __forceinline__ void ldsm4(unsigned* r, unsigned addr) {
    asm volatile("ldmatrix.sync.aligned.m8n8.x4.shared.b16 {%0,%1,%2,%3}, [%4];"
        : "=r"(r[0]), "=r"(r[1]), "=r"(r[2]), "=r"(r[3]) : "r"(addr));
}
__device__ __forceinline__ void ldsm4t(unsigned* r, unsigned addr) {
    asm volatile("ldmatrix.sync.aligned.m8n8.x4.trans.shared.b16 {%0,%1,%2,%3}, [%4];"
        : "=r"(r[0]), "=r"(r[1]), "=r"(r[2]), "=r"(r[3]) : "r"(addr));
}
__device__ __forceinline__ void mma_bf16(float* c, const unsigned* a, const unsigned* b) {
    asm volatile(
        "mma.sync.aligned.m16n8k16.row.col.f32.bf16.bf16.f32 "
        "{%0,%1,%2,%3}, {%4,%5,%6,%7}, {%8,%9}, {%0,%1,%2,%3};"
        : "+f"(c[0]), "+f"(c[1]), "+f"(c[2]), "+f"(c[3])
        : "r"(a[0]), "r"(a[1]), "r"(a[2]), "r"(a[3]), "r"(b[0]), "r"(b[1]));
}
__device__ __forceinline__ void mma_f16(float* c, const unsigned* a, const unsigned* b) {
    asm volatile(
        "mma.sync.aligned.m16n8k16.row.col.f32.f16.f16.f32 "
        "{%0,%1,%2,%3}, {%4,%5,%6,%7}, {%8,%9}, {%0,%1,%2,%3};"
        : "+f"(c[0]), "+f"(c[1]), "+f"(c[2]), "+f"(c[3])
        : "r"(a[0]), "r"(a[1]), "r"(a[2]), "r"(a[3]), "r"(b[0]), "r"(b[1]));
}
__device__ __forceinline__ unsigned h2exp2(unsigned x) {
    unsigned d;
    asm("ex2.approx.f16x2 %0, %1;" : "=r"(d) : "r"(x));
    return d;
}
__device__ __forceinline__ float ex2f(float x) {
    float d;
    asm("ex2.approx.f32 %0, %1;" : "=f"(d) : "f"(x));
    return d;
}
__device__ __forceinline__ void splitpack(float p0, float p1, unsigned& hi, unsigned& lo) {
    __nv_bfloat162 h2 = __floats2bfloat162_rn(p0, p1);
    float r0 = p0 - __low2float(h2);
    float r1 = p1 - __high2float(h2);
    __nv_bfloat162 l2 = __floats2bfloat162_rn(r0, r1);
    hi = *(unsigned*)&h2;
    lo = *(unsigned*)&l2;
}
// swizzled byte offset within a (row, c4) cell; c4 = group of 4 elements
__device__ __forceinline__ unsigned swoff(int row, int c4) {
    return (unsigned)(row * 128 + ((c4 * 8) ^ ((row & 7) << 4)));
}

// stage2 smem: Q hi/lo 2x8K; double-buffered {Khi 8K, Klo 8K, V 8K} x2; kn x2
#define SQHI 0
#define SQLO 8192
#define SKV  16384            // + buf*24576 ; Khi +0, Klo +8192, V +16384
#define SKNN 65536
#define STOT (65536 + 512)

// ---------------------------------------------------------------------------
// 1) merged: blocks [0,NBH) = score+scan+group-sums+prefix;
//            blocks [NBH, NBH+4*NBH) = prep_kv
// ---------------------------------------------------------------------------
__global__ void __launch_bounds__(1024) prep_kernel(
    const float* __restrict__ q, const float* __restrict__ wv,
    const float* __restrict__ q_mask,
    const float* __restrict__ k, const float* __restrict__ v,
    const float* __restrict__ k_mask)
{
    int tid = threadIdx.x;
    if (blockIdx.x >= NBH) {
        // ---------------- prep_kv part: 256 rows per block ----------------
        int pb = blockIdx.x - NBH;
        int bh = pb >> 2, qtr = pb & 3;
        int b = bh / Hc, h = bh % Hc;
        float km = k_mask[b * Lc];
        unsigned char* khi = g_khi + (size_t)bh * PBH;
        unsigned char* klo = g_klo + (size_t)bh * PBH;
        unsigned char* vhi = g_vhi + (size_t)bh * PBH;
        #pragma unroll
        for (int itr = 0; itr < 4; ++itr) {
            int idx = itr * 1024 + tid;
            int row = qtr * 256 + (idx >> 4), c4 = idx & 15;
            size_t goff = ((size_t)((b * Lc + row) * Hc + h)) * Ec + c4 * 4;
            unsigned off = swoff(row, c4);
            float4 kx = *(const float4*)(k + goff);
            {
                unsigned h0, l0_, h1, l1;
                splitpack(kx.x, kx.y, h0, l0_);
                splitpack(kx.z, kx.w, h1, l1);
                *(uint2*)(khi + off) = make_uint2(h0, h1);
                *(uint2*)(klo + off) = make_uint2(l0_, l1);
            }
            {
                float4 x = *(const float4*)(v + goff);
                __half2 a2 = __floats2half2_rn(x.x, x.y);
                __half2 b2 = __floats2half2_rn(x.z, x.w);
                *(uint2*)(vhi + off) = make_uint2(*(unsigned*)&a2, *(unsigned*)&b2);
            }
            float ps = kx.x * kx.x + kx.y * kx.y + kx.z * kx.z + kx.w * kx.w;
            #pragma unroll
            for (int o = 1; o < 16; o <<= 1) ps += __shfl_xor_sync(0xffffffffu, ps, o);
            if ((tid & 15) == 0) g_kkn[bh * Lc + row] = -km * ps * L2E;
        }
        return;
    }

    // ---------------- score + softmax-scan + group sums ----------------
    int bh = blockIdx.x;
    int b = bh / Hc, h = bh % Hc;

    __shared__ float s_sh[Lc];          // scores, then wexp
    __shared__ float gq_sh[64][Ec];     // 16-row sums, then exclusive prefix
    __shared__ float w_sh[Ec];
    __shared__ float red[32];
    __shared__ float Msh;

    int lane = tid & 31, warp = tid >> 5;

    if (tid < Ec) w_sh[tid] = wv[h * Ec + tid];
    __syncthreads();
    float qm = q_mask[b * Lc];

    for (int j = warp; j < Lc; j += 32) {
        const float* qrow = q + ((size_t)((b * Lc + j) * Hc + h)) * Ec;
        float p = qrow[lane] * w_sh[lane] + qrow[lane + 32] * w_sh[lane + 32];
        #pragma unroll
        for (int o = 16; o; o >>= 1) p += __shfl_xor_sync(0xffffffffu, p, o);
        if (lane == 0) s_sh[j] = p * qm;
    }
    __syncthreads();

    float m = s_sh[tid];
    #pragma unroll
    for (int o = 16; o; o >>= 1) m = fmaxf(m, __shfl_xor_sync(0xffffffffu, m, o));
    if (lane == 0) red[warp] = m;
    __syncthreads();
    if (warp == 0) {
        float t = red[lane];
        #pragma unroll
        for (int o = 16; o; o >>= 1) t = fmaxf(t, __shfl_xor_sync(0xffffffffu, t, o));
        if (lane == 0) Msh = t;
    }
    __syncthreads();
    float M = Msh;

    float wexp = __expf(s_sh[tid] - M);
    float sc = wexp;
    #pragma unroll
    for (int o = 1; o < 32; o <<= 1) {
        float t = __shfl_up_sync(0xffffffffu, sc, o);
        if (lane >= o) sc += t;
    }
    if (lane == 31) red[warp] = sc;
    __syncthreads();
    if (warp == 0) {
        float v0 = red[lane];
        float scn = v0;
        #pragma unroll
        for (int o = 1; o < 32; o <<= 1) {
            float t = __shfl_up_sync(0xffffffffu, scn, o);
            if (lane >= o) scn += t;
        }
        red[lane] = scn - v0;
    }
    __syncthreads();
    float Z = sc + red[warp];
    g_wexp[bh * Lc + tid] = wexp;
    g_invz[bh * Lc + tid] = 1.0f / Z;
    s_sh[tid] = wexp;      // each thread overwrites its own element
    __syncthreads();

    // ---- 16-row group sums: gq_sh[gr][e] = sum_{jj<16} wexp * q ----
    {
        int e = tid & 63, rb = tid >> 6;      // rb: 0..15
        const float* qcol = q + (((size_t)(b * Lc)) * Hc + h) * Ec + e;
        #pragma unroll
        for (int p = 0; p < 4; ++p) {
            int gr = p * 16 + rb;
            int j0 = gr * 16;
            float acc = 0.f;
            #pragma unroll
            for (int jj = 0; jj < 16; ++jj)
                acc += s_sh[j0 + jj] * qcol[(size_t)(j0 + jj) * (Hc * Ec)];
            gq_sh[gr][e] = acc;
        }
    }
    __syncthreads();

    // ---- exclusive prefix over the 64 groups (per e-lane) ----
    if (tid < Ec) {
        float run = 0.f;
        #pragma unroll
        for (int gr = 0; gr < 64; ++gr) {
            float t = gq_sh[gr][tid];
            gq_sh[gr][tid] = run;
            run += t;
        }
    }
    __syncthreads();

    // ---- write prefix to global ----
    {
        int e = tid & 63, rb = tid >> 6;
        #pragma unroll
        for (int p = 0; p < 4; ++p) {
            int gr = p * 16 + rb;
            g_gqp[(bh * 64 + gr) * Ec + e] = gq_sh[gr][e];
        }
    }
}

// ---------------------------------------------------------------------------
// 2) Stage 2: flash attention with FUSED qhat scan in the prologue.
//    S: 3-term split-bf16 MMA, log2-domain scores; exp via ex2.approx.f16x2;
//    PV: plain fp16 V. K+V double-buffered.
//    grid (NBH, NIT) heavy-first, 128 threads (4 warps x 16 rows), 3 CTAs/SM
// ---------------------------------------------------------------------------
__global__ void __launch_bounds__(128, 3) stage2_kernel(
    const float* __restrict__ q, const float* __restrict__ k_mask,
    float* __restrict__ out)
{
    extern __shared__ char smem[];
    const unsigned sbase = smem_u32(smem);
    int tid = threadIdx.x, lane = tid & 31, w = tid >> 5;
    int bh = blockIdx.x, b = bh / Hc, h = bh % Hc;
    int it = NIT - 1 - (int)blockIdx.y;   // heavy tiles first
    int i0 = it * BM;
    float twokm = 2.f * k_mask[b * Lc] * L2E;   // log2-domain scale
    const size_t bhoff = (size_t)bh * PBH;

    // ---- prologue A: issue K0 + V0 + kn0 prefetch ----
    {
        #pragma unroll
        for (int c = 0; c < 4; ++c) {
            unsigned off = (unsigned)((c * 128 + tid) * 16);
            cpa16(sbase + SKV + off,         g_khi + bhoff + off);
            cpa16(sbase + SKV + 8192 + off,  g_klo + bhoff + off);
            cpa16(sbase + SKV + 16384 + off, g_vhi + bhoff + off);
        }
        if (tid < BN)
            *(float*)(smem + SKNN + tid * 4) = g_kkn[bh * Lc + tid];
        asm volatile("cp.async.commit_group;");
    }

    // ---- prologue B: fused qhat scan -> split-bf16 Q tile in smem ----
    // 128 threads = 64 e-lanes x 2 group-pairs; 2 chains of 16 rows each.
    {
        int e = tid & 63, gp = tid >> 6;                 // gp: 0..1
        unsigned ebase = (unsigned)((e >> 2) * 8);
        unsigned elow = (unsigned)((e & 3) * 2);
        #pragma unroll
        for (int gg = 0; gg < 2; ++gg) {
            int g = gp * 2 + gg;                          // 0..3
            int gr = (i0 >> 4) + g;
            float acc = g_gqp[(bh * 64 + gr) * Ec + e];
            int jbase = i0 + g * 16;
            #pragma unroll
            for (int jj = 0; jj < 16; ++jj) {
                int j = jbase + jj;
                acc += g_wexp[bh * Lc + j] *
                       q[((size_t)((b * Lc + j) * Hc + h)) * Ec + e];
                float val = acc * g_invz[bh * Lc + j];
                int row = g * 16 + jj;
                __nv_bfloat16 hb = __float2bfloat16_rn(val);
                __nv_bfloat16 lb = __float2bfloat16_rn(val - __bfloat162float(hb));
                unsigned off = (unsigned)(row * 128) + (ebase ^ ((row & 7) << 4)) + elow;
                *(__nv_bfloat16*)(smem + SQHI + off) = hb;
                *(__nv_bfloat16*)(smem + SQLO + off) = lb;
            }
        }
    }
    __syncthreads();   // Q tile visible to all warps

    // ---- per-lane fragment geometry ----
    int a_t = lane >> 3, a_r = lane & 7;
    int a_row = w * 16 + ((a_t & 1) << 3) + a_r;
    unsigned a_rowoff = (unsigned)(a_row * 128);
    unsigned a_x = (unsigned)((a_row & 7) << 4);
    unsigned a_cb = (unsigned)(((a_t >> 1) << 3) * 2);
    int quad = lane >> 3;                 // 0..3 (x4 B-fragment geometry)
    int qlo_ = quad & 1, qhi_ = quad >> 1;
    int b_r = lane & 7;
    unsigned bx = (unsigned)(b_r << 4);
    int rA = lane >> 2;
    int igA = i0 + w * 16 + rA, igB = igA + 8;
    int cA = (lane & 3) << 1;

    float oc[8][4];
    #pragma unroll
    for (int t = 0; t < 8; ++t)
        #pragma unroll
        for (int c = 0; c < 4; ++c) oc[t][c] = 0.f;
    float mA = -INFINITY, mB = -INFINITY, lA = 0.f, lB = 0.f;

    for (int jt = 0; jt <= it; ++jt) {
        int j0 = jt * BN;
        int buf = jt & 1;
        __syncthreads();   // all warps done reading buffer buf^1 (tile jt-1)

        // ---- prefetch K,V,kn of tile jt+1 into the other buffer ----
        int kIss = 0;
        if (jt < it) {
            unsigned kb = SKV + (unsigned)(buf ^ 1) * 24576;
            const size_t tg = bhoff + (size_t)(j0 + BN) * 128;
            #pragma unroll
            for (int c = 0; c < 4; ++c) {
                unsigned off = (unsigned)((c * 128 + tid) * 16);
                cpa16(sbase + kb + off,         g_khi + tg + off);
                cpa16(sbase + kb + 8192 + off,  g_klo + tg + off);
                cpa16(sbase + kb + 16384 + off, g_vhi + tg + off);
            }
            if (tid < BN)
                *(float*)(smem + SKNN + (buf ^ 1) * 256 + tid * 4) =
                    g_kkn[bh * Lc + j0 + BN + tid];
            asm volatile("cp.async.commit_group;");
            kIss = 1;
        }
        if (kIss) asm volatile("cp.async.wait_group 1;");
        else      asm volatile("cp.async.wait_group 0;");
        __syncthreads();   // tile jt fully resident

        const char* knp = smem + SKNN + buf * 256;
        unsigned kvb = SKV + (unsigned)buf * 24576;
        unsigned KHI = kvb, KLO = kvb + 8192, SV = kvb + 16384;

        // ---- S = Qhat . K^T  (3-split bf16, x4 B-fragments) ----
        float sc_[8][4];
        #pragma unroll
        for (int t = 0; t < 8; ++t)
            #pragma unroll
            for (int c = 0; c < 4; ++c) sc_[t][c] = 0.f;

        #pragma unroll
        for (int ks = 0; ks < 4; ++ks) {
            unsigned ah[4], al[4];
            unsigned aoff = a_rowoff + (((unsigned)(ks * 32) + a_cb) ^ a_x);
            ldsm4(ah, sbase + SQHI + aoff);
            ldsm4(al, sbase + SQLO + aoff);
            #pragma unroll
            for (int u = 0; u < 4; ++u) {
                unsigned jroff = (unsigned)((u * 16 + qhi_ * 8 + b_r) * 128);
                unsigned boff = jroff + (((unsigned)(ks * 32 + qlo_ * 16)) ^ bx);
                unsigned kh4[4], kl4[4];
                ldsm4(kh4, sbase + KHI + boff);
                ldsm4(kl4, sbase + KLO + boff);
                mma_bf16(sc_[2 * u],     ah, kh4);
                mma_bf16(sc_[2 * u],     ah, kl4);
                mma_bf16(sc_[2 * u],     al, kh4);
                mma_bf16(sc_[2 * u + 1], ah, kh4 + 2);
                mma_bf16(sc_[2 * u + 1], ah, kl4 + 2);
                mma_bf16(sc_[2 * u + 1], al, kh4 + 2);
            }
        }

        // ---- scores (log2 domain) + online softmax (quad lanes share row) ----
        float mxA = -INFINITY, mxB = -INFINITY;
        #pragma unroll
        for (int t = 0; t < 8; ++t) {
            int jb = j0 + t * 8 + cA;
            float k0 = *(const float*)(knp + (t * 8 + cA) * 4);
            float k1 = *(const float*)(knp + (t * 8 + cA + 1) * 4);
            float s0 = fmaf(twokm, sc_[t][0], k0); if (jb     > igA) s0 = -INFINITY;
            float s1 = fmaf(twokm, sc_[t][1], k1); if (jb + 1 > igA) s1 = -INFINITY;
            float s2 = fmaf(twokm, sc_[t][2], k0); if (jb     > igB) s2 = -INFINITY;
            float s3 = fmaf(twokm, sc_[t][3], k1); if (jb + 1 > igB) s3 = -INFINITY;
            sc_[t][0] = s0; sc_[t][1] = s1; sc_[t][2] = s2; sc_[t][3] = s3;
            mxA = fmaxf(mxA, fmaxf(s0, s1));
            mxB = fmaxf(mxB, fmaxf(s2, s3));
        }
        mxA = fmaxf(mxA, __shfl_xor_sync(0xffffffffu, mxA, 1));
        mxA = fmaxf(mxA, __shfl_xor_sync(0xffffffffu, mxA, 2));
        mxB = fmaxf(mxB, __shfl_xor_sync(0xffffffffu, mxB, 1));
        mxB = fmaxf(mxB, __shfl_xor_sync(0xffffffffu, mxB, 2));

        float mnA = fmaxf(mA, mxA), mnB = fmaxf(mB, mxB);
        float scA = ex2f(mA - mnA), scB = ex2f(mB - mnB);
        mA = mnA; mB = mnB;

        // packed fp16 exp: p = 2^(s - mn). Outputs ARE the PV A-fragments.
        unsigned pA[8], pB[8];
        float rsA = 0.f, rsB = 0.f;
        #pragma unroll
        for (int t = 0; t < 8; ++t) {
            __half2 hA = __floats2half2_rn(sc_[t][0] - mnA, sc_[t][1] - mnA);
            __half2 hB = __floats2half2_rn(sc_[t][2] - mnB, sc_[t][3] - mnB);
            pA[t] = h2exp2(*(unsigned*)&hA);
            pB[t] = h2exp2(*(unsigned*)&hB);
            float2 fa = __half22float2(*(__half2*)&pA[t]);
            float2 fb = __half22float2(*(__half2*)&pB[t]);
            rsA += fa.x + fa.y;
            rsB += fb.x + fb.y;
        }
        rsA += __shfl_xor_sync(0xffffffffu, rsA, 1);
        rsA += __shfl_xor_sync(0xffffffffu, rsA, 2);
        rsB += __shfl_xor_sync(0xffffffffu, rsB, 1);
        rsB += __shfl_xor_sync(0xffffffffu, rsB, 2);
        lA = lA * scA + rsA;
        lB = lB * scB + rsB;
        // skip the O-rescale when no row's max moved (warp-convergent test)
        if (!__all_sync(0xffffffffu, (scA == 1.f) & (scB == 1.f))) {
            #pragma unroll
            for (int t = 0; t < 8; ++t) {
                oc[t][0] *= scA; oc[t][1] *= scA;
                oc[t][2] *= scB; oc[t][3] *= scB;
            }
        }

        // ---- O += P . V  (plain fp16 V, x4t fragments) ----
        #pragma unroll
        for (int ks = 0; ks < 4; ++ks) {
            unsigned pah[4];
            pah[0] = pA[2 * ks];     pah[1] = pB[2 * ks];
            pah[2] = pA[2 * ks + 1]; pah[3] = pB[2 * ks + 1];
            unsigned vroff = (unsigned)((ks * 16 + qlo_ * 8 + b_r) * 128);
            #pragma unroll
            for (int u = 0; u < 4; ++u) {
                unsigned voff = vroff + (((unsigned)((2 * u + qhi_) * 16)) ^ bx);
                unsigned vh4[4];
                ldsm4t(vh4, sbase + SV + voff);
                mma_f16(oc[2 * u],     pah, vh4);
                mma_f16(oc[2 * u + 1], pah, vh4 + 2);
            }
        }
    }

    // ---- epilogue: out = queries + O / l ----
    float liA = 1.f / lA, liB = 1.f / lB;
    #pragma unroll
    for (int t = 0; t < 8; ++t) {
        int e = t * 8 + cA;
        size_t offA = ((size_t)((b * Lc + igA) * Hc + h)) * Ec + e;
        size_t offB = ((size_t)((b * Lc + igB) * Hc + h)) * Ec + e;
        float2 qa = *(const float2*)(q + offA);
        float2 qb = *(const float2*)(q + offB);
        *(float2*)(out + offA) = make_float2(qa.x + oc[t][0] * liA,
                                             qa.y + oc[t][1] * liA);
        *(float2*)(out + offB) = make_float2(qb.x + oc[t][2] * liB,
                                             qb.y + oc[t][3] * liB);
    }
}

// ---------------------------------------------------------------------------

extern "C" void kernel_launch(void* const* d_in, const int* in_sizes, int n_in,
                              void* d_out, int out_size)
{
    const float* q  = (const float*)d_in[0];
    const float* k  = (const float*)d_in[1];
    const float* v  = (const float*)d_in[2];
    const float* qm = (const float*)d_in[3];
    const float* kmsk = (const float*)d_in[4];
    const float* w  = (const float*)d_in[5];
    float* out = (float*)d_out;

    cudaFuncSetAttribute(stage2_kernel,
                         cudaFuncAttributeMaxDynamicSharedMemorySize, STOT);

    prep_kernel<<<NBH + NBH * 4, 1024>>>(q, w, qm, k, v, kmsk);

    dim3 grid(NBH, NIT);   // y slow => heavy tiles (it = NIT-1-y) first
    stage2_kernel<<<grid, 128, STOT>>>(q, kmsk, out);
}

// round 15
// speedup vs baseline: 1.4688x; 1.0054x over previous
#include <cuda_runtime.h>
#include <cuda_bf16.h>
#include <cuda_fp16.h>
#include <math.h>
#include <float.h>

#define Bc 4
#define Lc 1024
#define Hc 12
#define Ec 64
#define BM 64
#define BN 64
#define NIT (Lc / BM)    // 16 i-tiles
#define NBH (Bc * Hc)    // 48
#define PBH (Lc * 128)   // 131072 bytes per (b,h) per 16-bit array
#define L2E 1.4426950408889634f

// ---------------------------------------------------------------------------
// global scratch (allocation-free rule: __device__ globals)
// K: bf16 hi/lo; V: plain fp16. PRE-SWIZZLED like the stage2 smem tiles.
// Q-hat is computed inside stage2 (fused scan) — no global image needed.
// ---------------------------------------------------------------------------
__device__ __align__(16) unsigned char g_khi[NBH * PBH];
__device__ __align__(16) unsigned char g_klo[NBH * PBH];
__device__ __align__(16) unsigned char g_vhi[NBH * PBH];
__device__ float g_wexp[NBH * Lc];
__device__ float g_invz[NBH * Lc];
__device__ float g_kkn[NBH * Lc];          // -km * |k|^2 * log2(e)
__device__ float g_gqp[NBH * 64 * Ec];     // EXCLUSIVE prefix of 16-row sums

// ---------------------------------------------------------------------------
// helpers
// ---------------------------------------------------------------------------
__device__ __forceinline__ unsigned smem_u32(const void* p) {
    unsigned a;
    asm("{ .reg .u64 t; cvta.to.shared.u64 t, %1; cvt.u32.u64 %0, t; }"
        : "=r"(a) : "l"(p));
    return a;
}
__device__ __forceinline__ void cpa16(unsigned dst, const void* src) {
    asm volatile("cp.async.cg.shared.global [%0], [%1], 16;" :: "r"(dst), "l"(src));
}
__device__ __forceinline__ void ldsm4(unsigned* r, unsigned addr) {
    asm volatile("ldmatrix.sync.aligned.m8n8.x4.shared.b16 {%0,%1,%2,%3}, [%4];"
        : "=r"(r[0]), "=r"(r[1]), "=r"(r[2]), "=r"(r[3]) : "r"(addr));
}
__device__ __forceinline__ void ldsm4t(unsigned* r, unsigned addr) {
    asm volatile("ldmatrix.sync.aligned.m8n8.x4.trans.shared.b16 {%0,%1,%2,%3}, [%4];"
        : "=r"(r[0]), "=r"(r[1]), "=r"(r[2]), "=r"(r[3]) : "r"(addr));
}
__device__ __forceinline__ void mma_bf16(float* c, const unsigned* a, const unsigned* b) {
    asm volatile(
        "mma.sync.aligned.m16n8k16.row.col.f32.bf16.bf16.f32 "
        "{%0,%1,%2,%3}, {%4,%5,%6,%7}, {%8,%9}, {%0,%1,%2,%3};"
        : "+f"(c[0]), "+f"(c[1]), "+f"(c[2]), "+f"(c[3])
        : "r"(a[0]), "r"(a[1]), "r"(a[2]), "r"(a[3]), "r"(b[0]), "r"(b[1]));
}
__device__ __forceinline__ void mma_f16(float* c, const unsigned* a, const unsigned* b) {
    asm volatile(
        "mma.sync.aligned.m16n8k16.row.col.f32.f16.f16.f32 "
        "{%0,%1,%2,%3}, {%4,%5,%6,%7}, {%8,%9}, {%0,%1,%2,%3};"
        : "+f"(c[0]), "+f"(c[1]), "+f"(c[2]), "+f"(c[3])
        : "r"(a[0]), "r"(a[1]), "r"(a[2]), "r"(a[3]), "r"(b[0]), "r"(b[1]));
}
__device__ __forceinline__ unsigned h2exp2(unsigned x) {
    unsigned d;
    asm("ex2.approx.f16x2 %0, %1;" : "=r"(d) : "r"(x));
    return d;
}
__device__ __forceinline__ float ex2f(float x) {
    float d;
    asm("ex2.approx.f32 %0, %1;" : "=f"(d) : "f"(x));
    return d;
}
__device__ __forceinline__ void splitpack(float p0, float p1, unsigned& hi, unsigned& lo) {
    __nv_bfloat162 h2 = __floats2bfloat162_rn(p0, p1);
    float r0 = p0 - __low2float(h2);
    float r1 = p1 - __high2float(h2);
    __nv_bfloat162 l2 = __floats2bfloat162_rn(r0, r1);
    hi = *(unsigned*)&h2;
    lo = *(unsigned*)&l2;
}
// swizzled byte offset within a (row, c4) cell; c4 = group of 4 elements
__device__ __forceinline__ unsigned swoff(int row, int c4) {
    return (unsigned)(row * 128 + ((c4 * 8) ^ ((row & 7) << 4)));
}

// stage2 smem: Q hi/lo 2x8K; double-buffered {Khi 8K, Klo 8K, V 8K} x2; kn x2
#define SQHI 0
#define SQLO 8192
#define SKV  16384            // + buf*24576 ; Khi +0, Klo +8192, V +16384
#define SKNN 65536
#define STOT (65536 + 512)

// ---------------------------------------------------------------------------
// 1) merged: blocks [0,NBH) = score+scan+group-sums+prefix;
//            blocks [NBH, NBH+4*NBH) = prep_kv
// ---------------------------------------------------------------------------
__global__ void __launch_bounds__(1024) prep_kernel(
    const float* __restrict__ q, const float* __restrict__ wv,
    const float* __restrict__ q_mask,
    const float* __restrict__ k, const float* __restrict__ v,
    const float* __restrict__ k_mask)
{
    int tid = threadIdx.x;
    if (blockIdx.x >= NBH) {
        // ---------------- prep_kv part: 256 rows per block ----------------
        int pb = blockIdx.x - NBH;
        int bh = pb >> 2, qtr = pb & 3;
        int b = bh / Hc, h = bh % Hc;
        float km = k_mask[b * Lc];
        unsigned char* khi = g_khi + (size_t)bh * PBH;
        unsigned char* klo = g_klo + (size_t)bh * PBH;
        unsigned char* vhi = g_vhi + (size_t)bh * PBH;
        #pragma unroll
        for (int itr = 0; itr < 4; ++itr) {
            int idx = itr * 1024 + tid;
            int row = qtr * 256 + (idx >> 4), c4 = idx & 15;
            size_t goff = ((size_t)((b * Lc + row) * Hc + h)) * Ec + c4 * 4;
            unsigned off = swoff(row, c4);
            float4 kx = *(const float4*)(k + goff);
            {
                unsigned h0, l0_, h1, l1;
                splitpack(kx.x, kx.y, h0, l0_);
                splitpack(kx.z, kx.w, h1, l1);
                *(uint2*)(khi + off) = make_uint2(h0, h1);
                *(uint2*)(klo + off) = make_uint2(l0_, l1);
            }
            {
                float4 x = *(const float4*)(v + goff);
                __half2 a2 = __floats2half2_rn(x.x, x.y);
                __half2 b2 = __floats2half2_rn(x.z, x.w);
                *(uint2*)(vhi + off) = make_uint2(*(unsigned*)&a2, *(unsigned*)&b2);
            }
            float ps = kx.x * kx.x + kx.y * kx.y + kx.z * kx.z + kx.w * kx.w;
            #pragma unroll
            for (int o = 1; o < 16; o <<= 1) ps += __shfl_xor_sync(0xffffffffu, ps, o);
            if ((tid & 15) == 0) g_kkn[bh * Lc + row] = -km * ps * L2E;
        }
        return;
    }

    // ---------------- score + softmax-scan + group sums ----------------
    int bh = blockIdx.x;
    int b = bh / Hc, h = bh % Hc;

    __shared__ float s_sh[Lc];          // scores, then wexp
    __shared__ float gq_sh[64][Ec];     // 16-row sums, then exclusive prefix
    __shared__ float w_sh[Ec];
    __shared__ float red[32];
    __shared__ float Msh;

    int lane = tid & 31, warp = tid >> 5;

    if (tid < Ec) w_sh[tid] = wv[h * Ec + tid];
    __syncthreads();
    float qm = q_mask[b * Lc];

    for (int j = warp; j < Lc; j += 32) {
        const float* qrow = q + ((size_t)((b * Lc + j) * Hc + h)) * Ec;
        float p = qrow[lane] * w_sh[lane] + qrow[lane + 32] * w_sh[lane + 32];
        #pragma unroll
        for (int o = 16; o; o >>= 1) p += __shfl_xor_sync(0xffffffffu, p, o);
        if (lane == 0) s_sh[j] = p * qm;
    }
    __syncthreads();

    float m = s_sh[tid];
    #pragma unroll
    for (int o = 16; o; o >>= 1) m = fmaxf(m, __shfl_xor_sync(0xffffffffu, m, o));
    if (lane == 0) red[warp] = m;
    __syncthreads();
    if (warp == 0) {
        float t = red[lane];
        #pragma unroll
        for (int o = 16; o; o >>= 1) t = fmaxf(t, __shfl_xor_sync(0xffffffffu, t, o));
        if (lane == 0) Msh = t;
    }
    __syncthreads();
    float M = Msh;

    float wexp = __expf(s_sh[tid] - M);
    float sc = wexp;
    #pragma unroll
    for (int o = 1; o < 32; o <<= 1) {
        float t = __shfl_up_sync(0xffffffffu, sc, o);
        if (lane >= o) sc += t;
    }
    if (lane == 31) red[warp] = sc;
    __syncthreads();
    if (warp == 0) {
        float v0 = red[lane];
        float scn = v0;
        #pragma unroll
        for (int o = 1; o < 32; o <<= 1) {
            float t = __shfl_up_sync(0xffffffffu, scn, o);
            if (lane >= o) scn += t;
        }
        red[lane] = scn - v0;
    }
    __syncthreads();
    float Z = sc + red[warp];
    g_wexp[bh * Lc + tid] = wexp;
    g_invz[bh * Lc + tid] = 1.0f / Z;
    s_sh[tid] = wexp;      // each thread overwrites its own element
    __syncthreads();

    // ---- 16-row group sums: gq_sh[gr][e] = sum_{jj<16} wexp * q ----
    {
        int e = tid & 63, rb = tid >> 6;      // rb: 0..15
        const float* qcol = q + (((size_t)(b * Lc)) * Hc + h) * Ec + e;
        #pragma unroll
        for (int p = 0; p < 4; ++p) {
            int gr = p * 16 + rb;
            int j0 = gr * 16;
            float acc = 0.f;
            #pragma unroll
            for (int jj = 0; jj < 16; ++jj)
                acc += s_sh[j0 + jj] * qcol[(size_t)(j0 + jj) * (Hc * Ec)];
            gq_sh[gr][e] = acc;
        }
    }
    __syncthreads();

    // ---- exclusive prefix over the 64 groups (per e-lane) ----
    if (tid < Ec) {
        float run = 0.f;
        #pragma unroll
        for (int gr = 0; gr < 64; ++gr) {
            float t = gq_sh[gr][tid];
            gq_sh[gr][tid] = run;
            run += t;
        }
    }
    __syncthreads();

    // ---- write prefix to global ----
    {
        int e = tid & 63, rb = tid >> 6;
        #pragma unroll
        for (int p = 0; p < 4; ++p) {
            int gr = p * 16 + rb;
            g_gqp[(bh * 64 + gr) * Ec + e] = gq_sh[gr][e];
        }
    }
}

// ---------------------------------------------------------------------------
// 2) Stage 2: flash attention with FUSED qhat scan + register-resident Q.
//    S: 3-term split-bf16 MMA, log2-domain scores; exp via ex2.approx.f16x2;
//    PV: plain fp16 V. K+V double-buffered. Masking only on diagonal tiles.
//    grid (NBH, NIT) heavy-first, 128 threads (4 warps x 16 rows), 3 CTAs/SM
// ---------------------------------------------------------------------------
__global__ void __launch_bounds__(128, 3) stage2_kernel(
    const float* __restrict__ q, const float* __restrict__ k_mask,
    float* __restrict__ out)
{
    extern __shared__ char smem[];
    const unsigned sbase = smem_u32(smem);
    int tid = threadIdx.x, lane = tid & 31, w = tid >> 5;
    int bh = blockIdx.x, b = bh / Hc, h = bh % Hc;
    int it = NIT - 1 - (int)blockIdx.y;   // heavy tiles first
    int i0 = it * BM;
    float twokm = 2.f * k_mask[b * Lc] * L2E;   // log2-domain scale
    const size_t bhoff = (size_t)bh * PBH;

    // ---- prologue A: issue K0 + V0 + kn0 prefetch ----
    {
        #pragma unroll
        for (int c = 0; c < 4; ++c) {
            unsigned off = (unsigned)((c * 128 + tid) * 16);
            cpa16(sbase + SKV + off,         g_khi + bhoff + off);
            cpa16(sbase + SKV + 8192 + off,  g_klo + bhoff + off);
            cpa16(sbase + SKV + 16384 + off, g_vhi + bhoff + off);
        }
        if (tid < BN)
            *(float*)(smem + SKNN + tid * 4) = g_kkn[bh * Lc + tid];
        asm volatile("cp.async.commit_group;");
    }

    // ---- prologue B: fused qhat scan -> split-bf16 Q tile in smem ----
    {
        int e = tid & 63, gp = tid >> 6;                 // gp: 0..1
        unsigned ebase = (unsigned)((e >> 2) * 8);
        unsigned elow = (unsigned)((e & 3) * 2);
        #pragma unroll
        for (int gg = 0; gg < 2; ++gg) {
            int g = gp * 2 + gg;                          // 0..3
            int gr = (i0 >> 4) + g;
            float acc = g_gqp[(bh * 64 + gr) * Ec + e];
            int jbase = i0 + g * 16;
            #pragma unroll
            for (int jj = 0; jj < 16; ++jj) {
                int j = jbase + jj;
                acc += g_wexp[bh * Lc + j] *
                       q[((size_t)((b * Lc + j) * Hc + h)) * Ec + e];
                float val = acc * g_invz[bh * Lc + j];
                int row = g * 16 + jj;
                __nv_bfloat16 hb = __float2bfloat16_rn(val);
                __nv_bfloat16 lb = __float2bfloat16_rn(val - __bfloat162float(hb));
                unsigned off = (unsigned)(row * 128) + (ebase ^ ((row & 7) << 4)) + elow;
                *(__nv_bfloat16*)(smem + SQHI + off) = hb;
                *(__nv_bfloat16*)(smem + SQLO + off) = lb;
            }
        }
    }
    __syncthreads();   // Q tile visible to all warps

    // ---- per-lane fragment geometry ----
    int a_t = lane >> 3, a_r = lane & 7;
    int a_row = w * 16 + ((a_t & 1) << 3) + a_r;
    unsigned a_rowoff = (unsigned)(a_row * 128);
    unsigned a_x = (unsigned)((a_row & 7) << 4);
    unsigned a_cb = (unsigned)(((a_t >> 1) << 3) * 2);
    int quad = lane >> 3;                 // 0..3 (x4 B-fragment geometry)
    int qlo_ = quad & 1, qhi_ = quad >> 1;
    int b_r = lane & 7;
    unsigned bx = (unsigned)(b_r << 4);
    int rA = lane >> 2;
    int igA = i0 + w * 16 + rA, igB = igA + 8;
    int cA = (lane & 3) << 1;

    // ---- Q fragments: load ONCE into registers (invariant over j-loop) ----
    unsigned qah[4][4], qal[4][4];
    #pragma unroll
    for (int ks = 0; ks < 4; ++ks) {
        unsigned aoff = a_rowoff + (((unsigned)(ks * 32) + a_cb) ^ a_x);
        ldsm4(qah[ks], sbase + SQHI + aoff);
        ldsm4(qal[ks], sbase + SQLO + aoff);
    }

    float oc[8][4];
    #pragma unroll
    for (int t = 0; t < 8; ++t)
        #pragma unroll
        for (int c = 0; c < 4; ++c) oc[t][c] = 0.f;
    float mA = -INFINITY, mB = -INFINITY, lA = 0.f, lB = 0.f;

    for (int jt = 0; jt <= it; ++jt) {
        int j0 = jt * BN;
        int buf = jt & 1;
        __syncthreads();   // all warps done reading buffer buf^1 (tile jt-1)

        // ---- prefetch K,V,kn of tile jt+1 into the other buffer ----
        int kIss = 0;
        if (jt < it) {
            unsigned kb = SKV + (unsigned)(buf ^ 1) * 24576;
            const size_t tg = bhoff + (size_t)(j0 + BN) * 128;
            #pragma unroll
            for (int c = 0; c < 4; ++c) {
                unsigned off = (unsigned)((c * 128 + tid) * 16);
                cpa16(sbase + kb + off,         g_khi + tg + off);
                cpa16(sbase + kb + 8192 + off,  g_klo + tg + off);
                cpa16(sbase + kb + 16384 + off, g_vhi + tg + off);
            }
            if (tid < BN)
                *(float*)(smem + SKNN + (buf ^ 1) * 256 + tid * 4) =
                    g_kkn[bh * Lc + j0 + BN + tid];
            asm volatile("cp.async.commit_group;");
            kIss = 1;
        }
        if (kIss) asm volatile("cp.async.wait_group 1;");
        else      asm volatile("cp.async.wait_group 0;");
        __syncthreads();   // tile jt fully resident

        const float2* kn2 = (const float2*)(smem + SKNN + buf * 256);
        unsigned kvb = SKV + (unsigned)buf * 24576;
        unsigned KHI = kvb, KLO = kvb + 8192, SV = kvb + 16384;

        // ---- S = Qhat . K^T  (3-split bf16, x4 B-fragments, Q in regs) ----
        float sc_[8][4];
        #pragma unroll
        for (int t = 0; t < 8; ++t)
            #pragma unroll
            for (int c = 0; c < 4; ++c) sc_[t][c] = 0.f;

        #pragma unroll
        for (int ks = 0; ks < 4; ++ks) {
            #pragma unroll
            for (int u = 0; u < 4; ++u) {
                unsigned jroff = (unsigned)((u * 16 + qhi_ * 8 + b_r) * 128);
                unsigned boff = jroff + (((unsigned)(ks * 32 + qlo_ * 16)) ^ bx);
                unsigned kh4[4], kl4[4];
                ldsm4(kh4, sbase + KHI + boff);
                ldsm4(kl4, sbase + KLO + boff);
                mma_bf16(sc_[2 * u],     qah[ks], kh4);
                mma_bf16(sc_[2 * u],     qah[ks], kl4);
                mma_bf16(sc_[2 * u],     qal[ks], kh4);
                mma_bf16(sc_[2 * u + 1], qah[ks], kh4 + 2);
                mma_bf16(sc_[2 * u + 1], qah[ks], kl4 + 2);
                mma_bf16(sc_[2 * u + 1], qal[ks], kh4 + 2);
            }
        }

        // ---- scores (log2 domain); masks only on the diagonal tile ----
        float mxA = -INFINITY, mxB = -INFINITY;
        if (jt == it) {
            #pragma unroll
            for (int t = 0; t < 8; ++t) {
                int jb = j0 + t * 8 + cA;
                float2 kk = kn2[t * 4 + (cA >> 1)];
                float s0 = fmaf(twokm, sc_[t][0], kk.x); if (jb     > igA) s0 = -INFINITY;
                float s1 = fmaf(twokm, sc_[t][1], kk.y); if (jb + 1 > igA) s1 = -INFINITY;
                float s2 = fmaf(twokm, sc_[t][2], kk.x); if (jb     > igB) s2 = -INFINITY;
                float s3 = fmaf(twokm, sc_[t][3], kk.y); if (jb + 1 > igB) s3 = -INFINITY;
                sc_[t][0] = s0; sc_[t][1] = s1; sc_[t][2] = s2; sc_[t][3] = s3;
                mxA = fmaxf(mxA, fmaxf(s0, s1));
                mxB = fmaxf(mxB, fmaxf(s2, s3));
            }
        } else {
            #pragma unroll
            for (int t = 0; t < 8; ++t) {
                float2 kk = kn2[t * 4 + (cA >> 1)];
                float s0 = fmaf(twokm, sc_[t][0], kk.x);
                float s1 = fmaf(twokm, sc_[t][1], kk.y);
                float s2 = fmaf(twokm, sc_[t][2], kk.x);
                float s3 = fmaf(twokm, sc_[t][3], kk.y);
                sc_[t][0] = s0; sc_[t][1] = s1; sc_[t][2] = s2; sc_[t][3] = s3;
                mxA = fmaxf(mxA, fmaxf(s0, s1));
                mxB = fmaxf(mxB, fmaxf(s2, s3));
            }
        }
        mxA = fmaxf(mxA, __shfl_xor_sync(0xffffffffu, mxA, 1));
        mxA = fmaxf(mxA, __shfl_xor_sync(0xffffffffu, mxA, 2));
        mxB = fmaxf(mxB, __shfl_xor_sync(0xffffffffu, mxB, 1));
        mxB = fmaxf(mxB, __shfl_xor_sync(0xffffffffu, mxB, 2));

        float mnA = fmaxf(mA, mxA), mnB = fmaxf(mB, mxB);
        float scA = ex2f(mA - mnA), scB = ex2f(mB - mnB);
        mA = mnA; mB = mnB;

        // packed fp16 exp: p = 2^(s - mn). Outputs ARE the PV A-fragments.
        unsigned pA[8], pB[8];
        float rsA = 0.f, rsB = 0.f;
        #pragma unroll
        for (int t = 0; t < 8; ++t) {
            __half2 hA = __floats2half2_rn(sc_[t][0] - mnA, sc_[t][1] - mnA);
            __half2 hB = __floats2half2_rn(sc_[t][2] - mnB, sc_[t][3] - mnB);
            pA[t] = h2exp2(*(unsigned*)&hA);
            pB[t] = h2exp2(*(unsigned*)&hB);
            float2 fa = __half22float2(*(__half2*)&pA[t]);
            float2 fb = __half22float2(*(__half2*)&pB[t]);
            rsA += fa.x + fa.y;
            rsB += fb.x + fb.y;
        }
        rsA += __shfl_xor_sync(0xffffffffu, rsA, 1);
        rsA += __shfl_xor_sync(0xffffffffu, rsA, 2);
        rsB += __shfl_xor_sync(0xffffffffu, rsB, 1);
        rsB += __shfl_xor_sync(0xffffffffu, rsB, 2);
        lA = lA * scA + rsA;
        lB = lB * scB + rsB;
        // skip the O-rescale when no row's max moved (warp-convergent test)
        if (!__all_sync(0xffffffffu, (scA == 1.f) & (scB == 1.f))) {
            #pragma unroll
            for (int t = 0; t < 8; ++t) {
                oc[t][0] *= scA; oc[t][1] *= scA;
                oc[t][2] *= scB; oc[t][3] *= scB;
            }
        }

        // ---- O += P . V  (plain fp16 V, x4t fragments) ----
        #pragma unroll
        for (int ks = 0; ks < 4; ++ks) {
            unsigned pah[4];
            pah[0] = pA[2 * ks];     pah[1] = pB[2 * ks];
            pah[2] = pA[2 * ks + 1]; pah[3] = pB[2 * ks + 1];
            unsigned vroff = (unsigned)((ks * 16 + qlo_ * 8 + b_r) * 128);
            #pragma unroll
            for (int u = 0; u < 4; ++u) {
                unsigned voff = vroff + (((unsigned)((2 * u + qhi_) * 16)) ^ bx);
                unsigned vh4[4];
                ldsm4t(vh4, sbase + SV + voff);
                mma_f16(oc[2 * u],     pah, vh4);
                mma_f16(oc[2 * u + 1], pah, vh4 + 2);
            }
        }
    }

    // ---- epilogue: out = queries + O / l ----
    float liA = 1.f / lA, liB = 1.f / lB;
    #pragma unroll
    for (int t = 0; t < 8; ++t) {
        int e = t * 8 + cA;
        size_t offA = ((size_t)((b * Lc + igA) * Hc + h)) * Ec + e;
        size_t offB = ((size_t)((b * Lc + igB) * Hc + h)) * Ec + e;
        float2 qa = *(const float2*)(q + offA);
        float2 qb = *(const float2*)(q + offB);
        *(float2*)(out + offA) = make_float2(qa.x + oc[t][0] * liA,
                                             qa.y + oc[t][1] * liA);
        *(float2*)(out + offB) = make_float2(qb.x + oc[t][2] * liB,
                                             qb.y + oc[t][3] * liB);
    }
}

// ---------------------------------------------------------------------------

extern "C" void kernel_launch(void* const* d_in, const int* in_sizes, int n_in,
                              void* d_out, int out_size)
{
    const float* q  = (const float*)d_in[0];
    const float* k  = (const float*)d_in[1];
    const float* v  = (const float*)d_in[2];
    const float* qm = (const float*)d_in[3];
    const float* kmsk = (const float*)d_in[4];
    const float* w  = (const float*)d_in[5];
    float* out = (float*)d_out;

    cudaFuncSetAttribute(stage2_kernel,
                         cudaFuncAttributeMaxDynamicSharedMemorySize, STOT);

    prep_kernel<<<NBH + NBH * 4, 1024>>>(q, w, qm, k, v, kmsk);

    dim3 grid(NBH, NIT);   // y slow => heavy tiles (it = NIT-1-y) first
    stage2_kernel<<<grid, 128, STOT>>>(q, kmsk, out);
}

// round 16
// speedup vs baseline: 1.4943x; 1.0174x over previous
#include <cuda_runtime.h>
#include <cuda_bf16.h>
#include <cuda_fp16.h>
#include <math.h>
#include <float.h>

#define Bc 4
#define Lc 1024
#define Hc 12
#define Ec 64
#define BM 64
#define BN 64
#define NIT (Lc / BM)    // 16 i-tiles
#define NBH (Bc * Hc)    // 48
#define PBH (Lc * 128)   // 131072 bytes per (b,h) per 16-bit array
#define L2E 1.4426950408889634f

// ---------------------------------------------------------------------------
// global scratch (allocation-free rule: __device__ globals)
// K: bf16 hi/lo; V: plain fp16. PRE-SWIZZLED like the stage2 smem tiles.
// Q-hat is computed inside stage2 (fused scan) — no global image needed.
// ---------------------------------------------------------------------------
__device__ __align__(16) unsigned char g_khi[NBH * PBH];
__device__ __align__(16) unsigned char g_klo[NBH * PBH];
__device__ __align__(16) unsigned char g_vhi[NBH * PBH];
__device__ float2 g_wiz[NBH * Lc];         // (wexp, invz) packed
__device__ float g_kkn[NBH * Lc];          // -km * |k|^2 * log2(e)
__device__ float g_gqp[NBH * 64 * Ec];     // EXCLUSIVE prefix of 16-row sums

// ---------------------------------------------------------------------------
// helpers
// ---------------------------------------------------------------------------
__device__ __forceinline__ unsigned smem_u32(const void* p) {
    unsigned a;
    asm("{ .reg .u64 t; cvta.to.shared.u64 t, %1; cvt.u32.u64 %0, t; }"
        : "=r"(a) : "l"(p));
    return a;
}
__device__ __forceinline__ void cpa16(unsigned dst, const void* src) {
    asm volatile("cp.async.cg.shared.global [%0], [%1], 16;" :: "r"(dst), "l"(src));
}
__device__ __forceinline__ void ldsm4(unsigned* r, unsigned addr) {
    asm volatile("ldmatrix.sync.aligned.m8n8.x4.shared.b16 {%0,%1,%2,%3}, [%4];"
        : "=r"(r[0]), "=r"(r[1]), "=r"(r[2]), "=r"(r[3]) : "r"(addr));
}
__device__ __forceinline__ void ldsm4t(unsigned* r, unsigned addr) {
    asm volatile("ldmatrix.sync.aligned.m8n8.x4.trans.shared.b16 {%0,%1,%2,%3}, [%4];"
        : "=r"(r[0]), "=r"(r[1]), "=r"(r[2]), "=r"(r[3]) : "r"(addr));
}
__device__ __forceinline__ void mma_bf16(float* c, const unsigned* a, const unsigned* b) {
    asm volatile(
        "mma.sync.aligned.m16n8k16.row.col.f32.bf16.bf16.f32 "
        "{%0,%1,%2,%3}, {%4,%5,%6,%7}, {%8,%9}, {%0,%1,%2,%3};"
        : "+f"(c[0]), "+f"(c[1]), "+f"(c[2]), "+f"(c[3])
        : "r"(a[0]), "r"(a[1]), "r"(a[2]), "r"(a[3]), "r"(b[0]), "r"(b[1]));
}
__device__ __forceinline__ void mma_f16(float* c, const unsigned* a, const unsigned* b) {
    asm volatile(
        "mma.sync.aligned.m16n8k16.row.col.f32.f16.f16.f32 "
        "{%0,%1,%2,%3}, {%4,%5,%6,%7}, {%8,%9}, {%0,%1,%2,%3};"
        : "+f"(c[0]), "+f"(c[1]), "+f"(c[2]), "+f"(c[3])
        : "r"(a[0]), "r"(a[1]), "r"(a[2]), "r"(a[3]), "r"(b[0]), "r"(b[1]));
}
__device__ __forceinline__ unsigned h2exp2(unsigned x) {
    unsigned d;
    asm("ex2.approx.f16x2 %0, %1;" : "=r"(d) : "r"(x));
    return d;
}
__device__ __forceinline__ float ex2f(float x) {
    float d;
    asm("ex2.approx.f32 %0, %1;" : "=f"(d) : "f"(x));
    return d;
}
__device__ __forceinline__ void splitpack(float p0, float p1, unsigned& hi, unsigned& lo) {
    __nv_bfloat162 h2 = __floats2bfloat162_rn(p0, p1);
    float r0 = p0 - __low2float(h2);
    float r1 = p1 - __high2float(h2);
    __nv_bfloat162 l2 = __floats2bfloat162_rn(r0, r1);
    hi = *(unsigned*)&h2;
    lo = *(unsigned*)&l2;
}
// swizzled byte offset within a (row, c4) cell; c4 = group of 4 elements
__device__ __forceinline__ unsigned swoff(int row, int c4) {
    return (unsigned)(row * 128 + ((c4 * 8) ^ ((row & 7) << 4)));
}

// stage2 smem: Q hi/lo 2x8K; double-buffered {Khi 8K, Klo 8K, V 8K} x2; kn x2
#define SQHI 0
#define SQLO 8192
#define SKV  16384            // + buf*24576 ; Khi +0, Klo +8192, V +16384
#define SKNN 65536
#define STOT (65536 + 512)

// ---------------------------------------------------------------------------
// 1) merged: blocks [0,NBH) = score+scan+group-sums+prefix;
//            blocks [NBH, NBH+4*NBH) = prep_kv
// ---------------------------------------------------------------------------
__global__ void __launch_bounds__(1024) prep_kernel(
    const float* __restrict__ q, const float* __restrict__ wv,
    const float* __restrict__ q_mask,
    const float* __restrict__ k, const float* __restrict__ v,
    const float* __restrict__ k_mask)
{
    int tid = threadIdx.x;
    if (blockIdx.x >= NBH) {
        // ---------------- prep_kv part: 256 rows per block ----------------
        int pb = blockIdx.x - NBH;
        int bh = pb >> 2, qtr = pb & 3;
        int b = bh / Hc, h = bh % Hc;
        float km = k_mask[b * Lc];
        unsigned char* khi = g_khi + (size_t)bh * PBH;
        unsigned char* klo = g_klo + (size_t)bh * PBH;
        unsigned char* vhi = g_vhi + (size_t)bh * PBH;
        #pragma unroll
        for (int itr = 0; itr < 4; ++itr) {
            int idx = itr * 1024 + tid;
            int row = qtr * 256 + (idx >> 4), c4 = idx & 15;
            size_t goff = ((size_t)((b * Lc + row) * Hc + h)) * Ec + c4 * 4;
            unsigned off = swoff(row, c4);
            float4 kx = *(const float4*)(k + goff);
            {
                unsigned h0, l0_, h1, l1;
                splitpack(kx.x, kx.y, h0, l0_);
                splitpack(kx.z, kx.w, h1, l1);
                *(uint2*)(khi + off) = make_uint2(h0, h1);
                *(uint2*)(klo + off) = make_uint2(l0_, l1);
            }
            {
                float4 x = *(const float4*)(v + goff);
                __half2 a2 = __floats2half2_rn(x.x, x.y);
                __half2 b2 = __floats2half2_rn(x.z, x.w);
                *(uint2*)(vhi + off) = make_uint2(*(unsigned*)&a2, *(unsigned*)&b2);
            }
            float ps = kx.x * kx.x + kx.y * kx.y + kx.z * kx.z + kx.w * kx.w;
            #pragma unroll
            for (int o = 1; o < 16; o <<= 1) ps += __shfl_xor_sync(0xffffffffu, ps, o);
            if ((tid & 15) == 0) g_kkn[bh * Lc + row] = -km * ps * L2E;
        }
        return;
    }

    // ---------------- score + softmax-scan + group sums ----------------
    int bh = blockIdx.x;
    int b = bh / Hc, h = bh % Hc;

    __shared__ float s_sh[Lc];          // scores, then wexp
    __shared__ float gq_sh[64][Ec];     // 16-row sums, then exclusive prefix
    __shared__ float w_sh[Ec];
    __shared__ float red[32];
    __shared__ float Msh;

    int lane = tid & 31, warp = tid >> 5;

    if (tid < Ec) w_sh[tid] = wv[h * Ec + tid];
    __syncthreads();
    float qm = q_mask[b * Lc];

    for (int j = warp; j < Lc; j += 32) {
        const float* qrow = q + ((size_t)((b * Lc + j) * Hc + h)) * Ec;
        float p = qrow[lane] * w_sh[lane] + qrow[lane + 32] * w_sh[lane + 32];
        #pragma unroll
        for (int o = 16; o; o >>= 1) p += __shfl_xor_sync(0xffffffffu, p, o);
        if (lane == 0) s_sh[j] = p * qm;
    }
    __syncthreads();

    float m = s_sh[tid];
    #pragma unroll
    for (int o = 16; o; o >>= 1) m = fmaxf(m, __shfl_xor_sync(0xffffffffu, m, o));
    if (lane == 0) red[warp] = m;
    __syncthreads();
    if (warp == 0) {
        float t = red[lane];
        #pragma unroll
        for (int o = 16; o; o >>= 1) t = fmaxf(t, __shfl_xor_sync(0xffffffffu, t, o));
        if (lane == 0) Msh = t;
    }
    __syncthreads();
    float M = Msh;

    float wexp = __expf(s_sh[tid] - M);
    float sc = wexp;
    #pragma unroll
    for (int o = 1; o < 32; o <<= 1) {
        float t = __shfl_up_sync(0xffffffffu, sc, o);
        if (lane >= o) sc += t;
    }
    if (lane == 31) red[warp] = sc;
    __syncthreads();
    if (warp == 0) {
        float v0 = red[lane];
        float scn = v0;
        #pragma unroll
        for (int o = 1; o < 32; o <<= 1) {
            float t = __shfl_up_sync(0xffffffffu, scn, o);
            if (lane >= o) scn += t;
        }
        red[lane] = scn - v0;
    }
    __syncthreads();
    float Z = sc + red[warp];
    g_wiz[bh * Lc + tid] = make_float2(wexp, 1.0f / Z);
    s_sh[tid] = wexp;      // each thread overwrites its own element
    __syncthreads();

    // ---- 16-row group sums: gq_sh[gr][e] = sum_{jj<16} wexp * q ----
    {
        int e = tid & 63, rb = tid >> 6;      // rb: 0..15
        const float* qcol = q + (((size_t)(b * Lc)) * Hc + h) * Ec + e;
        #pragma unroll
        for (int p = 0; p < 4; ++p) {
            int gr = p * 16 + rb;
            int j0 = gr * 16;
            float acc = 0.f;
            #pragma unroll
            for (int jj = 0; jj < 16; ++jj)
                acc += s_sh[j0 + jj] * qcol[(size_t)(j0 + jj) * (Hc * Ec)];
            gq_sh[gr][e] = acc;
        }
    }
    __syncthreads();

    // ---- exclusive prefix over the 64 groups (per e-lane) ----
    if (tid < Ec) {
        float run = 0.f;
        #pragma unroll
        for (int gr = 0; gr < 64; ++gr) {
            float t = gq_sh[gr][tid];
            gq_sh[gr][tid] = run;
            run += t;
        }
    }
    __syncthreads();

    // ---- write prefix to global ----
    {
        int e = tid & 63, rb = tid >> 6;
        #pragma unroll
        for (int p = 0; p < 4; ++p) {
            int gr = p * 16 + rb;
            g_gqp[(bh * 64 + gr) * Ec + e] = gq_sh[gr][e];
        }
    }
}

// ---------------------------------------------------------------------------
// 2) Stage 2: flash attention with FUSED qhat scan + register-resident Q.
//    S: 3-term split-bf16 MMA, log2-domain scores; exp via ex2.approx.f16x2;
//    row-sums via ones-B MMA (no shuffles/cvts); PV: plain fp16 V.
//    K+V double-buffered. Masking only on diagonal tiles.
//    grid (NBH, NIT) heavy-first, 128 threads (4 warps x 16 rows), 3 CTAs/SM
// ---------------------------------------------------------------------------
__global__ void __launch_bounds__(128, 3) stage2_kernel(
    const float* __restrict__ q, const float* __restrict__ k_mask,
    float* __restrict__ out)
{
    extern __shared__ char smem[];
    const unsigned sbase = smem_u32(smem);
    int tid = threadIdx.x, lane = tid & 31, w = tid >> 5;
    int bh = blockIdx.x, b = bh / Hc, h = bh % Hc;
    int it = NIT - 1 - (int)blockIdx.y;   // heavy tiles first
    int i0 = it * BM;
    float twokm = 2.f * k_mask[b * Lc] * L2E;   // log2-domain scale
    const size_t bhoff = (size_t)bh * PBH;

    // ---- prologue A: issue K0 + V0 + kn0 prefetch ----
    {
        #pragma unroll
        for (int c = 0; c < 4; ++c) {
            unsigned off = (unsigned)((c * 128 + tid) * 16);
            cpa16(sbase + SKV + off,         g_khi + bhoff + off);
            cpa16(sbase + SKV + 8192 + off,  g_klo + bhoff + off);
            cpa16(sbase + SKV + 16384 + off, g_vhi + bhoff + off);
        }
        if (tid < BN)
            *(float*)(smem + SKNN + tid * 4) = g_kkn[bh * Lc + tid];
        asm volatile("cp.async.commit_group;");
    }

    // ---- prologue B: fused qhat scan -> split-bf16 Q tile in smem ----
    {
        int e = tid & 63, gp = tid >> 6;                 // gp: 0..1
        unsigned ebase = (unsigned)((e >> 2) * 8);
        unsigned elow = (unsigned)((e & 3) * 2);
        #pragma unroll
        for (int gg = 0; gg < 2; ++gg) {
            int g = gp * 2 + gg;                          // 0..3
            int gr = (i0 >> 4) + g;
            float acc = g_gqp[(bh * 64 + gr) * Ec + e];
            int jbase = i0 + g * 16;
            #pragma unroll
            for (int jj = 0; jj < 16; ++jj) {
                int j = jbase + jj;
                float2 wi = g_wiz[bh * Lc + j];
                acc += wi.x * q[((size_t)((b * Lc + j) * Hc + h)) * Ec + e];
                float val = acc * wi.y;
                int row = g * 16 + jj;
                __nv_bfloat16 hb = __float2bfloat16_rn(val);
                __nv_bfloat16 lb = __float2bfloat16_rn(val - __bfloat162float(hb));
                unsigned off = (unsigned)(row * 128) + (ebase ^ ((row & 7) << 4)) + elow;
                *(__nv_bfloat16*)(smem + SQHI + off) = hb;
                *(__nv_bfloat16*)(smem + SQLO + off) = lb;
            }
        }
    }
    __syncthreads();   // Q tile visible to all warps

    // ---- per-lane fragment geometry ----
    int a_t = lane >> 3, a_r = lane & 7;
    int a_row = w * 16 + ((a_t & 1) << 3) + a_r;
    unsigned a_rowoff = (unsigned)(a_row * 128);
    unsigned a_x = (unsigned)((a_row & 7) << 4);
    unsigned a_cb = (unsigned)(((a_t >> 1) << 3) * 2);
    int quad = lane >> 3;                 // 0..3 (x4 B-fragment geometry)
    int qlo_ = quad & 1, qhi_ = quad >> 1;
    int b_r = lane & 7;
    unsigned bx = (unsigned)(b_r << 4);
    int rA = lane >> 2;
    int igA = i0 + w * 16 + rA, igB = igA + 8;
    int cA = (lane & 3) << 1;

    // ---- Q fragments: load ONCE into registers (invariant over j-loop) ----
    unsigned qah[4][4], qal[4][4];
    #pragma unroll
    for (int ks = 0; ks < 4; ++ks) {
        unsigned aoff = a_rowoff + (((unsigned)(ks * 32) + a_cb) ^ a_x);
        ldsm4(qah[ks], sbase + SQHI + aoff);
        ldsm4(qal[ks], sbase + SQLO + aoff);
    }

    float oc[8][4];
    #pragma unroll
    for (int t = 0; t < 8; ++t)
        #pragma unroll
        for (int c = 0; c < 4; ++c) oc[t][c] = 0.f;
    float mA = -INFINITY, mB = -INFINITY, lA = 0.f, lB = 0.f;

    for (int jt = 0; jt <= it; ++jt) {
        int j0 = jt * BN;
        int buf = jt & 1;
        __syncthreads();   // all warps done reading buffer buf^1 (tile jt-1)

        // ---- prefetch K,V,kn of tile jt+1 into the other buffer ----
        int kIss = 0;
        if (jt < it) {
            unsigned kb = SKV + (unsigned)(buf ^ 1) * 24576;
            const size_t tg = bhoff + (size_t)(j0 + BN) * 128;
            #pragma unroll
            for (int c = 0; c < 4; ++c) {
                unsigned off = (unsigned)((c * 128 + tid) * 16);
                cpa16(sbase + kb + off,         g_khi + tg + off);
                cpa16(sbase + kb + 8192 + off,  g_klo + tg + off);
                cpa16(sbase + kb + 16384 + off, g_vhi + tg + off);
            }
            if (tid < BN)
                *(float*)(smem + SKNN + (buf ^ 1) * 256 + tid * 4) =
                    g_kkn[bh * Lc + j0 + BN + tid];
            asm volatile("cp.async.commit_group;");
            kIss = 1;
        }
        if (kIss) asm volatile("cp.async.wait_group 1;");
        else      asm volatile("cp.async.wait_group 0;");
        __syncthreads();   // tile jt fully resident

        const float2* kn2 = (const float2*)(smem + SKNN + buf * 256);
        unsigned kvb = SKV + (unsigned)buf * 24576;
        unsigned KHI = kvb, KLO = kvb + 8192, SV = kvb + 16384;

        // ---- S = Qhat . K^T  (3-split bf16, x4 B-fragments, Q in regs) ----
        float sc_[8][4];
        #pragma unroll
        for (int t = 0; t < 8; ++t)
            #pragma unroll
            for (int c = 0; c < 4; ++c) sc_[t][c] = 0.f;

        #pragma unroll
        for (int ks = 0; ks < 4; ++ks) {
            #pragma unroll
            for (int u = 0; u < 4; ++u) {
                unsigned jroff = (unsigned)((u * 16 + qhi_ * 8 + b_r) * 128);
                unsigned boff = jroff + (((unsigned)(ks * 32 + qlo_ * 16)) ^ bx);
                unsigned kh4[4], kl4[4];
                ldsm4(kh4, sbase + KHI + boff);
                ldsm4(kl4, sbase + KLO + boff);
                mma_bf16(sc_[2 * u],     qah[ks], kh4);
                mma_bf16(sc_[2 * u],     qah[ks], kl4);
                mma_bf16(sc_[2 * u],     qal[ks], kh4);
                mma_bf16(sc_[2 * u + 1], qah[ks], kh4 + 2);
                mma_bf16(sc_[2 * u + 1], qah[ks], kl4 + 2);
                mma_bf16(sc_[2 * u + 1], qal[ks], kh4 + 2);
            }
        }

        // ---- scores (log2 domain); masks only on the diagonal tile ----
        float mxA = -INFINITY, mxB = -INFINITY;
        if (jt == it) {
            #pragma unroll
            for (int t = 0; t < 8; ++t) {
                int jb = j0 + t * 8 + cA;
                float2 kk = kn2[t * 4 + (cA >> 1)];
                float s0 = fmaf(twokm, sc_[t][0], kk.x); if (jb     > igA) s0 = -INFINITY;
                float s1 = fmaf(twokm, sc_[t][1], kk.y); if (jb + 1 > igA) s1 = -INFINITY;
                float s2 = fmaf(twokm, sc_[t][2], kk.x); if (jb     > igB) s2 = -INFINITY;
                float s3 = fmaf(twokm, sc_[t][3], kk.y); if (jb + 1 > igB) s3 = -INFINITY;
                sc_[t][0] = s0; sc_[t][1] = s1; sc_[t][2] = s2; sc_[t][3] = s3;
                mxA = fmaxf(mxA, fmaxf(s0, s1));
                mxB = fmaxf(mxB, fmaxf(s2, s3));
            }
        } else {
            #pragma unroll
            for (int t = 0; t < 8; ++t) {
                float2 kk = kn2[t * 4 + (cA >> 1)];
                float s0 = fmaf(twokm, sc_[t][0], kk.x);
                float s1 = fmaf(twokm, sc_[t][1], kk.y);
                float s2 = fmaf(twokm, sc_[t][2], kk.x);
                float s3 = fmaf(twokm, sc_[t][3], kk.y);
                sc_[t][0] = s0; sc_[t][1] = s1; sc_[t][2] = s2; sc_[t][3] = s3;
                mxA = fmaxf(mxA, fmaxf(s0, s1));
                mxB = fmaxf(mxB, fmaxf(s2, s3));
            }
        }
        mxA = fmaxf(mxA, __shfl_xor_sync(0xffffffffu, mxA, 1));
        mxA = fmaxf(mxA, __shfl_xor_sync(0xffffffffu, mxA, 2));
        mxB = fmaxf(mxB, __shfl_xor_sync(0xffffffffu, mxB, 1));
        mxB = fmaxf(mxB, __shfl_xor_sync(0xffffffffu, mxB, 2));

        float mnA = fmaxf(mA, mxA), mnB = fmaxf(mB, mxB);
        float scA = ex2f(mA - mnA), scB = ex2f(mB - mnB);
        mA = mnA; mB = mnB;

        // packed fp16 exp: p = 2^(s - mn). Outputs ARE the PV A-fragments,
        // assembled directly in fragment order pfr[ks] = {A0,B0,A1,B1}.
        unsigned pfr[4][4];
        #pragma unroll
        for (int ks = 0; ks < 4; ++ks) {
            #pragma unroll
            for (int v2 = 0; v2 < 2; ++v2) {
                int t = 2 * ks + v2;
                __half2 hA = __floats2half2_rn(sc_[t][0] - mnA, sc_[t][1] - mnA);
                __half2 hB = __floats2half2_rn(sc_[t][2] - mnB, sc_[t][3] - mnB);
                pfr[ks][2 * v2]     = h2exp2(*(unsigned*)&hA);
                pfr[ks][2 * v2 + 1] = h2exp2(*(unsigned*)&hB);
            }
        }

        // ---- row sums via ones-B MMA (tensor pipe does the reduction) ----
        {
            unsigned ones2[2] = {0x3C003C00u, 0x3C003C00u};
            float ls[4] = {0.f, 0.f, 0.f, 0.f};
            #pragma unroll
            for (int ks = 0; ks < 4; ++ks) mma_f16(ls, pfr[ks], ones2);
            lA = lA * scA + ls[0];
            lB = lB * scB + ls[2];
        }
        // skip the O-rescale when no row's max moved (warp-convergent test)
        if (!__all_sync(0xffffffffu, (scA == 1.f) & (scB == 1.f))) {
            #pragma unroll
            for (int t = 0; t < 8; ++t) {
                oc[t][0] *= scA; oc[t][1] *= scA;
                oc[t][2] *= scB; oc[t][3] *= scB;
            }
        }

        // ---- O += P . V  (plain fp16 V, x4t fragments) ----
        #pragma unroll
        for (int ks = 0; ks < 4; ++ks) {
            unsigned vroff = (unsigned)((ks * 16 + qlo_ * 8 + b_r) * 128);
            #pragma unroll
            for (int u = 0; u < 4; ++u) {
                unsigned voff = vroff + (((unsigned)((2 * u + qhi_) * 16)) ^ bx);
                unsigned vh4[4];
                ldsm4t(vh4, sbase + SV + voff);
                mma_f16(oc[2 * u],     pfr[ks], vh4);
                mma_f16(oc[2 * u + 1], pfr[ks], vh4 + 2);
            }
        }
    }

    // ---- epilogue: out = queries + O / l ----
    float liA = 1.f / lA, liB = 1.f / lB;
    #pragma unroll
    for (int t = 0; t < 8; ++t) {
        int e = t * 8 + cA;
        size_t offA = ((size_t)((b * Lc + igA) * Hc + h)) * Ec + e;
        size_t offB = ((size_t)((b * Lc + igB) * Hc + h)) * Ec + e;
        float2 qa = *(const float2*)(q + offA);
        float2 qb = *(const float2*)(q + offB);
        *(float2*)(out + offA) = make_float2(qa.x + oc[t][0] * liA,
                                             qa.y + oc[t][1] * liA);
        *(float2*)(out + offB) = make_float2(qb.x + oc[t][2] * liB,
                                             qb.y + oc[t][3] * liB);
    }
}

// ---------------------------------------------------------------------------

extern "C" void kernel_launch(void* const* d_in, const int* in_sizes, int n_in,
                              void* d_out, int out_size)
{
    const float* q  = (const float*)d_in[0];
    const float* k  = (const float*)d_in[1];
    const float* v  = (const float*)d_in[2];
    const float* qm = (const float*)d_in[3];
    const float* kmsk = (const float*)d_in[4];
    const float* w  = (const float*)d_in[5];
    float* out = (float*)d_out;

    cudaFuncSetAttribute(stage2_kernel,
                         cudaFuncAttributeMaxDynamicSharedMemorySize, STOT);

    prep_kernel<<<NBH + NBH * 4, 1024>>>(q, w, qm, k, v, kmsk);

    dim3 grid(NBH, NIT);   // y slow => heavy tiles (it = NIT-1-y) first
    stage2_kernel<<<grid, 128, STOT>>>(q, kmsk, out);
}

// round 17
// speedup vs baseline: 1.5513x; 1.0382x over previous
#include <cuda_runtime.h>
#include <cuda_bf16.h>
#include <cuda_fp16.h>
#include <math.h>
#include <float.h>

#define Bc 4
#define Lc 1024
#define Hc 12
#define Ec 64
#define BM 64
#define BN 64
#define NIT (Lc / BM)    // 16 i-tiles
#define NBH (Bc * Hc)    // 48
#define PBH (Lc * 128)   // 131072 bytes per (b,h) per 16-bit array
#define L2E 1.4426950408889634f

// ---------------------------------------------------------------------------
// global scratch (allocation-free rule: __device__ globals)
// K: bf16 hi/lo; V: plain fp16. PRE-SWIZZLED like the stage2 smem tiles.
// ---------------------------------------------------------------------------
__device__ __align__(16) unsigned char g_khi[NBH * PBH];
__device__ __align__(16) unsigned char g_klo[NBH * PBH];
__device__ __align__(16) unsigned char g_vhi[NBH * PBH];
__device__ float2 g_wiz[NBH * Lc];         // (wexp, invz) packed
__device__ float g_kkn[NBH * Lc];          // -km * |k|^2 * log2(e)
__device__ float g_gqp[NBH * 64 * Ec];     // EXCLUSIVE prefix of 16-row sums

// ---------------------------------------------------------------------------
// helpers
// ---------------------------------------------------------------------------
__device__ __forceinline__ unsigned smem_u32(const void* p) {
    unsigned a;
    asm("{ .reg .u64 t; cvta.to.shared.u64 t, %1; cvt.u32.u64 %0, t; }"
        : "=r"(a) : "l"(p));
    return a;
}
__device__ __forceinline__ void cpa16(unsigned dst, const void* src) {
    asm volatile("cp.async.cg.shared.global [%0], [%1], 16;" :: "r"(dst), "l"(src));
}
__device__ __forceinline__ void ldsm4(unsigned* r, unsigned addr) {
    asm volatile("ldmatrix.sync.aligned.m8n8.x4.shared.b16 {%0,%1,%2,%3}, [%4];"
        : "=r"(r[0]), "=r"(r[1]), "=r"(r[2]), "=r"(r[3]) : "r"(addr));
}
__device__ __forceinline__ void ldsm4t(unsigned* r, unsigned addr) {
    asm volatile("ldmatrix.sync.aligned.m8n8.x4.trans.shared.b16 {%0,%1,%2,%3}, [%4];"
        : "=r"(r[0]), "=r"(r[1]), "=r"(r[2]), "=r"(r[3]) : "r"(addr));
}
__device__ __forceinline__ void mma_bf16(float* c, const unsigned* a, const unsigned* b) {
    asm volatile(
        "mma.sync.aligned.m16n8k16.row.col.f32.bf16.bf16.f32 "
        "{%0,%1,%2,%3}, {%4,%5,%6,%7}, {%8,%9}, {%0,%1,%2,%3};"
        : "+f"(c[0]), "+f"(c[1]), "+f"(c[2]), "+f"(c[3])
        : "r"(a[0]), "r"(a[1]), "r"(a[2]), "r"(a[3]), "r"(b[0]), "r"(b[1]));
}
__device__ __forceinline__ void mma_f16(float* c, const unsigned* a, const unsigned* b) {
    asm volatile(
        "mma.sync.aligned.m16n8k16.row.col.f32.f16.f16.f32 "
        "{%0,%1,%2,%3}, {%4,%5,%6,%7}, {%8,%9}, {%0,%1,%2,%3};"
        : "+f"(c[0]), "+f"(c[1]), "+f"(c[2]), "+f"(c[3])
        : "r"(a[0]), "r"(a[1]), "r"(a[2]), "r"(a[3]), "r"(b[0]), "r"(b[1]));
}
__device__ __forceinline__ unsigned h2exp2(unsigned x) {
    unsigned d;
    asm("ex2.approx.f16x2 %0, %1;" : "=r"(d) : "r"(x));
    return d;
}
__device__ __forceinline__ float ex2f(float x) {
    float d;
    asm("ex2.approx.f32 %0, %1;" : "=f"(d) : "f"(x));
    return d;
}
__device__ __forceinline__ void splitpack(float p0, float p1, unsigned& hi, unsigned& lo) {
    __nv_bfloat162 h2 = __floats2bfloat162_rn(p0, p1);
    float r0 = p0 - __low2float(h2);
    float r1 = p1 - __high2float(h2);
    __nv_bfloat162 l2 = __floats2bfloat162_rn(r0, r1);
    hi = *(unsigned*)&h2;
    lo = *(unsigned*)&l2;
}
// swizzled byte offset within a (row, c4) cell; c4 = group of 4 elements
__device__ __forceinline__ unsigned swoff(int row, int c4) {
    return (unsigned)(row * 128 + ((c4 * 8) ^ ((row & 7) << 4)));
}

// stage2 smem: 3 KV buffers of 24K {Khi +0, Klo +8192, V +16384}; kn 3x256.
// Q staging (prologue only) reuses buffer 2 (Q lives in registers afterwards).
#define SKNN 73728
#define SQHI_ST 49152
#define SQLO_ST 57344
#define STOT (73728 + 768)

// ---------------------------------------------------------------------------
// 1) merged: blocks [0,NBH) = score+scan+group-sums+prefix;
//            blocks [NBH, NBH+4*NBH) = prep_kv
// ---------------------------------------------------------------------------
__global__ void __launch_bounds__(1024) prep_kernel(
    const float* __restrict__ q, const float* __restrict__ wv,
    const float* __restrict__ q_mask,
    const float* __restrict__ k, const float* __restrict__ v,
    const float* __restrict__ k_mask)
{
    int tid = threadIdx.x;
    if (blockIdx.x >= NBH) {
        // ---------------- prep_kv part: 256 rows per block ----------------
        int pb = blockIdx.x - NBH;
        int bh = pb >> 2, qtr = pb & 3;
        int b = bh / Hc, h = bh % Hc;
        float km = k_mask[b * Lc];
        unsigned char* khi = g_khi + (size_t)bh * PBH;
        unsigned char* klo = g_klo + (size_t)bh * PBH;
        unsigned char* vhi = g_vhi + (size_t)bh * PBH;
        #pragma unroll
        for (int itr = 0; itr < 4; ++itr) {
            int idx = itr * 1024 + tid;
            int row = qtr * 256 + (idx >> 4), c4 = idx & 15;
            size_t goff = ((size_t)((b * Lc + row) * Hc + h)) * Ec + c4 * 4;
            unsigned off = swoff(row, c4);
            float4 kx = *(const float4*)(k + goff);
            {
                unsigned h0, l0_, h1, l1;
                splitpack(kx.x, kx.y, h0, l0_);
                splitpack(kx.z, kx.w, h1, l1);
                *(uint2*)(khi + off) = make_uint2(h0, h1);
                *(uint2*)(klo + off) = make_uint2(l0_, l1);
            }
            {
                float4 x = *(const float4*)(v + goff);
                __half2 a2 = __floats2half2_rn(x.x, x.y);
                __half2 b2 = __floats2half2_rn(x.z, x.w);
                *(uint2*)(vhi + off) = make_uint2(*(unsigned*)&a2, *(unsigned*)&b2);
            }
            float ps = kx.x * kx.x + kx.y * kx.y + kx.z * kx.z + kx.w * kx.w;
            #pragma unroll
            for (int o = 1; o < 16; o <<= 1) ps += __shfl_xor_sync(0xffffffffu, ps, o);
            if ((tid & 15) == 0) g_kkn[bh * Lc + row] = -km * ps * L2E;
        }
        return;
    }

    // ---------------- score + softmax-scan + group sums ----------------
    int bh = blockIdx.x;
    int b = bh / Hc, h = bh % Hc;

    __shared__ float s_sh[Lc];          // scores, then wexp
    __shared__ float gq_sh[64][Ec];     // 16-row sums, then exclusive prefix
    __shared__ float w_sh[Ec];
    __shared__ float red[32];
    __shared__ float Msh;

    int lane = tid & 31, warp = tid >> 5;

    if (tid < Ec) w_sh[tid] = wv[h * Ec + tid];
    __syncthreads();
    float qm = q_mask[b * Lc];

    for (int j = warp; j < Lc; j += 32) {
        const float* qrow = q + ((size_t)((b * Lc + j) * Hc + h)) * Ec;
        float p = qrow[lane] * w_sh[lane] + qrow[lane + 32] * w_sh[lane + 32];
        #pragma unroll
        for (int o = 16; o; o >>= 1) p += __shfl_xor_sync(0xffffffffu, p, o);
        if (lane == 0) s_sh[j] = p * qm;
    }
    __syncthreads();

    float m = s_sh[tid];
    #pragma unroll
    for (int o = 16; o; o >>= 1) m = fmaxf(m, __shfl_xor_sync(0xffffffffu, m, o));
    if (lane == 0) red[warp] = m;
    __syncthreads();
    if (warp == 0) {
        float t = red[lane];
        #pragma unroll
        for (int o = 16; o; o >>= 1) t = fmaxf(t, __shfl_xor_sync(0xffffffffu, t, o));
        if (lane == 0) Msh = t;
    }
    __syncthreads();
    float M = Msh;

    float wexp = __expf(s_sh[tid] - M);
    float sc = wexp;
    #pragma unroll
    for (int o = 1; o < 32; o <<= 1) {
        float t = __shfl_up_sync(0xffffffffu, sc, o);
        if (lane >= o) sc += t;
    }
    if (lane == 31) red[warp] = sc;
    __syncthreads();
    if (warp == 0) {
        float v0 = red[lane];
        float scn = v0;
        #pragma unroll
        for (int o = 1; o < 32; o <<= 1) {
            float t = __shfl_up_sync(0xffffffffu, scn, o);
            if (lane >= o) scn += t;
        }
        red[lane] = scn - v0;
    }
    __syncthreads();
    float Z = sc + red[warp];
    g_wiz[bh * Lc + tid] = make_float2(wexp, 1.0f / Z);
    s_sh[tid] = wexp;      // each thread overwrites its own element
    __syncthreads();

    // ---- 16-row group sums: gq_sh[gr][e] = sum_{jj<16} wexp * q ----
    {
        int e = tid & 63, rb = tid >> 6;      // rb: 0..15
        const float* qcol = q + (((size_t)(b * Lc)) * Hc + h) * Ec + e;
        #pragma unroll
        for (int p = 0; p < 4; ++p) {
            int gr = p * 16 + rb;
            int j0 = gr * 16;
            float acc = 0.f;
            #pragma unroll
            for (int jj = 0; jj < 16; ++jj)
                acc += s_sh[j0 + jj] * qcol[(size_t)(j0 + jj) * (Hc * Ec)];
            gq_sh[gr][e] = acc;
        }
    }
    __syncthreads();

    // ---- exclusive prefix over the 64 groups (per e-lane) ----
    if (tid < Ec) {
        float run = 0.f;
        #pragma unroll
        for (int gr = 0; gr < 64; ++gr) {
            float t = gq_sh[gr][tid];
            gq_sh[gr][tid] = run;
            run += t;
        }
    }
    __syncthreads();

    // ---- write prefix to global ----
    {
        int e = tid & 63, rb = tid >> 6;
        #pragma unroll
        for (int p = 0; p < 4; ++p) {
            int gr = p * 16 + rb;
            g_gqp[(bh * 64 + gr) * Ec + e] = gq_sh[gr][e];
        }
    }
}

// ---------------------------------------------------------------------------
// 2) Stage 2: software-pipelined flash attention. S(jt+1) issued between
//    softmax(jt) and PV(jt); sc_ reused in place (softmax consumed it).
//    Triple-buffered K/V; fused qhat scan; register-resident Q; ones-MMA sums.
//    grid (NBH, NIT) heavy-first, 128 threads (4 warps x 16 rows), 3 CTAs/SM
// ---------------------------------------------------------------------------
__global__ void __launch_bounds__(128, 3) stage2_kernel(
    const float* __restrict__ q, const float* __restrict__ k_mask,
    float* __restrict__ out)
{
    extern __shared__ char smem[];
    const unsigned sbase = smem_u32(smem);
    int tid = threadIdx.x, lane = tid & 31, w = tid >> 5;
    int bh = blockIdx.x, b = bh / Hc, h = bh % Hc;
    int it = NIT - 1 - (int)blockIdx.y;   // heavy tiles first
    int i0 = it * BM;
    float twokm = 2.f * k_mask[b * Lc] * L2E;   // log2-domain scale
    const size_t bhoff = (size_t)bh * PBH;

    // ---- prologue A: issue G0 (+ G1 if it>=1), stage kn0/kn1 ----
    {
        #pragma unroll
        for (int c = 0; c < 4; ++c) {
            unsigned off = (unsigned)((c * 128 + tid) * 16);
            cpa16(sbase + off,         g_khi + bhoff + off);
            cpa16(sbase + 8192 + off,  g_klo + bhoff + off);
            cpa16(sbase + 16384 + off, g_vhi + bhoff + off);
        }
        if (tid < BN)
            *(float*)(smem + SKNN + tid * 4) = g_kkn[bh * Lc + tid];
        asm volatile("cp.async.commit_group;");
        if (it >= 1) {
            const size_t tg = bhoff + (size_t)BN * 128;
            #pragma unroll
            for (int c = 0; c < 4; ++c) {
                unsigned off = (unsigned)((c * 128 + tid) * 16);
                cpa16(sbase + 24576 + off,         g_khi + tg + off);
                cpa16(sbase + 24576 + 8192 + off,  g_klo + tg + off);
                cpa16(sbase + 24576 + 16384 + off, g_vhi + tg + off);
            }
            if (tid < BN)
                *(float*)(smem + SKNN + 256 + tid * 4) = g_kkn[bh * Lc + BN + tid];
            asm volatile("cp.async.commit_group;");
        }
    }

    // ---- prologue B: fused qhat scan -> split-bf16 Q tile in staging ----
    {
        int e = tid & 63, gp = tid >> 6;                 // gp: 0..1
        unsigned ebase = (unsigned)((e >> 2) * 8);
        unsigned elow = (unsigned)((e & 3) * 2);
        #pragma unroll
        for (int gg = 0; gg < 2; ++gg) {
            int g = gp * 2 + gg;                          // 0..3
            int gr = (i0 >> 4) + g;
            float acc = g_gqp[(bh * 64 + gr) * Ec + e];
            int jbase = i0 + g * 16;
            #pragma unroll
            for (int jj = 0; jj < 16; ++jj) {
                int j = jbase + jj;
                float2 wi = g_wiz[bh * Lc + j];
                acc += wi.x * q[((size_t)((b * Lc + j) * Hc + h)) * Ec + e];
                float val = acc * wi.y;
                int row = g * 16 + jj;
                __nv_bfloat16 hb = __float2bfloat16_rn(val);
                __nv_bfloat16 lb = __float2bfloat16_rn(val - __bfloat162float(hb));
                unsigned off = (unsigned)(row * 128) + (ebase ^ ((row & 7) << 4)) + elow;
                *(__nv_bfloat16*)(smem + SQHI_ST + off) = hb;
                *(__nv_bfloat16*)(smem + SQLO_ST + off) = lb;
            }
        }
    }
    asm volatile("cp.async.wait_group 0;");   // G0 (and G1) complete
    __syncthreads();                          // Q staging + K0 visible

    // ---- per-lane fragment geometry ----
    int a_t = lane >> 3, a_r = lane & 7;
    int a_row = w * 16 + ((a_t & 1) << 3) + a_r;
    unsigned a_rowoff = (unsigned)(a_row * 128);
    unsigned a_x = (unsigned)((a_row & 7) << 4);
    unsigned a_cb = (unsigned)(((a_t >> 1) << 3) * 2);
    int quad = lane >> 3;                 // 0..3 (x4 B-fragment geometry)
    int qlo_ = quad & 1, qhi_ = quad >> 1;
    int b_r = lane & 7;
    unsigned bx = (unsigned)(b_r << 4);
    int rA = lane >> 2;
    int igA = i0 + w * 16 + rA, igB = igA + 8;
    int cA = (lane & 3) << 1;

    // ---- Q fragments: load ONCE into registers ----
    unsigned qah[4][4], qal[4][4];
    #pragma unroll
    for (int ks = 0; ks < 4; ++ks) {
        unsigned aoff = a_rowoff + (((unsigned)(ks * 32) + a_cb) ^ a_x);
        ldsm4(qah[ks], sbase + SQHI_ST + aoff);
        ldsm4(qal[ks], sbase + SQLO_ST + aoff);
    }

    float sc_[8][4];
    auto runS = [&](unsigned kvb) {
        #pragma unroll
        for (int t = 0; t < 8; ++t)
            #pragma unroll
            for (int c = 0; c < 4; ++c) sc_[t][c] = 0.f;
        unsigned KHI = kvb, KLO = kvb + 8192;
        #pragma unroll
        for (int ks = 0; ks < 4; ++ks) {
            #pragma unroll
            for (int u = 0; u < 4; ++u) {
                unsigned jroff = (unsigned)((u * 16 + qhi_ * 8 + b_r) * 128);
                unsigned boff = jroff + (((unsigned)(ks * 32 + qlo_ * 16)) ^ bx);
                unsigned kh4[4], kl4[4];
                ldsm4(kh4, sbase + KHI + boff);
                ldsm4(kl4, sbase + KLO + boff);
                mma_bf16(sc_[2 * u],     qah[ks], kh4);
                mma_bf16(sc_[2 * u],     qah[ks], kl4);
                mma_bf16(sc_[2 * u],     qal[ks], kh4);
                mma_bf16(sc_[2 * u + 1], qah[ks], kh4 + 2);
                mma_bf16(sc_[2 * u + 1], qah[ks], kl4 + 2);
                mma_bf16(sc_[2 * u + 1], qal[ks], kh4 + 2);
            }
        }
    };

    // ---- S(0) ----
    runS(0);
    __syncthreads();   // all warps done reading Q staging (buffer 2)

    // ---- issue G2 into buffer 2 (overwrites staging) ----
    if (it >= 2) {
        const size_t tg = bhoff + (size_t)(2 * BN) * 128;
        #pragma unroll
        for (int c = 0; c < 4; ++c) {
            unsigned off = (unsigned)((c * 128 + tid) * 16);
            cpa16(sbase + 49152 + off,         g_khi + tg + off);
            cpa16(sbase + 49152 + 8192 + off,  g_klo + tg + off);
            cpa16(sbase + 49152 + 16384 + off, g_vhi + tg + off);
        }
        if (tid < BN)
            *(float*)(smem + SKNN + 512 + tid * 4) = g_kkn[bh * Lc + 2 * BN + tid];
        asm volatile("cp.async.commit_group;");
    }

    float oc[8][4];
    #pragma unroll
    for (int t = 0; t < 8; ++t)
        #pragma unroll
        for (int c = 0; c < 4; ++c) oc[t][c] = 0.f;
    float mA = -INFINITY, mB = -INFINITY, lA = 0.f, lB = 0.f;

    int bi = 0;   // buffer index = jt % 3
    for (int jt = 0; jt <= it; ++jt) {
        int bi1 = bi + 1; if (bi1 == 3) bi1 = 0;
        unsigned kvb = (unsigned)bi * 24576;
        const float2* kn2 = (const float2*)(smem + SKNN + bi * 256);

        // ---- scores (log2 domain) from sc_ (computed last iteration) ----
        float mxA = -INFINITY, mxB = -INFINITY;
        if (jt == it) {
            int j0 = jt * BN;
            #pragma unroll
            for (int t = 0; t < 8; ++t) {
                int jb = j0 + t * 8 + cA;
                float2 kk = kn2[t * 4 + (cA >> 1)];
                float s0 = fmaf(twokm, sc_[t][0], kk.x); if (jb     > igA) s0 = -INFINITY;
                float s1 = fmaf(twokm, sc_[t][1], kk.y); if (jb + 1 > igA) s1 = -INFINITY;
                float s2 = fmaf(twokm, sc_[t][2], kk.x); if (jb     > igB) s2 = -INFINITY;
                float s3 = fmaf(twokm, sc_[t][3], kk.y); if (jb + 1 > igB) s3 = -INFINITY;
                sc_[t][0] = s0; sc_[t][1] = s1; sc_[t][2] = s2; sc_[t][3] = s3;
                mxA = fmaxf(mxA, fmaxf(s0, s1));
                mxB = fmaxf(mxB, fmaxf(s2, s3));
            }
        } else {
            #pragma unroll
            for (int t = 0; t < 8; ++t) {
                float2 kk = kn2[t * 4 + (cA >> 1)];
                float s0 = fmaf(twokm, sc_[t][0], kk.x);
                float s1 = fmaf(twokm, sc_[t][1], kk.y);
                float s2 = fmaf(twokm, sc_[t][2], kk.x);
                float s3 = fmaf(twokm, sc_[t][3], kk.y);
                sc_[t][0] = s0; sc_[t][1] = s1; sc_[t][2] = s2; sc_[t][3] = s3;
                mxA = fmaxf(mxA, fmaxf(s0, s1));
                mxB = fmaxf(mxB, fmaxf(s2, s3));
            }
        }
        mxA = fmaxf(mxA, __shfl_xor_sync(0xffffffffu, mxA, 1));
        mxA = fmaxf(mxA, __shfl_xor_sync(0xffffffffu, mxA, 2));
        mxB = fmaxf(mxB, __shfl_xor_sync(0xffffffffu, mxB, 1));
        mxB = fmaxf(mxB, __shfl_xor_sync(0xffffffffu, mxB, 2));

        float mnA = fmaxf(mA, mxA), mnB = fmaxf(mB, mxB);
        float scA = ex2f(mA - mnA), scB = ex2f(mB - mnB);
        mA = mnA; mB = mnB;

        // packed fp16 exp -> PV A-fragments (sc_ fully consumed here)
        unsigned pfr[4][4];
        #pragma unroll
        for (int ks = 0; ks < 4; ++ks) {
            #pragma unroll
            for (int v2 = 0; v2 < 2; ++v2) {
                int t = 2 * ks + v2;
                __half2 hA = __floats2half2_rn(sc_[t][0] - mnA, sc_[t][1] - mnA);
                __half2 hB = __floats2half2_rn(sc_[t][2] - mnB, sc_[t][3] - mnB);
                pfr[ks][2 * v2]     = h2exp2(*(unsigned*)&hA);
                pfr[ks][2 * v2 + 1] = h2exp2(*(unsigned*)&hB);
            }
        }

        // row sums via ones-B MMA
        {
            unsigned ones2[2] = {0x3C003C00u, 0x3C003C00u};
            float ls[4] = {0.f, 0.f, 0.f, 0.f};
            #pragma unroll
            for (int ks = 0; ks < 4; ++ks) mma_f16(ls, pfr[ks], ones2);
            lA = lA * scA + ls[0];
            lB = lB * scB + ls[2];
        }
        if (!__all_sync(0xffffffffu, (scA == 1.f) & (scB == 1.f))) {
            #pragma unroll
            for (int t = 0; t < 8; ++t) {
                oc[t][0] *= scA; oc[t][1] *= scA;
                oc[t][2] *= scB; oc[t][3] *= scB;
            }
        }

        // ---- issue S(jt+1) into sc_ (K(jt+1) resident, waited last iter) ----
        if (jt < it) runS((unsigned)bi1 * 24576);

        // ---- O += P . V  (V of tile jt) ----
        unsigned SV = kvb + 16384;
        #pragma unroll
        for (int ks = 0; ks < 4; ++ks) {
            unsigned vroff = (unsigned)((ks * 16 + qlo_ * 8 + b_r) * 128);
            #pragma unroll
            for (int u = 0; u < 4; ++u) {
                unsigned voff = vroff + (((unsigned)((2 * u + qhi_) * 16)) ^ bx);
                unsigned vh4[4];
                ldsm4t(vh4, sbase + SV + voff);
                mma_f16(oc[2 * u],     pfr[ks], vh4);
                mma_f16(oc[2 * u + 1], pfr[ks], vh4 + 2);
            }
        }

        // ---- rotate: free buf bi, issue G(jt+3), wait G(jt+2) ----
        if (jt < it) {
            __syncthreads();   // all warps done reading buffer bi (K+V of jt)
            int iss = (jt + 3 <= it);
            if (iss) {
                const size_t tg = bhoff + (size_t)((jt + 3) * BN) * 128;
                #pragma unroll
                for (int c = 0; c < 4; ++c) {
                    unsigned off = (unsigned)((c * 128 + tid) * 16);
                    cpa16(sbase + kvb + off,         g_khi + tg + off);
                    cpa16(sbase + kvb + 8192 + off,  g_klo + tg + off);
                    cpa16(sbase + kvb + 16384 + off, g_vhi + tg + off);
                }
                if (tid < BN)
                    *(float*)(smem + SKNN + bi * 256 + tid * 4) =
                        g_kkn[bh * Lc + (jt + 3) * BN + tid];
                asm volatile("cp.async.commit_group;");
            }
            if (iss) asm volatile("cp.async.wait_group 1;");
            else     asm volatile("cp.async.wait_group 0;");
            __syncthreads();   // K(jt+2)/V(jt+2)/kn visible for next iterations
        }
        bi = bi1;
    }

    // ---- epilogue: out = queries + O / l ----
    float liA = 1.f / lA, liB = 1.f / lB;
    #pragma unroll
    for (int t = 0; t < 8; ++t) {
        int e = t * 8 + cA;
        size_t offA = ((size_t)((b * Lc + igA) * Hc + h)) * Ec + e;
        size_t offB = ((size_t)((b * Lc + igB) * Hc + h)) * Ec + e;
        float2 qa = *(const float2*)(q + offA);
        float2 qb = *(const float2*)(q + offB);
        *(float2*)(out + offA) = make_float2(qa.x + oc[t][0] * liA,
                                             qa.y + oc[t][1] * liA);
        *(float2*)(out + offB) = make_float2(qb.x + oc[t][2] * liB,
                                             qb.y + oc[t][3] * liB);
    }
}

// ---------------------------------------------------------------------------

extern "C" void kernel_launch(void* const* d_in, const int* in_sizes, int n_in,
                              void* d_out, int out_size)
{
    const float* q  = (const float*)d_in[0];
    const float* k  = (const float*)d_in[1];
    const float* v  = (const float*)d_in[2];
    const float* qm = (const float*)d_in[3];
    const float* kmsk = (const float*)d_in[4];
    const float* w  = (const float*)d_in[5];
    float* out = (float*)d_out;

    cudaFuncSetAttribute(stage2_kernel,
                         cudaFuncAttributeMaxDynamicSharedMemorySize, STOT);

    prep_kernel<<<NBH + NBH * 4, 1024>>>(q, w, qm, k, v, kmsk);

    dim3 grid(NBH, NIT);   // y slow => heavy tiles (it = NIT-1-y) first
    stage2_kernel<<<grid, 128, STOT>>>(q, kmsk, out);
}